// round 14
// baseline (speedup 1.0000x reference)
#include <cuda_runtime.h>
#include <cuda_bf16.h>
#include <math.h>
#include <stdint.h>

// Problem constants
#define BB 4
#define TT 1024
#define CC 512
#define HH 8
#define DH 64
#define FF 2048
#define BT (BB*TT)
#define NEGI (-1e9f)
#define QKVN (3*CC)

// ---------------- scratch ----------------
__device__ float g_x[BT*CC];
__device__ float g_qkv[BT*QKVN];
__device__ float g_s[(size_t)BB*HH*TT*TT];
__device__ float g_p0[(size_t)BB*TT*TT];
__device__ float g_t[BT*CC];
__device__ float g_w[BT];
__device__ float g_aw[BT];
__device__ float g_wp[BB*HH*8*TT];
__device__ int   g_seg[BT];
__device__ int   g_segstart[BB*(TT+1)];
__device__ int   g_nseg[BB];

// bf16 buffers
__device__ __nv_bfloat16 g_xb[BT*CC];
__device__ __nv_bfloat16 g_ab[BT*CC];
__device__ __nv_bfloat16 g_hb[BT*FF];
__device__ __nv_bfloat16 g_qkvb[BT*QKVN];
__device__ __nv_bfloat16 g_sb[(size_t)BB*HH*TT*TT];
__device__ __nv_bfloat16 g_wqkv_b[4*3*CC*CC];
__device__ __nv_bfloat16 g_wo_b[4*CC*CC];
__device__ __nv_bfloat16 g_w1_b[4*FF*CC];
__device__ __nv_bfloat16 g_w2_b[4*CC*FF];

__device__ __forceinline__ float f2tf32(float x) {
    uint32_t r;
    asm("cvt.rna.tf32.f32 %0, %1;" : "=r"(r) : "f"(x));
    return __uint_as_float(r);
}
__device__ __forceinline__ uint32_t packbf2(float lo, float hi) {
    uint32_t r;
    asm("cvt.rn.bf16x2.f32 %0, %1, %2;" : "=r"(r) : "f"(hi), "f"(lo));
    return r;
}
__device__ __forceinline__ float2 bf2f(uint32_t u) {
    __nv_bfloat162 h = *reinterpret_cast<__nv_bfloat162*>(&u);
    return __bfloat1622float2(h);
}

#define MMA_TF32(acc, a0,a1,a2,a3, b0,b1) \
    asm("mma.sync.aligned.m16n8k8.row.col.f32.tf32.tf32.f32 " \
        "{%0,%1,%2,%3}, {%4,%5,%6,%7}, {%8,%9}, {%0,%1,%2,%3};" \
        : "+f"(acc[0]), "+f"(acc[1]), "+f"(acc[2]), "+f"(acc[3]) \
        : "r"(a0), "r"(a1), "r"(a2), "r"(a3), "r"(b0), "r"(b1))

#define MMA_BF16(acc, a0,a1,a2,a3, b0,b1) \
    asm("mma.sync.aligned.m16n8k16.row.col.f32.bf16.bf16.f32 " \
        "{%0,%1,%2,%3}, {%4,%5,%6,%7}, {%8,%9}, {%0,%1,%2,%3};" \
        : "+f"(acc[0]), "+f"(acc[1]), "+f"(acc[2]), "+f"(acc[3]) \
        : "r"(a0), "r"(a1), "r"(a2), "r"(a3), "r"(b0), "r"(b1))

// ======== single-launch batched transpose+convert (24 weight matrices) ========
__global__ void transpose_cvt_all_kernel(const float* __restrict__ Wqkv,
                                         const float* __restrict__ Wo,
                                         const float* __restrict__ W1,
                                         const float* __restrict__ W2,
                                         __nv_bfloat16* __restrict__ dq,
                                         __nv_bfloat16* __restrict__ dwo,
                                         __nv_bfloat16* __restrict__ d1,
                                         __nv_bfloat16* __restrict__ d2)
{
    __shared__ float tile[32][33];
    int z = blockIdx.z;
    const float* src;
    __nv_bfloat16* dst;
    int K, N;
    if (z < 12)      { src = Wqkv + (size_t)z * CC * CC; dst = dq + (size_t)z * CC * CC; K = CC; N = CC; }
    else if (z < 16) { int m = z - 12; src = Wo + (size_t)m * CC * CC; dst = dwo + (size_t)m * CC * CC; K = CC; N = CC; }
    else if (z < 20) { int m = z - 16; src = W1 + (size_t)m * CC * FF; dst = d1 + (size_t)m * FF * CC; K = CC; N = FF; }
    else             { int m = z - 20; src = W2 + (size_t)m * FF * CC; dst = d2 + (size_t)m * CC * FF; K = FF; N = CC; }

    int ntn = N / 32, ntk = K / 32;
    int flat = blockIdx.x;
    if (flat >= ntn * ntk) return;
    int nb = (flat % ntn) * 32, kb = (flat / ntn) * 32;
    int tx = threadIdx.x, ty = threadIdx.y;
    #pragma unroll
    for (int j = ty; j < 32; j += 8)
        tile[j][tx] = src[(size_t)(kb + j) * N + nb + tx];
    __syncthreads();
    #pragma unroll
    for (int j = ty; j < 32; j += 8)
        dst[(size_t)(nb + j) * K + kb + tx] = __float2bfloat16(tile[tx][j]);
}

__global__ void cvt_kernel(const float* __restrict__ src, __nv_bfloat16* __restrict__ dst)
{
    size_t i = (size_t)blockIdx.x * 256 + threadIdx.x;
    dst[i] = __float2bfloat16(src[i]);
}

// ======== BF16xBF16 GEMM: 128x128x16, 2-stage (R12-proven) ========
__global__ __launch_bounds__(256) void gemm_bb_kernel(
    const __nv_bfloat16* __restrict__ A, const __nv_bfloat16* __restrict__ Wt,
    const float* __restrict__ bias, float* __restrict__ outf,
    __nv_bfloat16* __restrict__ outb, int nstride, int K, int relu, int obf)
{
    __shared__ uint32_t As[2][128][9];
    __shared__ uint32_t Bs[2][128][9];
    int tid = threadIdx.x;
    int lane = tid & 31;
    int warp = tid >> 5;
    int warp_m = warp & 3;
    int warp_n = warp >> 2;
    int grp = lane >> 2;
    int tig = lane & 3;

    int row0 = blockIdx.y * 128, col0 = blockIdx.x * 128;
    const __nv_bfloat16* Ab = A + (size_t)row0 * K;
    const __nv_bfloat16* Wb = Wt + (size_t)col0 * K;

    const int arow = tid >> 1, akoff = (tid & 1) * 8, akp = (tid & 1) * 4;

    float acc[2][8][4];
    #pragma unroll
    for (int i = 0; i < 2; i++)
        #pragma unroll
        for (int j = 0; j < 8; j++)
            #pragma unroll
            for (int c = 0; c < 4; c++) acc[i][j][c] = 0.0f;

    uint4 ua, ub;
    ua = *(const uint4*)&Ab[(size_t)arow * K + akoff];
    ub = *(const uint4*)&Wb[(size_t)arow * K + akoff];
    As[0][arow][akp+0] = ua.x; As[0][arow][akp+1] = ua.y;
    As[0][arow][akp+2] = ua.z; As[0][arow][akp+3] = ua.w;
    Bs[0][arow][akp+0] = ub.x; Bs[0][arow][akp+1] = ub.y;
    Bs[0][arow][akp+2] = ub.z; Bs[0][arow][akp+3] = ub.w;

    int nk = K >> 4;
    for (int kt = 0; kt < nk; kt++) {
        __syncthreads();
        int cur = kt & 1;
        if (kt + 1 < nk) {
            int k0 = (kt + 1) << 4;
            ua = *(const uint4*)&Ab[(size_t)arow * K + k0 + akoff];
            ub = *(const uint4*)&Wb[(size_t)arow * K + k0 + akoff];
        }
        {
            uint32_t af[2][4];
            #pragma unroll
            for (int mf = 0; mf < 2; mf++) {
                int m = warp_m * 32 + mf * 16 + grp;
                af[mf][0] = As[cur][m][tig];
                af[mf][1] = As[cur][m + 8][tig];
                af[mf][2] = As[cur][m][tig + 4];
                af[mf][3] = As[cur][m + 8][tig + 4];
            }
            #pragma unroll
            for (int nf = 0; nf < 8; nf++) {
                int n = warp_n * 64 + nf * 8 + grp;
                uint32_t b0 = Bs[cur][n][tig];
                uint32_t b1 = Bs[cur][n][tig + 4];
                #pragma unroll
                for (int mf = 0; mf < 2; mf++)
                    MMA_BF16(acc[mf][nf], af[mf][0], af[mf][1], af[mf][2], af[mf][3], b0, b1);
            }
        }
        if (kt + 1 < nk) {
            int nb = cur ^ 1;
            As[nb][arow][akp+0] = ua.x; As[nb][arow][akp+1] = ua.y;
            As[nb][arow][akp+2] = ua.z; As[nb][arow][akp+3] = ua.w;
            Bs[nb][arow][akp+0] = ub.x; Bs[nb][arow][akp+1] = ub.y;
            Bs[nb][arow][akp+2] = ub.z; Bs[nb][arow][akp+3] = ub.w;
        }
    }

    #pragma unroll
    for (int mf = 0; mf < 2; mf++) {
        int r_lo = row0 + warp_m * 32 + mf * 16 + grp;
        int r_hi = r_lo + 8;
        #pragma unroll
        for (int nf = 0; nf < 8; nf++) {
            int cl = warp_n * 64 + nf * 8 + tig * 2;
            float bv0 = bias[col0 + cl], bv1 = bias[col0 + cl + 1];
            float v0 = acc[mf][nf][0] + bv0, v1 = acc[mf][nf][1] + bv1;
            float v2 = acc[mf][nf][2] + bv0, v3 = acc[mf][nf][3] + bv1;
            if (relu) { v0 = fmaxf(v0, 0.f); v1 = fmaxf(v1, 0.f);
                        v2 = fmaxf(v2, 0.f); v3 = fmaxf(v3, 0.f); }
            if (!obf) {
                *(float2*)&outf[(size_t)r_lo * nstride + col0 + cl] = make_float2(v0, v1);
                *(float2*)&outf[(size_t)r_hi * nstride + col0 + cl] = make_float2(v2, v3);
            } else {
                *(uint32_t*)&outb[(size_t)r_lo * nstride + col0 + cl] = packbf2(v0, v1);
                *(uint32_t*)&outb[(size_t)r_hi * nstride + col0 + cl] = packbf2(v2, v3);
            }
        }
    }
}

// ======== BF16 GEMM 64x128 tile (for grid-limited N=512 GEMMs) ========
// grid: (N/128, M/64). Bit-identical accumulation order to 128-tile version.
__global__ __launch_bounds__(256) void gemm_bb64_kernel(
    const __nv_bfloat16* __restrict__ A, const __nv_bfloat16* __restrict__ Wt,
    const float* __restrict__ bias, float* __restrict__ outf,
    __nv_bfloat16* __restrict__ outb, int nstride, int K, int relu, int obf)
{
    __shared__ uint32_t As[2][64][9];
    __shared__ uint32_t Bs[2][128][9];
    int tid = threadIdx.x;
    int lane = tid & 31;
    int warp = tid >> 5;
    int warp_m = warp & 1;          // 2 warp-rows of 32
    int warp_n = warp >> 1;         // 4 warp-cols of 32
    int grp = lane >> 2;
    int tig = lane & 3;

    int row0 = blockIdx.y * 64, col0 = blockIdx.x * 128;
    const __nv_bfloat16* Ab = A + (size_t)row0 * K;
    const __nv_bfloat16* Wb = Wt + (size_t)col0 * K;

    // A loader: 64 rows x 8 kpairs = 512 u32; each thread one uint2
    const int a_row = tid >> 2, a_kp = (tid & 3) * 2, a_ko = (tid & 3) * 4;
    // B loader: 128 rows x 8 kpairs = 1024 u32; each thread one uint4
    const int b_row = tid >> 1, b_kp = (tid & 1) * 4, b_ko = (tid & 1) * 8;

    float acc[2][4][4];
    #pragma unroll
    for (int i = 0; i < 2; i++)
        #pragma unroll
        for (int j = 0; j < 4; j++)
            #pragma unroll
            for (int c = 0; c < 4; c++) acc[i][j][c] = 0.0f;

    uint2 ua;
    uint4 ub;
    ua = *(const uint2*)&Ab[(size_t)a_row * K + a_ko];
    ub = *(const uint4*)&Wb[(size_t)b_row * K + b_ko];
    As[0][a_row][a_kp+0] = ua.x; As[0][a_row][a_kp+1] = ua.y;
    Bs[0][b_row][b_kp+0] = ub.x; Bs[0][b_row][b_kp+1] = ub.y;
    Bs[0][b_row][b_kp+2] = ub.z; Bs[0][b_row][b_kp+3] = ub.w;

    int nk = K >> 4;
    for (int kt = 0; kt < nk; kt++) {
        __syncthreads();
        int cur = kt & 1;
        if (kt + 1 < nk) {
            int k0 = (kt + 1) << 4;
            ua = *(const uint2*)&Ab[(size_t)a_row * K + k0 + a_ko];
            ub = *(const uint4*)&Wb[(size_t)b_row * K + k0 + b_ko];
        }
        {
            uint32_t af[2][4];
            #pragma unroll
            for (int mf = 0; mf < 2; mf++) {
                int m = warp_m * 32 + mf * 16 + grp;
                af[mf][0] = As[cur][m][tig];
                af[mf][1] = As[cur][m + 8][tig];
                af[mf][2] = As[cur][m][tig + 4];
                af[mf][3] = As[cur][m + 8][tig + 4];
            }
            #pragma unroll
            for (int nf = 0; nf < 4; nf++) {
                int n = warp_n * 32 + nf * 8 + grp;
                uint32_t b0 = Bs[cur][n][tig];
                uint32_t b1 = Bs[cur][n][tig + 4];
                #pragma unroll
                for (int mf = 0; mf < 2; mf++)
                    MMA_BF16(acc[mf][nf], af[mf][0], af[mf][1], af[mf][2], af[mf][3], b0, b1);
            }
        }
        if (kt + 1 < nk) {
            int nb = cur ^ 1;
            As[nb][a_row][a_kp+0] = ua.x; As[nb][a_row][a_kp+1] = ua.y;
            Bs[nb][b_row][b_kp+0] = ub.x; Bs[nb][b_row][b_kp+1] = ub.y;
            Bs[nb][b_row][b_kp+2] = ub.z; Bs[nb][b_row][b_kp+3] = ub.w;
        }
    }

    #pragma unroll
    for (int mf = 0; mf < 2; mf++) {
        int r_lo = row0 + warp_m * 32 + mf * 16 + grp;
        int r_hi = r_lo + 8;
        #pragma unroll
        for (int nf = 0; nf < 4; nf++) {
            int cl = warp_n * 32 + nf * 8 + tig * 2;
            float bv0 = bias[col0 + cl], bv1 = bias[col0 + cl + 1];
            float v0 = acc[mf][nf][0] + bv0, v1 = acc[mf][nf][1] + bv1;
            float v2 = acc[mf][nf][2] + bv0, v3 = acc[mf][nf][3] + bv1;
            if (relu) { v0 = fmaxf(v0, 0.f); v1 = fmaxf(v1, 0.f);
                        v2 = fmaxf(v2, 0.f); v3 = fmaxf(v3, 0.f); }
            if (!obf) {
                *(float2*)&outf[(size_t)r_lo * nstride + col0 + cl] = make_float2(v0, v1);
                *(float2*)&outf[(size_t)r_hi * nstride + col0 + cl] = make_float2(v2, v3);
            } else {
                *(uint32_t*)&outb[(size_t)r_lo * nstride + col0 + cl] = packbf2(v0, v1);
                *(uint32_t*)&outb[(size_t)r_hi * nstride + col0 + cl] = packbf2(v2, v3);
            }
        }
    }
}

// ======== exact fp32 SIMT GEMM (seg-critical stage0/l0 Q,K) ========
__global__ __launch_bounds__(256) void gemm_kernel(
    const float* __restrict__ A, const float* __restrict__ W,
    const float* __restrict__ bias, float* __restrict__ Cout,
    int M, int Ntot, int K, int relu, int sub_n)
{
    __shared__ float As[2][16][128];
    __shared__ float Bs[2][16][128];
    int tid = threadIdx.x;
    int tx = tid & 15, ty = tid >> 4;
    int row0 = blockIdx.y * 128, col0 = blockIdx.x * 128;
    int mat = col0 / sub_n;
    int coln = col0 % sub_n;
    const float* Wb = W + (size_t)mat * K * sub_n + coln;
    const float* Ab = A + (size_t)row0 * K;

    const int arow = tid >> 1, akoff = (tid & 1) * 8;
    const int bk = tid >> 4, bcol = (tid & 15) * 8;

    float acc[8][8] = {};
    float4 ra0, ra1, rb0, rb1;

    ra0 = *(const float4*)&Ab[(size_t)arow * K + akoff];
    ra1 = *(const float4*)&Ab[(size_t)arow * K + akoff + 4];
    rb0 = *(const float4*)&Wb[(size_t)bk * sub_n + bcol];
    rb1 = *(const float4*)&Wb[(size_t)bk * sub_n + bcol + 4];
    As[0][akoff+0][arow]=ra0.x; As[0][akoff+1][arow]=ra0.y;
    As[0][akoff+2][arow]=ra0.z; As[0][akoff+3][arow]=ra0.w;
    As[0][akoff+4][arow]=ra1.x; As[0][akoff+5][arow]=ra1.y;
    As[0][akoff+6][arow]=ra1.z; As[0][akoff+7][arow]=ra1.w;
    *(float4*)&Bs[0][bk][bcol]   = rb0;
    *(float4*)&Bs[0][bk][bcol+4] = rb1;
    __syncthreads();

    int nk = K >> 4;
    for (int kt = 0; kt < nk; kt++) {
        int buf = kt & 1;
        if (kt + 1 < nk) {
            int k0 = (kt + 1) << 4;
            ra0 = *(const float4*)&Ab[(size_t)arow * K + k0 + akoff];
            ra1 = *(const float4*)&Ab[(size_t)arow * K + k0 + akoff + 4];
            rb0 = *(const float4*)&Wb[(size_t)(k0 + bk) * sub_n + bcol];
            rb1 = *(const float4*)&Wb[(size_t)(k0 + bk) * sub_n + bcol + 4];
        }
        #pragma unroll
        for (int kk = 0; kk < 16; kk++) {
            float a[8], b[8];
            *(float4*)(a)   = *(const float4*)&As[buf][kk][ty*8];
            *(float4*)(a+4) = *(const float4*)&As[buf][kk][ty*8+4];
            *(float4*)(b)   = *(const float4*)&Bs[buf][kk][tx*8];
            *(float4*)(b+4) = *(const float4*)&Bs[buf][kk][tx*8+4];
            #pragma unroll
            for (int i = 0; i < 8; i++)
                #pragma unroll
                for (int j = 0; j < 8; j++)
                    acc[i][j] += a[i] * b[j];
        }
        if (kt + 1 < nk) {
            int nb2 = buf ^ 1;
            As[nb2][akoff+0][arow]=ra0.x; As[nb2][akoff+1][arow]=ra0.y;
            As[nb2][akoff+2][arow]=ra0.z; As[nb2][akoff+3][arow]=ra0.w;
            As[nb2][akoff+4][arow]=ra1.x; As[nb2][akoff+5][arow]=ra1.y;
            As[nb2][akoff+6][arow]=ra1.z; As[nb2][akoff+7][arow]=ra1.w;
            *(float4*)&Bs[nb2][bk][bcol]   = rb0;
            *(float4*)&Bs[nb2][bk][bcol+4] = rb1;
        }
        __syncthreads();
    }

    const float* bb = bias + (size_t)mat * sub_n + coln;
    float bv[8];
    #pragma unroll
    for (int j = 0; j < 8; j++) bv[j] = bb[tx*8 + j];
    #pragma unroll
    for (int i = 0; i < 8; i++) {
        size_t r = (size_t)(row0 + ty*8 + i);
        float o[8];
        #pragma unroll
        for (int j = 0; j < 8; j++) {
            float v = acc[i][j] + bv[j];
            o[j] = relu ? fmaxf(v, 0.0f) : v;
        }
        *(float4*)&Cout[r * Ntot + col0 + tx*8]     = *(float4*)(o);
        *(float4*)&Cout[r * Ntot + col0 + tx*8 + 4] = *(float4*)(o+4);
    }
}

// ======== exact fp32 scores (stage0/l0 only) ========
__global__ __launch_bounds__(256) void scores_kernel(int use_mask)
{
    int bh = blockIdx.z;
    int b = bh >> 3, h = bh & 7;
    int t0 = blockIdx.y * 128, s0 = blockIdx.x * 128;
    __shared__ float Qs[2][16][128];
    __shared__ float Ks[2][16][128];
    int tid = threadIdx.x;
    int tx = tid & 15, ty = tid >> 4;

    const int arow = tid >> 1, akoff = (tid & 1) * 8;
    const float* qb = g_qkv + (size_t)(b*TT + t0) * QKVN + h*64;
    const float* kb = g_qkv + (size_t)(b*TT + s0) * QKVN + CC + h*64;

    float acc[8][8] = {};
    float4 ra0, ra1, rb0, rb1;

    ra0 = *(const float4*)&qb[(size_t)arow * QKVN + akoff];
    ra1 = *(const float4*)&qb[(size_t)arow * QKVN + akoff + 4];
    rb0 = *(const float4*)&kb[(size_t)arow * QKVN + akoff];
    rb1 = *(const float4*)&kb[(size_t)arow * QKVN + akoff + 4];
    Qs[0][akoff+0][arow]=ra0.x; Qs[0][akoff+1][arow]=ra0.y;
    Qs[0][akoff+2][arow]=ra0.z; Qs[0][akoff+3][arow]=ra0.w;
    Qs[0][akoff+4][arow]=ra1.x; Qs[0][akoff+5][arow]=ra1.y;
    Qs[0][akoff+6][arow]=ra1.z; Qs[0][akoff+7][arow]=ra1.w;
    Ks[0][akoff+0][arow]=rb0.x; Ks[0][akoff+1][arow]=rb0.y;
    Ks[0][akoff+2][arow]=rb0.z; Ks[0][akoff+3][arow]=rb0.w;
    Ks[0][akoff+4][arow]=rb1.x; Ks[0][akoff+5][arow]=rb1.y;
    Ks[0][akoff+6][arow]=rb1.z; Ks[0][akoff+7][arow]=rb1.w;
    __syncthreads();

    #pragma unroll
    for (int kt = 0; kt < 4; kt++) {
        int buf = kt & 1;
        if (kt + 1 < 4) {
            int k0 = (kt + 1) << 4;
            ra0 = *(const float4*)&qb[(size_t)arow * QKVN + k0 + akoff];
            ra1 = *(const float4*)&qb[(size_t)arow * QKVN + k0 + akoff + 4];
            rb0 = *(const float4*)&kb[(size_t)arow * QKVN + k0 + akoff];
            rb1 = *(const float4*)&kb[(size_t)arow * QKVN + k0 + akoff + 4];
        }
        #pragma unroll
        for (int kk = 0; kk < 16; kk++) {
            float a[8], c[8];
            *(float4*)(a)   = *(const float4*)&Qs[buf][kk][ty*8];
            *(float4*)(a+4) = *(const float4*)&Qs[buf][kk][ty*8+4];
            *(float4*)(c)   = *(const float4*)&Ks[buf][kk][tx*8];
            *(float4*)(c+4) = *(const float4*)&Ks[buf][kk][tx*8+4];
            #pragma unroll
            for (int i = 0; i < 8; i++)
                #pragma unroll
                for (int j = 0; j < 8; j++)
                    acc[i][j] += a[i] * c[j];
        }
        if (kt + 1 < 4) {
            int nb2 = buf ^ 1;
            Qs[nb2][akoff+0][arow]=ra0.x; Qs[nb2][akoff+1][arow]=ra0.y;
            Qs[nb2][akoff+2][arow]=ra0.z; Qs[nb2][akoff+3][arow]=ra0.w;
            Qs[nb2][akoff+4][arow]=ra1.x; Qs[nb2][akoff+5][arow]=ra1.y;
            Qs[nb2][akoff+6][arow]=ra1.z; Qs[nb2][akoff+7][arow]=ra1.w;
            Ks[nb2][akoff+0][arow]=rb0.x; Ks[nb2][akoff+1][arow]=rb0.y;
            Ks[nb2][akoff+2][arow]=rb0.z; Ks[nb2][akoff+3][arow]=rb0.w;
            Ks[nb2][akoff+4][arow]=rb1.x; Ks[nb2][akoff+5][arow]=rb1.y;
            Ks[nb2][akoff+6][arow]=rb1.z; Ks[nb2][akoff+7][arow]=rb1.w;
        }
        __syncthreads();
    }

    float* dst = g_s + (size_t)bh * TT * TT;
    int segt[8], segs[8];
    if (use_mask) {
        #pragma unroll
        for (int i = 0; i < 8; i++) segt[i] = g_seg[b*TT + t0 + ty*8 + i];
        #pragma unroll
        for (int j = 0; j < 8; j++) segs[j] = g_seg[b*TT + s0 + tx*8 + j];
    }
    #pragma unroll
    for (int i = 0; i < 8; i++) {
        size_t t = (size_t)(t0 + ty*8 + i);
        float o[8];
        #pragma unroll
        for (int j = 0; j < 8; j++) {
            float v = acc[i][j] * 0.125f;
            if (use_mask && segt[i] != segs[j]) v += NEGI;
            o[j] = v;
        }
        *(float4*)&dst[t * TT + s0 + tx*8]     = *(float4*)(o);
        *(float4*)&dst[t * TT + s0 + tx*8 + 4] = *(float4*)(o+4);
    }
}

// ======== BF16 scores: bf16 in (g_qkvb), bf16 out (g_sb) ========
__global__ __launch_bounds__(256) void scores_bf16_kernel(int use_mask)
{
    int bh = blockIdx.z;
    int b = bh >> 3, h = bh & 7;
    int t0 = blockIdx.y * 128, s0 = blockIdx.x * 128;
    __shared__ uint32_t Qs[2][128][9];
    __shared__ uint32_t Ks[2][128][9];
    int tid = threadIdx.x;
    int lane = tid & 31;
    int warp = tid >> 5;
    int warp_m = warp & 3;
    int warp_n = warp >> 2;
    int grp = lane >> 2;
    int tig = lane & 3;

    const int arow = tid >> 1, akoff = (tid & 1) * 8, akp = (tid & 1) * 4;
    const __nv_bfloat16* qb = g_qkvb + (size_t)(b*TT + t0) * QKVN + h*64;
    const __nv_bfloat16* kb = g_qkvb + (size_t)(b*TT + s0) * QKVN + CC + h*64;

    float acc[2][8][4];
    #pragma unroll
    for (int i = 0; i < 2; i++)
        #pragma unroll
        for (int j = 0; j < 8; j++)
            #pragma unroll
            for (int c = 0; c < 4; c++) acc[i][j][c] = 0.0f;

    uint4 uq, uk;
    uq = *(const uint4*)&qb[(size_t)arow * QKVN + akoff];
    uk = *(const uint4*)&kb[(size_t)arow * QKVN + akoff];
    Qs[0][arow][akp+0] = uq.x; Qs[0][arow][akp+1] = uq.y;
    Qs[0][arow][akp+2] = uq.z; Qs[0][arow][akp+3] = uq.w;
    Ks[0][arow][akp+0] = uk.x; Ks[0][arow][akp+1] = uk.y;
    Ks[0][arow][akp+2] = uk.z; Ks[0][arow][akp+3] = uk.w;

    #pragma unroll
    for (int kt = 0; kt < 4; kt++) {
        __syncthreads();
        int cur = kt & 1;
        if (kt + 1 < 4) {
            int k0 = (kt + 1) << 4;
            uq = *(const uint4*)&qb[(size_t)arow * QKVN + k0 + akoff];
            uk = *(const uint4*)&kb[(size_t)arow * QKVN + k0 + akoff];
        }
        {
            uint32_t af[2][4];
            #pragma unroll
            for (int mf = 0; mf < 2; mf++) {
                int m = warp_m * 32 + mf * 16 + grp;
                af[mf][0] = Qs[cur][m][tig];
                af[mf][1] = Qs[cur][m + 8][tig];
                af[mf][2] = Qs[cur][m][tig + 4];
                af[mf][3] = Qs[cur][m + 8][tig + 4];
            }
            #pragma unroll
            for (int nf = 0; nf < 8; nf++) {
                int n = warp_n * 64 + nf * 8 + grp;
                uint32_t b0 = Ks[cur][n][tig];
                uint32_t b1 = Ks[cur][n][tig + 4];
                #pragma unroll
                for (int mf = 0; mf < 2; mf++)
                    MMA_BF16(acc[mf][nf], af[mf][0], af[mf][1], af[mf][2], af[mf][3], b0, b1);
            }
        }
        if (kt + 1 < 4) {
            int nb2 = cur ^ 1;
            Qs[nb2][arow][akp+0] = uq.x; Qs[nb2][arow][akp+1] = uq.y;
            Qs[nb2][arow][akp+2] = uq.z; Qs[nb2][arow][akp+3] = uq.w;
            Ks[nb2][arow][akp+0] = uk.x; Ks[nb2][arow][akp+1] = uk.y;
            Ks[nb2][arow][akp+2] = uk.z; Ks[nb2][arow][akp+3] = uk.w;
        }
    }

    __nv_bfloat16* dst = g_sb + (size_t)bh * TT * TT;
    #pragma unroll
    for (int mf = 0; mf < 2; mf++) {
        int r_lo = warp_m * 32 + mf * 16 + grp;
        int r_hi = r_lo + 8;
        int sg_lo = 0, sg_hi = 0;
        if (use_mask) {
            sg_lo = g_seg[b*TT + t0 + r_lo];
            sg_hi = g_seg[b*TT + t0 + r_hi];
        }
        #pragma unroll
        for (int nf = 0; nf < 8; nf++) {
            int cl = warp_n * 64 + nf * 8 + tig * 2;
            float v0 = acc[mf][nf][0] * 0.125f, v1 = acc[mf][nf][1] * 0.125f;
            float v2 = acc[mf][nf][2] * 0.125f, v3 = acc[mf][nf][3] * 0.125f;
            if (use_mask) {
                int s_a = g_seg[b*TT + s0 + cl];
                int s_b = g_seg[b*TT + s0 + cl + 1];
                if (sg_lo != s_a) v0 += NEGI;
                if (sg_lo != s_b) v1 += NEGI;
                if (sg_hi != s_a) v2 += NEGI;
                if (sg_hi != s_b) v3 += NEGI;
            }
            *(uint32_t*)&dst[(size_t)(t0 + r_lo) * TT + s0 + cl] = packbf2(v0, v1);
            *(uint32_t*)&dst[(size_t)(t0 + r_hi) * TT + s0 + cl] = packbf2(v2, v3);
        }
    }
}

// ======== TF32 PV (stage0/l0 only): fp32 S @ fp32 V -> bf16 g_ab ========
__global__ __launch_bounds__(256) void pv_tf32_kernel()
{
    int bh = blockIdx.y;
    int b = bh >> 3, h = bh & 7;
    int t0 = blockIdx.x * 128;
    __shared__ float Ps[16][136];
    __shared__ float Vs[16][72];
    int tid = threadIdx.x;
    int lane = tid & 31;
    int warp = tid >> 5;
    int warp_m = warp & 3;
    int warp_n = warp >> 2;
    int grp = lane >> 2;
    int tig = lane & 3;

    const int arow = tid >> 1, akoff = (tid & 1) * 8;
    const int vk = tid >> 4, vcol = (tid & 15) * 4;

    const float* srow = g_s + (size_t)bh * TT * TT + (size_t)t0 * TT;
    const float* vb = g_qkv + (size_t)(b*TT) * QKVN + 2*CC + h*64;

    float acc[2][4][4];
    #pragma unroll
    for (int i = 0; i < 2; i++)
        #pragma unroll
        for (int j = 0; j < 4; j++)
            #pragma unroll
            for (int c = 0; c < 4; c++) acc[i][j][c] = 0.0f;

    float4 ra0, ra1, rv0;
    ra0 = *(const float4*)&srow[(size_t)arow * TT + akoff];
    ra1 = *(const float4*)&srow[(size_t)arow * TT + akoff + 4];
    rv0 = *(const float4*)&vb[(size_t)vk * QKVN + vcol];

    const int nk = TT / 16;
    for (int kt = 0; kt < nk; kt++) {
        Ps[akoff+0][arow] = f2tf32(ra0.x); Ps[akoff+1][arow] = f2tf32(ra0.y);
        Ps[akoff+2][arow] = f2tf32(ra0.z); Ps[akoff+3][arow] = f2tf32(ra0.w);
        Ps[akoff+4][arow] = f2tf32(ra1.x); Ps[akoff+5][arow] = f2tf32(ra1.y);
        Ps[akoff+6][arow] = f2tf32(ra1.z); Ps[akoff+7][arow] = f2tf32(ra1.w);
        Vs[vk][vcol+0] = f2tf32(rv0.x); Vs[vk][vcol+1] = f2tf32(rv0.y);
        Vs[vk][vcol+2] = f2tf32(rv0.z); Vs[vk][vcol+3] = f2tf32(rv0.w);
        __syncthreads();

        if (kt + 1 < nk) {
            int k0 = (kt + 1) << 4;
            ra0 = *(const float4*)&srow[(size_t)arow * TT + k0 + akoff];
            ra1 = *(const float4*)&srow[(size_t)arow * TT + k0 + akoff + 4];
            rv0 = *(const float4*)&vb[(size_t)(k0 + vk) * QKVN + vcol];
        }

        #pragma unroll
        for (int ks = 0; ks < 2; ks++) {
            int kb2 = ks * 8;
            uint32_t af[2][4];
            #pragma unroll
            for (int mf = 0; mf < 2; mf++) {
                int m = warp_m * 32 + mf * 16 + grp;
                af[mf][0] = __float_as_uint(Ps[kb2 + tig][m]);
                af[mf][1] = __float_as_uint(Ps[kb2 + tig][m + 8]);
                af[mf][2] = __float_as_uint(Ps[kb2 + tig + 4][m]);
                af[mf][3] = __float_as_uint(Ps[kb2 + tig + 4][m + 8]);
            }
            #pragma unroll
            for (int nf = 0; nf < 4; nf++) {
                int n = warp_n * 32 + nf * 8 + grp;
                uint32_t b0 = __float_as_uint(Vs[kb2 + tig][n]);
                uint32_t b1 = __float_as_uint(Vs[kb2 + tig + 4][n]);
                #pragma unroll
                for (int mf = 0; mf < 2; mf++)
                    MMA_TF32(acc[mf][nf], af[mf][0], af[mf][1], af[mf][2], af[mf][3], b0, b1);
            }
        }
        __syncthreads();
    }

    #pragma unroll
    for (int mf = 0; mf < 2; mf++) {
        int r_lo = warp_m * 32 + mf * 16 + grp;
        int r_hi = r_lo + 8;
        #pragma unroll
        for (int nf = 0; nf < 4; nf++) {
            int cl = warp_n * 32 + nf * 8 + tig * 2;
            *(uint32_t*)&g_ab[(size_t)(b*TT + t0 + r_lo) * CC + h*64 + cl] =
                packbf2(acc[mf][nf][0], acc[mf][nf][1]);
            *(uint32_t*)&g_ab[(size_t)(b*TT + t0 + r_hi) * CC + h*64 + cl] =
                packbf2(acc[mf][nf][2], acc[mf][nf][3]);
        }
    }
}

// ======== FUSED softmax + PV, bf16 S + bf16 V -> bf16 g_ab (fast exp) ========
__global__ __launch_bounds__(256) void fused_softmax_pv_kernel(int docolsum)
{
    int bh = blockIdx.y;
    int b = bh >> 3, h = bh & 7;
    int t0 = blockIdx.x * 128;
    const __nv_bfloat16* srow = g_sb + (size_t)bh * TT * TT + (size_t)t0 * TT;
    const __nv_bfloat16* vb = g_qkvb + (size_t)(b*TT) * QKVN + 2*CC + h*64;

    __shared__ float rowm[128];
    __shared__ float rowstat[128];
    __shared__ float Ps[16][136];
    __shared__ float Vs[16][72];
    __shared__ float colpart[16][8];

    int tid = threadIdx.x;
    int lane = tid & 31;
    int warp = tid >> 5;
    int warp_m = warp & 3;
    int warp_n = warp >> 2;
    int grp = lane >> 2;
    int tig = lane & 3;

    for (int r = warp * 16; r < warp * 16 + 16; r++) {
        const __nv_bfloat16* p = srow + (size_t)r * TT;
        float m = -3.4e38f, l = 0.0f;
        #pragma unroll
        for (int i = 0; i < 4; i++) {
            uint4 u = *(const uint4*)&p[lane * 8 + i * 256];
            float2 a0 = bf2f(u.x), a1 = bf2f(u.y), a2 = bf2f(u.z), a3 = bf2f(u.w);
            float mx = fmaxf(fmaxf(fmaxf(a0.x, a0.y), fmaxf(a1.x, a1.y)),
                             fmaxf(fmaxf(a2.x, a2.y), fmaxf(a3.x, a3.y)));
            if (docolsum) {
                float mn = fmaxf(m, mx);
                l = l * __expf(m - mn)
                  + __expf(a0.x - mn) + __expf(a0.y - mn) + __expf(a1.x - mn) + __expf(a1.y - mn)
                  + __expf(a2.x - mn) + __expf(a2.y - mn) + __expf(a3.x - mn) + __expf(a3.y - mn);
                m = mn;
            } else {
                m = fmaxf(m, mx);
            }
        }
        #pragma unroll
        for (int o = 16; o > 0; o >>= 1) {
            float m2 = __shfl_xor_sync(0xffffffffu, m, o);
            if (docolsum) {
                float l2 = __shfl_xor_sync(0xffffffffu, l, o);
                float mn = fmaxf(m, m2);
                l = l * __expf(m - mn) + l2 * __expf(m2 - mn);
                m = mn;
            } else {
                m = fmaxf(m, m2);
            }
        }
        if (lane == 0) { rowm[r] = m; rowstat[r] = l; }
    }
    __syncthreads();

    const int arow = tid >> 1, akoff = (tid & 1) * 8;
    const int vk = tid >> 4, vcol = (tid & 15) * 4;
    float minv = rowm[arow];
    float rl = docolsum ? (1.0f / rowstat[arow]) : 1.0f;
    float lpart = 0.0f;

    float acc[2][4][4];
    #pragma unroll
    for (int i = 0; i < 2; i++)
        #pragma unroll
        for (int j = 0; j < 4; j++)
            #pragma unroll
            for (int c = 0; c < 4; c++) acc[i][j][c] = 0.0f;

    float* wpdst = 0;
    if (docolsum)
        wpdst = g_wp + ((size_t)bh * 8 + blockIdx.x) * TT;

    const int nk = TT / 16;
    for (int kt = 0; kt < nk; kt++) {
        uint4 u = *(const uint4*)&srow[(size_t)arow * TT + kt*16 + akoff];
        float2 a0 = bf2f(u.x), a1 = bf2f(u.y), a2 = bf2f(u.z), a3 = bf2f(u.w);
        float pv_[8];
        pv_[0] = __expf(a0.x - minv) * rl; pv_[1] = __expf(a0.y - minv) * rl;
        pv_[2] = __expf(a1.x - minv) * rl; pv_[3] = __expf(a1.y - minv) * rl;
        pv_[4] = __expf(a2.x - minv) * rl; pv_[5] = __expf(a2.y - minv) * rl;
        pv_[6] = __expf(a3.x - minv) * rl; pv_[7] = __expf(a3.y - minv) * rl;
        if (!docolsum) {
            #pragma unroll
            for (int j = 0; j < 8; j++) lpart += pv_[j];
        }
        #pragma unroll
        for (int j = 0; j < 8; j++) Ps[akoff + j][arow] = f2tf32(pv_[j]);

        uint2 uv = *(const uint2*)&vb[(size_t)(kt*16 + vk) * QKVN + vcol];
        float2 v0 = bf2f(uv.x), v1 = bf2f(uv.y);
        Vs[vk][vcol+0] = f2tf32(v0.x); Vs[vk][vcol+1] = f2tf32(v0.y);
        Vs[vk][vcol+2] = f2tf32(v1.x); Vs[vk][vcol+3] = f2tf32(v1.y);
        __syncthreads();

        if (docolsum) {
            if (tid < 128) {
                int c = tid >> 3, rseg = tid & 7;
                float cs = 0.0f;
                #pragma unroll
                for (int j = 0; j < 16; j++) cs += Ps[c][rseg * 16 + j];
                colpart[c][rseg] = cs;
            }
            __syncthreads();
            if (tid < 16) {
                float cs = 0.0f;
                #pragma unroll
                for (int j = 0; j < 8; j++) cs += colpart[tid][j];
                wpdst[kt * 16 + tid] = cs;
            }
        }

        #pragma unroll
        for (int ks = 0; ks < 2; ks++) {
            int kb2 = ks * 8;
            uint32_t af[2][4];
            #pragma unroll
            for (int mf = 0; mf < 2; mf++) {
                int m = warp_m * 32 + mf * 16 + grp;
                af[mf][0] = __float_as_uint(Ps[kb2 + tig][m]);
                af[mf][1] = __float_as_uint(Ps[kb2 + tig][m + 8]);
                af[mf][2] = __float_as_uint(Ps[kb2 + tig + 4][m]);
                af[mf][3] = __float_as_uint(Ps[kb2 + tig + 4][m + 8]);
            }
            #pragma unroll
            for (int nf = 0; nf < 4; nf++) {
                int n = warp_n * 32 + nf * 8 + grp;
                uint32_t b0 = __float_as_uint(Vs[kb2 + tig][n]);
                uint32_t b1 = __float_as_uint(Vs[kb2 + tig + 4][n]);
                #pragma unroll
                for (int mf = 0; mf < 2; mf++)
                    MMA_TF32(acc[mf][nf], af[mf][0], af[mf][1], af[mf][2], af[mf][3], b0, b1);
            }
        }
        __syncthreads();
    }

    if (!docolsum) {
        lpart += __shfl_xor_sync(0xffffffffu, lpart, 1);
        if ((tid & 1) == 0) rowstat[arow] = lpart;
        __syncthreads();
    }

    #pragma unroll
    for (int mf = 0; mf < 2; mf++) {
        int r_lo = warp_m * 32 + mf * 16 + grp;
        int r_hi = r_lo + 8;
        float inv_lo = docolsum ? 1.0f : (1.0f / rowstat[r_lo]);
        float inv_hi = docolsum ? 1.0f : (1.0f / rowstat[r_hi]);
        #pragma unroll
        for (int nf = 0; nf < 4; nf++) {
            int cl = warp_n * 32 + nf * 8 + tig * 2;
            *(uint32_t*)&g_ab[(size_t)(b*TT + t0 + r_lo) * CC + h*64 + cl] =
                packbf2(acc[mf][nf][0] * inv_lo, acc[mf][nf][1] * inv_lo);
            *(uint32_t*)&g_ab[(size_t)(b*TT + t0 + r_hi) * CC + h*64 + cl] =
                packbf2(acc[mf][nf][2] * inv_hi, acc[mf][nf][3] * inv_hi);
        }
    }
}

// ---------------- reduce colsum partials ----------------
__global__ void wreduce_kernel()
{
    int idx = blockIdx.x * 256 + threadIdx.x;
    int b = idx / TT, s = idx % TT;
    float acc = 0.0f;
    #pragma unroll 8
    for (int j = 0; j < HH * 8; j++)
        acc += g_wp[((size_t)(b * HH * 8 + j)) * TT + s];
    g_w[idx] = acc * (1.0f / HH);
}

// ---------------- row softmax (stage0/l0 only — exact order) ----------------
__global__ void softmax_rows_kernel(float* __restrict__ S)
{
    float* p = S + (size_t)blockIdx.x * TT;
    int tid = threadIdx.x;
    float v[4];
    float m = -3.4e38f;
    #pragma unroll
    for (int i = 0; i < 4; i++) { v[i] = p[tid + i * 256]; m = fmaxf(m, v[i]); }
    __shared__ float red[256];
    red[tid] = m; __syncthreads();
    for (int s = 128; s > 0; s >>= 1) { if (tid < s) red[tid] = fmaxf(red[tid], red[tid + s]); __syncthreads(); }
    float mx = red[0];
    __syncthreads();
    float sum = 0.0f;
    #pragma unroll
    for (int i = 0; i < 4; i++) { v[i] = expf(v[i] - mx); sum += v[i]; }
    red[tid] = sum; __syncthreads();
    for (int s = 128; s > 0; s >>= 1) { if (tid < s) red[tid] += red[tid + s]; __syncthreads(); }
    float inv = 1.0f / red[0];
    #pragma unroll
    for (int i = 0; i < 4; i++) p[tid + i * 256] = v[i] * inv;
}

// ---------------- head-averaged probs (stage0/l0 only) ----------------
__global__ void head_avg_kernel()
{
    size_t idx = (size_t)blockIdx.x * 256 + threadIdx.x;
    size_t b = idx / ((size_t)TT * TT / 4);
    size_t r = idx % ((size_t)TT * TT / 4);
    float4 sum = make_float4(0.f, 0.f, 0.f, 0.f);
    #pragma unroll
    for (int h = 0; h < HH; h++) {
        float4 x = *((const float4*)(g_s + (b * HH + h) * (size_t)TT * TT) + r);
        sum.x += x.x; sum.y += x.y; sum.z += x.z; sum.w += x.w;
    }
    sum.x *= (1.0f/HH); sum.y *= (1.0f/HH); sum.z *= (1.0f/HH); sum.w *= (1.0f/HH);
    *((float4*)(g_p0 + b * (size_t)TT * TT) + r) = sum;
}

// ---------------- out = LN(res + add), fp32 + bf16 copies ----------------
__global__ void ln_residual_kernel(const float* __restrict__ res, const float* __restrict__ add,
                                   float* __restrict__ out, __nv_bfloat16* __restrict__ outb,
                                   const float* __restrict__ gamma, const float* __restrict__ beta)
{
    int row = blockIdx.x, tid = threadIdx.x;
    const float* r = res + (size_t)row * CC;
    const float* a = add + (size_t)row * CC;
    float v0 = r[tid] + a[tid];
    float v1 = r[tid + 256] + a[tid + 256];
    __shared__ float red[256];
    red[tid] = v0 + v1; __syncthreads();
    for (int s = 128; s > 0; s >>= 1) { if (tid < s) red[tid] += red[tid + s]; __syncthreads(); }
    float mu = red[0] * (1.0f / CC);
    __syncthreads();
    float d0 = v0 - mu, d1 = v1 - mu;
    red[tid] = d0 * d0 + d1 * d1; __syncthreads();
    for (int s = 128; s > 0; s >>= 1) { if (tid < s) red[tid] += red[tid + s]; __syncthreads(); }
    float rstd = rsqrtf(red[0] * (1.0f / CC) + 1e-5f);
    float o0 = d0 * rstd * gamma[tid] + beta[tid];
    float o1 = d1 * rstd * gamma[tid + 256] + beta[tid + 256];
    float* o = out + (size_t)row * CC;
    o[tid] = o0; o[tid + 256] = o1;
    __nv_bfloat16* ob = outb + (size_t)row * CC;
    ob[tid] = __float2bfloat16(o0);
    ob[tid + 256] = __float2bfloat16(o1);
}

// ---------------- w[b,s] = sum_t p0[b,t,s] (stage0 only, order-preserving) ----
__global__ void colsum_kernel()
{
    int idx = blockIdx.x * 256 + threadIdx.x;
    int b = idx / TT, s = idx % TT;
    const float* base = g_p0 + (size_t)b * TT * TT + s;
    float acc = 0.0f;
    for (int t = 0; t < TT; t += 8) {
        float v[8];
        #pragma unroll
        for (int j = 0; j < 8; j++) v[j] = base[(size_t)(t + j) * TT];
        #pragma unroll
        for (int j = 0; j < 8; j++) acc += v[j];
    }
    g_w[idx] = acc;
}

// ---------------- segment scan ----------------
__global__ void segment_kernel()
{
    int b = blockIdx.x, tid = threadIdx.x;
    __shared__ float smin[256], smax[256];
    float lo = 3.4e38f, hi = -3.4e38f;
    for (int t = tid; t < TT; t += 256) {
        float v = g_w[b * TT + t];
        lo = fminf(lo, v); hi = fmaxf(hi, v);
    }
    smin[tid] = lo; smax[tid] = hi; __syncthreads();
    for (int s = 128; s > 0; s >>= 1) {
        if (tid < s) { smin[tid] = fminf(smin[tid], smin[tid + s]); smax[tid] = fmaxf(smax[tid], smax[tid + s]); }
        __syncthreads();
    }
    if (tid == 0) {
        float wmin = smin[0], wmax = smax[0];
        float denom = fmaxf(wmax - wmin, 1e-12f);
        bool prev = ((g_w[b * TT + 0] - wmin) / denom) >= 0.5f;
        int start = 0, segc = 0;
        g_seg[b * TT + 0] = 0;
        g_segstart[b * (TT + 1) + 0] = 0;
        for (int t = 1; t < TT; t++) {
            bool cur = ((g_w[b * TT + t] - wmin) / denom) >= 0.5f;
            if (cur != prev && (start + 1) != t) {
                start = t; segc++;
                g_segstart[b * (TT + 1) + segc] = t;
            }
            g_seg[b * TT + t] = segc;
            prev = cur;
        }
        g_nseg[b] = segc + 1;
        g_segstart[b * (TT + 1) + segc + 1] = TT;
    }
}

// ---------------- aw = softmax_s(w) ----------------
__global__ void batch_softmax_kernel()
{
    int b = blockIdx.x, tid = threadIdx.x;
    __shared__ float red[256];
    float v[4];
    float m = -3.4e38f;
    #pragma unroll
    for (int i = 0; i < 4; i++) { v[i] = g_w[b * TT + tid + i * 256]; m = fmaxf(m, v[i]); }
    red[tid] = m; __syncthreads();
    for (int s = 128; s > 0; s >>= 1) { if (tid < s) red[tid] = fmaxf(red[tid], red[tid + s]); __syncthreads(); }
    float mx = red[0];
    __syncthreads();
    float sum = 0.0f;
    #pragma unroll
    for (int i = 0; i < 4; i++) { v[i] = expf(v[i] - mx); sum += v[i]; }
    red[tid] = sum; __syncthreads();
    for (int s = 128; s > 0; s >>= 1) { if (tid < s) red[tid] += red[tid + s]; __syncthreads(); }
    float inv = 1.0f / red[0];
    #pragma unroll
    for (int i = 0; i < 4; i++) g_aw[b * TT + tid + i * 256] = v[i] * inv;
}

// ---------------- word tokens ----------------
__global__ void word_tokens_kernel(float* __restrict__ out)
{
    int b = blockIdx.y, i = blockIdx.x, tid = threadIdx.x;
    float* dst = out + ((size_t)b * 2 * TT + i) * CC;
    int ns = g_nseg[b];
    if (i >= ns) {
        for (int c = tid; c < CC; c += 256) dst[c] = 0.0f;
        return;
    }
    int t0 = g_segstart[b * (TT + 1) + i];
    int t1 = g_segstart[b * (TT + 1) + i + 1];
    for (int c = tid; c < CC; c += 256) {
        float acc = 0.0f;
        for (int t = t0; t < t1; t++)
            acc += g_x[((size_t)b * TT + t) * CC + c] * g_aw[b * TT + t];
        dst[c] = acc;
    }
}

__global__ void copyx_kernel(const float* __restrict__ xin, float* __restrict__ out)
{
    size_t idx = (size_t)blockIdx.x * 256 + threadIdx.x;
    size_t b = idx / ((size_t)TT * CC);
    size_t rem = idx % ((size_t)TT * CC);
    out[b * (size_t)2 * TT * CC + (size_t)TT * CC + rem] = xin[idx];
}

__global__ void wm_kernel(float* __restrict__ wmout)
{
    size_t idx = (size_t)blockIdx.x * 256 + threadIdx.x;
    size_t b = idx / ((size_t)TT * TT);
    int i = (int)((idx / TT) % TT);
    int t = (int)(idx % TT);
    wmout[idx] = (g_seg[b * TT + t] == i) ? 1.0f : 0.0f;
}

// ---------------- host orchestration ----------------
extern "C" void kernel_launch(void* const* d_in, const int* in_sizes, int n_in,
                              void* d_out, int out_size)
{
    const float* x_in = (const float*)d_in[0];
    const float* Wqkv = (const float*)d_in[1];
    const float* bqkv = (const float*)d_in[2];
    const float* Wo   = (const float*)d_in[3];
    const float* bo   = (const float*)d_in[4];
    const float* W1   = (const float*)d_in[5];
    const float* b1   = (const float*)d_in[6];
    const float* W2   = (const float*)d_in[7];
    const float* b2   = (const float*)d_in[8];
    const float* lng  = (const float*)d_in[9];
    const float* lnb  = (const float*)d_in[10];
    float* out = (float*)d_out;

    float *p_x, *p_qkv, *p_s, *p_t;
    __nv_bfloat16 *p_xb, *p_ab, *p_hb, *p_qkvb, *p_wqkv_b, *p_wo_b, *p_w1_b, *p_w2_b;
    cudaGetSymbolAddress((void**)&p_x, g_x);
    cudaGetSymbolAddress((void**)&p_qkv, g_qkv);
    cudaGetSymbolAddress((void**)&p_s, g_s);
    cudaGetSymbolAddress((void**)&p_t, g_t);
    cudaGetSymbolAddress((void**)&p_xb, g_xb);
    cudaGetSymbolAddress((void**)&p_ab, g_ab);
    cudaGetSymbolAddress((void**)&p_hb, g_hb);
    cudaGetSymbolAddress((void**)&p_qkvb, g_qkvb);
    cudaGetSymbolAddress((void**)&p_wqkv_b, g_wqkv_b);
    cudaGetSymbolAddress((void**)&p_wo_b, g_wo_b);
    cudaGetSymbolAddress((void**)&p_w1_b, g_w1_b);
    cudaGetSymbolAddress((void**)&p_w2_b, g_w2_b);

    cudaMemcpyAsync(p_x, x_in, sizeof(float) * (size_t)BT * CC, cudaMemcpyDeviceToDevice);
    cvt_kernel<<<(int)(((size_t)BT * CC) / 256), 256>>>(x_in, p_xb);

    dim3 tb(32, 8);
    transpose_cvt_all_kernel<<<dim3(1024, 1, 24), tb>>>(Wqkv, Wo, W1, W2,
                                                        p_wqkv_b, p_wo_b, p_w1_b, p_w2_b);

    dim3 grid_qkv(QKVN / 128, BT / 128);
    dim3 grid_cc64(CC / 128, BT / 64);     // 4 x 64 = 256 blocks for N=512 GEMMs
    dim3 grid_ff(FF / 128, BT / 128);
    dim3 grid_qk(2 * CC / 128, BT / 128);
    dim3 grid_sc(TT / 128, TT / 128, BB * HH);
    dim3 grid_pv(TT / 128, BB * HH);

    for (int stage = 0; stage < 2; stage++) {
        int use_mask = (stage == 1);
        for (int l = 0; l < 2; l++) {
            int sl = stage * 2 + l;
            const __nv_bfloat16* Wqb = p_wqkv_b + (size_t)sl * 3 * CC * CC;
            const float* bb = bqkv + (size_t)sl * 3 * CC;

            if (stage == 0 && l == 0) {
                // seg-critical exact island (fp32 throughout for probs0 path)
                gemm_kernel<<<grid_qk, 256>>>(p_x, Wqkv + (size_t)sl * 3 * CC * CC, bb,
                                              p_qkv, BT, QKVN, CC, 0, CC);
                gemm_bb64_kernel<<<grid_cc64, 256>>>(p_xb, Wqb + (size_t)2 * CC * CC,
                                                     bb + 2 * CC, p_qkv + 2 * CC, 0,
                                                     QKVN, CC, 0, 0);
                scores_kernel<<<grid_sc, 256>>>(use_mask);
                softmax_rows_kernel<<<BB * HH * TT, 256>>>(p_s);
                head_avg_kernel<<<(int)(((size_t)BB * TT * TT / 4) / 256), 256>>>();
                pv_tf32_kernel<<<grid_pv, 256>>>();
            } else {
                gemm_bb_kernel<<<grid_qkv, 256>>>(p_xb, Wqb, bb, 0, p_qkvb,
                                                  QKVN, CC, 0, 1);
                scores_bf16_kernel<<<grid_sc, 256>>>(use_mask);
                int docolsum = (stage == 1 && l == 0) ? 1 : 0;
                fused_softmax_pv_kernel<<<grid_pv, 256>>>(docolsum);
                if (docolsum)
                    wreduce_kernel<<<BT / 256, 256>>>();
            }

            gemm_bb64_kernel<<<grid_cc64, 256>>>(p_ab, p_wo_b + (size_t)sl * CC * CC,
                                                 bo + (size_t)sl * CC, p_t, 0, CC, CC, 0, 0);
            ln_residual_kernel<<<BT, 256>>>(p_x, p_t, p_x, p_xb,
                                            lng + (size_t)(sl * 2 + 0) * CC,
                                            lnb + (size_t)(sl * 2 + 0) * CC);

            gemm_bb_kernel<<<grid_ff, 256>>>(p_xb, p_w1_b + (size_t)sl * FF * CC,
                                             b1 + (size_t)sl * FF, 0, p_hb, FF, CC, 1, 1);
            gemm_bb64_kernel<<<grid_cc64, 256>>>(p_hb, p_w2_b + (size_t)sl * CC * FF,
                                                 b2 + (size_t)sl * CC, p_t, 0, CC, FF, 0, 0);
            ln_residual_kernel<<<BT, 256>>>(p_x, p_t, p_x, p_xb,
                                            lng + (size_t)(sl * 2 + 1) * CC,
                                            lnb + (size_t)(sl * 2 + 1) * CC);
        }
        if (stage == 0) {
            colsum_kernel<<<BT / 256, 256>>>();
            segment_kernel<<<BB, 256>>>();
        } else {
            batch_softmax_kernel<<<BB, 256>>>();
        }
    }

    word_tokens_kernel<<<dim3(TT, BB), 256>>>(out);
    copyx_kernel<<<(int)(((size_t)BT * CC) / 256), 256>>>(x_in, out);
    wm_kernel<<<(int)(((size_t)BB * TT * TT) / 256), 256>>>(out + (size_t)BB * 2 * TT * CC);
}

// round 15
// speedup vs baseline: 1.0778x; 1.0778x over previous
#include <cuda_runtime.h>
#include <cuda_bf16.h>
#include <math.h>
#include <stdint.h>

// Problem constants
#define BB 4
#define TT 1024
#define CC 512
#define HH 8
#define DH 64
#define FF 2048
#define BT (BB*TT)
#define NEGI (-1e9f)
#define QKVN (3*CC)

// ---------------- scratch ----------------
__device__ float g_x[BT*CC];
__device__ float g_qkv[BT*QKVN];
__device__ float g_s[(size_t)BB*HH*TT*TT];
__device__ float g_p0[(size_t)BB*TT*TT];
__device__ float g_t[BT*CC];
__device__ float g_w[BT];
__device__ float g_aw[BT];
__device__ float g_wp[BB*HH*8*TT];
__device__ int   g_seg[BT];
__device__ int   g_segstart[BB*(TT+1)];
__device__ int   g_nseg[BB];

// bf16 buffers
__device__ __nv_bfloat16 g_xb[BT*CC];
__device__ __nv_bfloat16 g_ab[BT*CC];
__device__ __nv_bfloat16 g_hb[BT*FF];
__device__ __nv_bfloat16 g_qkvb[BT*QKVN];
__device__ __nv_bfloat16 g_sb[(size_t)BB*HH*TT*TT];
__device__ __nv_bfloat16 g_wqkv_b[4*3*CC*CC];
__device__ __nv_bfloat16 g_wo_b[4*CC*CC];
__device__ __nv_bfloat16 g_w1_b[4*FF*CC];
__device__ __nv_bfloat16 g_w2_b[4*CC*FF];

__device__ __forceinline__ float f2tf32(float x) {
    uint32_t r;
    asm("cvt.rna.tf32.f32 %0, %1;" : "=r"(r) : "f"(x));
    return __uint_as_float(r);
}
__device__ __forceinline__ uint32_t packbf2(float lo, float hi) {
    uint32_t r;
    asm("cvt.rn.bf16x2.f32 %0, %1, %2;" : "=r"(r) : "f"(hi), "f"(lo));
    return r;
}
__device__ __forceinline__ float2 bf2f(uint32_t u) {
    __nv_bfloat162 h = *reinterpret_cast<__nv_bfloat162*>(&u);
    return __bfloat1622float2(h);
}

#define MMA_TF32(acc, a0,a1,a2,a3, b0,b1) \
    asm("mma.sync.aligned.m16n8k8.row.col.f32.tf32.tf32.f32 " \
        "{%0,%1,%2,%3}, {%4,%5,%6,%7}, {%8,%9}, {%0,%1,%2,%3};" \
        : "+f"(acc[0]), "+f"(acc[1]), "+f"(acc[2]), "+f"(acc[3]) \
        : "r"(a0), "r"(a1), "r"(a2), "r"(a3), "r"(b0), "r"(b1))

#define MMA_BF16(acc, a0,a1,a2,a3, b0,b1) \
    asm("mma.sync.aligned.m16n8k16.row.col.f32.bf16.bf16.f32 " \
        "{%0,%1,%2,%3}, {%4,%5,%6,%7}, {%8,%9}, {%0,%1,%2,%3};" \
        : "+f"(acc[0]), "+f"(acc[1]), "+f"(acc[2]), "+f"(acc[3]) \
        : "r"(a0), "r"(a1), "r"(a2), "r"(a3), "r"(b0), "r"(b1))

// ======== single-launch batched transpose+convert (24 weight matrices) ========
__global__ void transpose_cvt_all_kernel(const float* __restrict__ Wqkv,
                                         const float* __restrict__ Wo,
                                         const float* __restrict__ W1,
                                         const float* __restrict__ W2,
                                         __nv_bfloat16* __restrict__ dq,
                                         __nv_bfloat16* __restrict__ dwo,
                                         __nv_bfloat16* __restrict__ d1,
                                         __nv_bfloat16* __restrict__ d2)
{
    __shared__ float tile[32][33];
    int z = blockIdx.z;
    const float* src;
    __nv_bfloat16* dst;
    int K, N;
    if (z < 12)      { src = Wqkv + (size_t)z * CC * CC; dst = dq + (size_t)z * CC * CC; K = CC; N = CC; }
    else if (z < 16) { int m = z - 12; src = Wo + (size_t)m * CC * CC; dst = dwo + (size_t)m * CC * CC; K = CC; N = CC; }
    else if (z < 20) { int m = z - 16; src = W1 + (size_t)m * CC * FF; dst = d1 + (size_t)m * FF * CC; K = CC; N = FF; }
    else             { int m = z - 20; src = W2 + (size_t)m * FF * CC; dst = d2 + (size_t)m * CC * FF; K = FF; N = CC; }

    int ntn = N / 32, ntk = K / 32;
    int flat = blockIdx.x;
    if (flat >= ntn * ntk) return;
    int nb = (flat % ntn) * 32, kb = (flat / ntn) * 32;
    int tx = threadIdx.x, ty = threadIdx.y;
    #pragma unroll
    for (int j = ty; j < 32; j += 8)
        tile[j][tx] = src[(size_t)(kb + j) * N + nb + tx];
    __syncthreads();
    #pragma unroll
    for (int j = ty; j < 32; j += 8)
        dst[(size_t)(nb + j) * K + kb + tx] = __float2bfloat16(tile[tx][j]);
}

__global__ void cvt_kernel(const float* __restrict__ src, __nv_bfloat16* __restrict__ dst)
{
    size_t i = (size_t)blockIdx.x * 256 + threadIdx.x;
    dst[i] = __float2bfloat16(src[i]);
}

// ======== BF16xBF16 GEMM: 128x128x16, 2-stage (R12-proven) ========
__global__ __launch_bounds__(256) void gemm_bb_kernel(
    const __nv_bfloat16* __restrict__ A, const __nv_bfloat16* __restrict__ Wt,
    const float* __restrict__ bias, float* __restrict__ outf,
    __nv_bfloat16* __restrict__ outb, int nstride, int K, int relu, int obf)
{
    __shared__ uint32_t As[2][128][9];
    __shared__ uint32_t Bs[2][128][9];
    int tid = threadIdx.x;
    int lane = tid & 31;
    int warp = tid >> 5;
    int warp_m = warp & 3;
    int warp_n = warp >> 2;
    int grp = lane >> 2;
    int tig = lane & 3;

    int row0 = blockIdx.y * 128, col0 = blockIdx.x * 128;
    const __nv_bfloat16* Ab = A + (size_t)row0 * K;
    const __nv_bfloat16* Wb = Wt + (size_t)col0 * K;

    const int arow = tid >> 1, akoff = (tid & 1) * 8, akp = (tid & 1) * 4;

    float acc[2][8][4];
    #pragma unroll
    for (int i = 0; i < 2; i++)
        #pragma unroll
        for (int j = 0; j < 8; j++)
            #pragma unroll
            for (int c = 0; c < 4; c++) acc[i][j][c] = 0.0f;

    uint4 ua, ub;
    ua = *(const uint4*)&Ab[(size_t)arow * K + akoff];
    ub = *(const uint4*)&Wb[(size_t)arow * K + akoff];
    As[0][arow][akp+0] = ua.x; As[0][arow][akp+1] = ua.y;
    As[0][arow][akp+2] = ua.z; As[0][arow][akp+3] = ua.w;
    Bs[0][arow][akp+0] = ub.x; Bs[0][arow][akp+1] = ub.y;
    Bs[0][arow][akp+2] = ub.z; Bs[0][arow][akp+3] = ub.w;

    int nk = K >> 4;
    for (int kt = 0; kt < nk; kt++) {
        __syncthreads();
        int cur = kt & 1;
        if (kt + 1 < nk) {
            int k0 = (kt + 1) << 4;
            ua = *(const uint4*)&Ab[(size_t)arow * K + k0 + akoff];
            ub = *(const uint4*)&Wb[(size_t)arow * K + k0 + akoff];
        }
        {
            uint32_t af[2][4];
            #pragma unroll
            for (int mf = 0; mf < 2; mf++) {
                int m = warp_m * 32 + mf * 16 + grp;
                af[mf][0] = As[cur][m][tig];
                af[mf][1] = As[cur][m + 8][tig];
                af[mf][2] = As[cur][m][tig + 4];
                af[mf][3] = As[cur][m + 8][tig + 4];
            }
            #pragma unroll
            for (int nf = 0; nf < 8; nf++) {
                int n = warp_n * 64 + nf * 8 + grp;
                uint32_t b0 = Bs[cur][n][tig];
                uint32_t b1 = Bs[cur][n][tig + 4];
                #pragma unroll
                for (int mf = 0; mf < 2; mf++)
                    MMA_BF16(acc[mf][nf], af[mf][0], af[mf][1], af[mf][2], af[mf][3], b0, b1);
            }
        }
        if (kt + 1 < nk) {
            int nb = cur ^ 1;
            As[nb][arow][akp+0] = ua.x; As[nb][arow][akp+1] = ua.y;
            As[nb][arow][akp+2] = ua.z; As[nb][arow][akp+3] = ua.w;
            Bs[nb][arow][akp+0] = ub.x; Bs[nb][arow][akp+1] = ub.y;
            Bs[nb][arow][akp+2] = ub.z; Bs[nb][arow][akp+3] = ub.w;
        }
    }

    #pragma unroll
    for (int mf = 0; mf < 2; mf++) {
        int r_lo = row0 + warp_m * 32 + mf * 16 + grp;
        int r_hi = r_lo + 8;
        #pragma unroll
        for (int nf = 0; nf < 8; nf++) {
            int cl = warp_n * 64 + nf * 8 + tig * 2;
            float bv0 = bias[col0 + cl], bv1 = bias[col0 + cl + 1];
            float v0 = acc[mf][nf][0] + bv0, v1 = acc[mf][nf][1] + bv1;
            float v2 = acc[mf][nf][2] + bv0, v3 = acc[mf][nf][3] + bv1;
            if (relu) { v0 = fmaxf(v0, 0.f); v1 = fmaxf(v1, 0.f);
                        v2 = fmaxf(v2, 0.f); v3 = fmaxf(v3, 0.f); }
            if (!obf) {
                *(float2*)&outf[(size_t)r_lo * nstride + col0 + cl] = make_float2(v0, v1);
                *(float2*)&outf[(size_t)r_hi * nstride + col0 + cl] = make_float2(v2, v3);
            } else {
                *(uint32_t*)&outb[(size_t)r_lo * nstride + col0 + cl] = packbf2(v0, v1);
                *(uint32_t*)&outb[(size_t)r_hi * nstride + col0 + cl] = packbf2(v2, v3);
            }
        }
    }
}

// ======== exact fp32 SIMT GEMM (seg-critical stage0/l0 Q,K) ========
__global__ __launch_bounds__(256) void gemm_kernel(
    const float* __restrict__ A, const float* __restrict__ W,
    const float* __restrict__ bias, float* __restrict__ Cout,
    int M, int Ntot, int K, int relu, int sub_n)
{
    __shared__ float As[2][16][128];
    __shared__ float Bs[2][16][128];
    int tid = threadIdx.x;
    int tx = tid & 15, ty = tid >> 4;
    int row0 = blockIdx.y * 128, col0 = blockIdx.x * 128;
    int mat = col0 / sub_n;
    int coln = col0 % sub_n;
    const float* Wb = W + (size_t)mat * K * sub_n + coln;
    const float* Ab = A + (size_t)row0 * K;

    const int arow = tid >> 1, akoff = (tid & 1) * 8;
    const int bk = tid >> 4, bcol = (tid & 15) * 8;

    float acc[8][8] = {};
    float4 ra0, ra1, rb0, rb1;

    ra0 = *(const float4*)&Ab[(size_t)arow * K + akoff];
    ra1 = *(const float4*)&Ab[(size_t)arow * K + akoff + 4];
    rb0 = *(const float4*)&Wb[(size_t)bk * sub_n + bcol];
    rb1 = *(const float4*)&Wb[(size_t)bk * sub_n + bcol + 4];
    As[0][akoff+0][arow]=ra0.x; As[0][akoff+1][arow]=ra0.y;
    As[0][akoff+2][arow]=ra0.z; As[0][akoff+3][arow]=ra0.w;
    As[0][akoff+4][arow]=ra1.x; As[0][akoff+5][arow]=ra1.y;
    As[0][akoff+6][arow]=ra1.z; As[0][akoff+7][arow]=ra1.w;
    *(float4*)&Bs[0][bk][bcol]   = rb0;
    *(float4*)&Bs[0][bk][bcol+4] = rb1;
    __syncthreads();

    int nk = K >> 4;
    for (int kt = 0; kt < nk; kt++) {
        int buf = kt & 1;
        if (kt + 1 < nk) {
            int k0 = (kt + 1) << 4;
            ra0 = *(const float4*)&Ab[(size_t)arow * K + k0 + akoff];
            ra1 = *(const float4*)&Ab[(size_t)arow * K + k0 + akoff + 4];
            rb0 = *(const float4*)&Wb[(size_t)(k0 + bk) * sub_n + bcol];
            rb1 = *(const float4*)&Wb[(size_t)(k0 + bk) * sub_n + bcol + 4];
        }
        #pragma unroll
        for (int kk = 0; kk < 16; kk++) {
            float a[8], b[8];
            *(float4*)(a)   = *(const float4*)&As[buf][kk][ty*8];
            *(float4*)(a+4) = *(const float4*)&As[buf][kk][ty*8+4];
            *(float4*)(b)   = *(const float4*)&Bs[buf][kk][tx*8];
            *(float4*)(b+4) = *(const float4*)&Bs[buf][kk][tx*8+4];
            #pragma unroll
            for (int i = 0; i < 8; i++)
                #pragma unroll
                for (int j = 0; j < 8; j++)
                    acc[i][j] += a[i] * b[j];
        }
        if (kt + 1 < nk) {
            int nb2 = buf ^ 1;
            As[nb2][akoff+0][arow]=ra0.x; As[nb2][akoff+1][arow]=ra0.y;
            As[nb2][akoff+2][arow]=ra0.z; As[nb2][akoff+3][arow]=ra0.w;
            As[nb2][akoff+4][arow]=ra1.x; As[nb2][akoff+5][arow]=ra1.y;
            As[nb2][akoff+6][arow]=ra1.z; As[nb2][akoff+7][arow]=ra1.w;
            *(float4*)&Bs[nb2][bk][bcol]   = rb0;
            *(float4*)&Bs[nb2][bk][bcol+4] = rb1;
        }
        __syncthreads();
    }

    const float* bb = bias + (size_t)mat * sub_n + coln;
    float bv[8];
    #pragma unroll
    for (int j = 0; j < 8; j++) bv[j] = bb[tx*8 + j];
    #pragma unroll
    for (int i = 0; i < 8; i++) {
        size_t r = (size_t)(row0 + ty*8 + i);
        float o[8];
        #pragma unroll
        for (int j = 0; j < 8; j++) {
            float v = acc[i][j] + bv[j];
            o[j] = relu ? fmaxf(v, 0.0f) : v;
        }
        *(float4*)&Cout[r * Ntot + col0 + tx*8]     = *(float4*)(o);
        *(float4*)&Cout[r * Ntot + col0 + tx*8 + 4] = *(float4*)(o+4);
    }
}

// ======== exact fp32 scores (stage0/l0 only) ========
__global__ __launch_bounds__(256) void scores_kernel(int use_mask)
{
    int bh = blockIdx.z;
    int b = bh >> 3, h = bh & 7;
    int t0 = blockIdx.y * 128, s0 = blockIdx.x * 128;
    __shared__ float Qs[2][16][128];
    __shared__ float Ks[2][16][128];
    int tid = threadIdx.x;
    int tx = tid & 15, ty = tid >> 4;

    const int arow = tid >> 1, akoff = (tid & 1) * 8;
    const float* qb = g_qkv + (size_t)(b*TT + t0) * QKVN + h*64;
    const float* kb = g_qkv + (size_t)(b*TT + s0) * QKVN + CC + h*64;

    float acc[8][8] = {};
    float4 ra0, ra1, rb0, rb1;

    ra0 = *(const float4*)&qb[(size_t)arow * QKVN + akoff];
    ra1 = *(const float4*)&qb[(size_t)arow * QKVN + akoff + 4];
    rb0 = *(const float4*)&kb[(size_t)arow * QKVN + akoff];
    rb1 = *(const float4*)&kb[(size_t)arow * QKVN + akoff + 4];
    Qs[0][akoff+0][arow]=ra0.x; Qs[0][akoff+1][arow]=ra0.y;
    Qs[0][akoff+2][arow]=ra0.z; Qs[0][akoff+3][arow]=ra0.w;
    Qs[0][akoff+4][arow]=ra1.x; Qs[0][akoff+5][arow]=ra1.y;
    Qs[0][akoff+6][arow]=ra1.z; Qs[0][akoff+7][arow]=ra1.w;
    Ks[0][akoff+0][arow]=rb0.x; Ks[0][akoff+1][arow]=rb0.y;
    Ks[0][akoff+2][arow]=rb0.z; Ks[0][akoff+3][arow]=rb0.w;
    Ks[0][akoff+4][arow]=rb1.x; Ks[0][akoff+5][arow]=rb1.y;
    Ks[0][akoff+6][arow]=rb1.z; Ks[0][akoff+7][arow]=rb1.w;
    __syncthreads();

    #pragma unroll
    for (int kt = 0; kt < 4; kt++) {
        int buf = kt & 1;
        if (kt + 1 < 4) {
            int k0 = (kt + 1) << 4;
            ra0 = *(const float4*)&qb[(size_t)arow * QKVN + k0 + akoff];
            ra1 = *(const float4*)&qb[(size_t)arow * QKVN + k0 + akoff + 4];
            rb0 = *(const float4*)&kb[(size_t)arow * QKVN + k0 + akoff];
            rb1 = *(const float4*)&kb[(size_t)arow * QKVN + k0 + akoff + 4];
        }
        #pragma unroll
        for (int kk = 0; kk < 16; kk++) {
            float a[8], c[8];
            *(float4*)(a)   = *(const float4*)&Qs[buf][kk][ty*8];
            *(float4*)(a+4) = *(const float4*)&Qs[buf][kk][ty*8+4];
            *(float4*)(c)   = *(const float4*)&Ks[buf][kk][tx*8];
            *(float4*)(c+4) = *(const float4*)&Ks[buf][kk][tx*8+4];
            #pragma unroll
            for (int i = 0; i < 8; i++)
                #pragma unroll
                for (int j = 0; j < 8; j++)
                    acc[i][j] += a[i] * c[j];
        }
        if (kt + 1 < 4) {
            int nb2 = buf ^ 1;
            Qs[nb2][akoff+0][arow]=ra0.x; Qs[nb2][akoff+1][arow]=ra0.y;
            Qs[nb2][akoff+2][arow]=ra0.z; Qs[nb2][akoff+3][arow]=ra0.w;
            Qs[nb2][akoff+4][arow]=ra1.x; Qs[nb2][akoff+5][arow]=ra1.y;
            Qs[nb2][akoff+6][arow]=ra1.z; Qs[nb2][akoff+7][arow]=ra1.w;
            Ks[nb2][akoff+0][arow]=rb0.x; Ks[nb2][akoff+1][arow]=rb0.y;
            Ks[nb2][akoff+2][arow]=rb0.z; Ks[nb2][akoff+3][arow]=rb0.w;
            Ks[nb2][akoff+4][arow]=rb1.x; Ks[nb2][akoff+5][arow]=rb1.y;
            Ks[nb2][akoff+6][arow]=rb1.z; Ks[nb2][akoff+7][arow]=rb1.w;
        }
        __syncthreads();
    }

    float* dst = g_s + (size_t)bh * TT * TT;
    int segt[8], segs[8];
    if (use_mask) {
        #pragma unroll
        for (int i = 0; i < 8; i++) segt[i] = g_seg[b*TT + t0 + ty*8 + i];
        #pragma unroll
        for (int j = 0; j < 8; j++) segs[j] = g_seg[b*TT + s0 + tx*8 + j];
    }
    #pragma unroll
    for (int i = 0; i < 8; i++) {
        size_t t = (size_t)(t0 + ty*8 + i);
        float o[8];
        #pragma unroll
        for (int j = 0; j < 8; j++) {
            float v = acc[i][j] * 0.125f;
            if (use_mask && segt[i] != segs[j]) v += NEGI;
            o[j] = v;
        }
        *(float4*)&dst[t * TT + s0 + tx*8]     = *(float4*)(o);
        *(float4*)&dst[t * TT + s0 + tx*8 + 4] = *(float4*)(o+4);
    }
}

// ======== BF16 scores: bf16 in (g_qkvb), bf16 out (g_sb) ========
__global__ __launch_bounds__(256) void scores_bf16_kernel(int use_mask)
{
    int bh = blockIdx.z;
    int b = bh >> 3, h = bh & 7;
    int t0 = blockIdx.y * 128, s0 = blockIdx.x * 128;
    __shared__ uint32_t Qs[2][128][9];
    __shared__ uint32_t Ks[2][128][9];
    int tid = threadIdx.x;
    int lane = tid & 31;
    int warp = tid >> 5;
    int warp_m = warp & 3;
    int warp_n = warp >> 2;
    int grp = lane >> 2;
    int tig = lane & 3;

    const int arow = tid >> 1, akoff = (tid & 1) * 8, akp = (tid & 1) * 4;
    const __nv_bfloat16* qb = g_qkvb + (size_t)(b*TT + t0) * QKVN + h*64;
    const __nv_bfloat16* kb = g_qkvb + (size_t)(b*TT + s0) * QKVN + CC + h*64;

    float acc[2][8][4];
    #pragma unroll
    for (int i = 0; i < 2; i++)
        #pragma unroll
        for (int j = 0; j < 8; j++)
            #pragma unroll
            for (int c = 0; c < 4; c++) acc[i][j][c] = 0.0f;

    uint4 uq, uk;
    uq = *(const uint4*)&qb[(size_t)arow * QKVN + akoff];
    uk = *(const uint4*)&kb[(size_t)arow * QKVN + akoff];
    Qs[0][arow][akp+0] = uq.x; Qs[0][arow][akp+1] = uq.y;
    Qs[0][arow][akp+2] = uq.z; Qs[0][arow][akp+3] = uq.w;
    Ks[0][arow][akp+0] = uk.x; Ks[0][arow][akp+1] = uk.y;
    Ks[0][arow][akp+2] = uk.z; Ks[0][arow][akp+3] = uk.w;

    #pragma unroll
    for (int kt = 0; kt < 4; kt++) {
        __syncthreads();
        int cur = kt & 1;
        if (kt + 1 < 4) {
            int k0 = (kt + 1) << 4;
            uq = *(const uint4*)&qb[(size_t)arow * QKVN + k0 + akoff];
            uk = *(const uint4*)&kb[(size_t)arow * QKVN + k0 + akoff];
        }
        {
            uint32_t af[2][4];
            #pragma unroll
            for (int mf = 0; mf < 2; mf++) {
                int m = warp_m * 32 + mf * 16 + grp;
                af[mf][0] = Qs[cur][m][tig];
                af[mf][1] = Qs[cur][m + 8][tig];
                af[mf][2] = Qs[cur][m][tig + 4];
                af[mf][3] = Qs[cur][m + 8][tig + 4];
            }
            #pragma unroll
            for (int nf = 0; nf < 8; nf++) {
                int n = warp_n * 64 + nf * 8 + grp;
                uint32_t b0 = Ks[cur][n][tig];
                uint32_t b1 = Ks[cur][n][tig + 4];
                #pragma unroll
                for (int mf = 0; mf < 2; mf++)
                    MMA_BF16(acc[mf][nf], af[mf][0], af[mf][1], af[mf][2], af[mf][3], b0, b1);
            }
        }
        if (kt + 1 < 4) {
            int nb2 = cur ^ 1;
            Qs[nb2][arow][akp+0] = uq.x; Qs[nb2][arow][akp+1] = uq.y;
            Qs[nb2][arow][akp+2] = uq.z; Qs[nb2][arow][akp+3] = uq.w;
            Ks[nb2][arow][akp+0] = uk.x; Ks[nb2][arow][akp+1] = uk.y;
            Ks[nb2][arow][akp+2] = uk.z; Ks[nb2][arow][akp+3] = uk.w;
        }
    }

    __nv_bfloat16* dst = g_sb + (size_t)bh * TT * TT;
    #pragma unroll
    for (int mf = 0; mf < 2; mf++) {
        int r_lo = warp_m * 32 + mf * 16 + grp;
        int r_hi = r_lo + 8;
        int sg_lo = 0, sg_hi = 0;
        if (use_mask) {
            sg_lo = g_seg[b*TT + t0 + r_lo];
            sg_hi = g_seg[b*TT + t0 + r_hi];
        }
        #pragma unroll
        for (int nf = 0; nf < 8; nf++) {
            int cl = warp_n * 64 + nf * 8 + tig * 2;
            float v0 = acc[mf][nf][0] * 0.125f, v1 = acc[mf][nf][1] * 0.125f;
            float v2 = acc[mf][nf][2] * 0.125f, v3 = acc[mf][nf][3] * 0.125f;
            if (use_mask) {
                int s_a = g_seg[b*TT + s0 + cl];
                int s_b = g_seg[b*TT + s0 + cl + 1];
                if (sg_lo != s_a) v0 += NEGI;
                if (sg_lo != s_b) v1 += NEGI;
                if (sg_hi != s_a) v2 += NEGI;
                if (sg_hi != s_b) v3 += NEGI;
            }
            *(uint32_t*)&dst[(size_t)(t0 + r_lo) * TT + s0 + cl] = packbf2(v0, v1);
            *(uint32_t*)&dst[(size_t)(t0 + r_hi) * TT + s0 + cl] = packbf2(v2, v3);
        }
    }
}

// ======== TF32 PV (stage0/l0 only): fp32 S @ fp32 V -> bf16 g_ab ========
__global__ __launch_bounds__(256) void pv_tf32_kernel()
{
    int bh = blockIdx.y;
    int b = bh >> 3, h = bh & 7;
    int t0 = blockIdx.x * 128;
    __shared__ float Ps[16][136];
    __shared__ float Vs[16][72];
    int tid = threadIdx.x;
    int lane = tid & 31;
    int warp = tid >> 5;
    int warp_m = warp & 3;
    int warp_n = warp >> 2;
    int grp = lane >> 2;
    int tig = lane & 3;

    const int arow = tid >> 1, akoff = (tid & 1) * 8;
    const int vk = tid >> 4, vcol = (tid & 15) * 4;

    const float* srow = g_s + (size_t)bh * TT * TT + (size_t)t0 * TT;
    const float* vb = g_qkv + (size_t)(b*TT) * QKVN + 2*CC + h*64;

    float acc[2][4][4];
    #pragma unroll
    for (int i = 0; i < 2; i++)
        #pragma unroll
        for (int j = 0; j < 4; j++)
            #pragma unroll
            for (int c = 0; c < 4; c++) acc[i][j][c] = 0.0f;

    float4 ra0, ra1, rv0;
    ra0 = *(const float4*)&srow[(size_t)arow * TT + akoff];
    ra1 = *(const float4*)&srow[(size_t)arow * TT + akoff + 4];
    rv0 = *(const float4*)&vb[(size_t)vk * QKVN + vcol];

    const int nk = TT / 16;
    for (int kt = 0; kt < nk; kt++) {
        Ps[akoff+0][arow] = f2tf32(ra0.x); Ps[akoff+1][arow] = f2tf32(ra0.y);
        Ps[akoff+2][arow] = f2tf32(ra0.z); Ps[akoff+3][arow] = f2tf32(ra0.w);
        Ps[akoff+4][arow] = f2tf32(ra1.x); Ps[akoff+5][arow] = f2tf32(ra1.y);
        Ps[akoff+6][arow] = f2tf32(ra1.z); Ps[akoff+7][arow] = f2tf32(ra1.w);
        Vs[vk][vcol+0] = f2tf32(rv0.x); Vs[vk][vcol+1] = f2tf32(rv0.y);
        Vs[vk][vcol+2] = f2tf32(rv0.z); Vs[vk][vcol+3] = f2tf32(rv0.w);
        __syncthreads();

        if (kt + 1 < nk) {
            int k0 = (kt + 1) << 4;
            ra0 = *(const float4*)&srow[(size_t)arow * TT + k0 + akoff];
            ra1 = *(const float4*)&srow[(size_t)arow * TT + k0 + akoff + 4];
            rv0 = *(const float4*)&vb[(size_t)(k0 + vk) * QKVN + vcol];
        }

        #pragma unroll
        for (int ks = 0; ks < 2; ks++) {
            int kb2 = ks * 8;
            uint32_t af[2][4];
            #pragma unroll
            for (int mf = 0; mf < 2; mf++) {
                int m = warp_m * 32 + mf * 16 + grp;
                af[mf][0] = __float_as_uint(Ps[kb2 + tig][m]);
                af[mf][1] = __float_as_uint(Ps[kb2 + tig][m + 8]);
                af[mf][2] = __float_as_uint(Ps[kb2 + tig + 4][m]);
                af[mf][3] = __float_as_uint(Ps[kb2 + tig + 4][m + 8]);
            }
            #pragma unroll
            for (int nf = 0; nf < 4; nf++) {
                int n = warp_n * 32 + nf * 8 + grp;
                uint32_t b0 = __float_as_uint(Vs[kb2 + tig][n]);
                uint32_t b1 = __float_as_uint(Vs[kb2 + tig + 4][n]);
                #pragma unroll
                for (int mf = 0; mf < 2; mf++)
                    MMA_TF32(acc[mf][nf], af[mf][0], af[mf][1], af[mf][2], af[mf][3], b0, b1);
            }
        }
        __syncthreads();
    }

    #pragma unroll
    for (int mf = 0; mf < 2; mf++) {
        int r_lo = warp_m * 32 + mf * 16 + grp;
        int r_hi = r_lo + 8;
        #pragma unroll
        for (int nf = 0; nf < 4; nf++) {
            int cl = warp_n * 32 + nf * 8 + tig * 2;
            *(uint32_t*)&g_ab[(size_t)(b*TT + t0 + r_lo) * CC + h*64 + cl] =
                packbf2(acc[mf][nf][0], acc[mf][nf][1]);
            *(uint32_t*)&g_ab[(size_t)(b*TT + t0 + r_hi) * CC + h*64 + cl] =
                packbf2(acc[mf][nf][2], acc[mf][nf][3]);
        }
    }
}

// ======== FUSED softmax + PV, bf16 S + bf16 V -> bf16 g_ab (fast exp) ========
__global__ __launch_bounds__(256) void fused_softmax_pv_kernel(int docolsum)
{
    int bh = blockIdx.y;
    int b = bh >> 3, h = bh & 7;
    int t0 = blockIdx.x * 128;
    const __nv_bfloat16* srow = g_sb + (size_t)bh * TT * TT + (size_t)t0 * TT;
    const __nv_bfloat16* vb = g_qkvb + (size_t)(b*TT) * QKVN + 2*CC + h*64;

    __shared__ float rowm[128];
    __shared__ float rowstat[128];
    __shared__ float Ps[16][136];
    __shared__ float Vs[16][72];
    __shared__ float colpart[16][8];

    int tid = threadIdx.x;
    int lane = tid & 31;
    int warp = tid >> 5;
    int warp_m = warp & 3;
    int warp_n = warp >> 2;
    int grp = lane >> 2;
    int tig = lane & 3;

    for (int r = warp * 16; r < warp * 16 + 16; r++) {
        const __nv_bfloat16* p = srow + (size_t)r * TT;
        float m = -3.4e38f, l = 0.0f;
        #pragma unroll
        for (int i = 0; i < 4; i++) {
            uint4 u = *(const uint4*)&p[lane * 8 + i * 256];
            float2 a0 = bf2f(u.x), a1 = bf2f(u.y), a2 = bf2f(u.z), a3 = bf2f(u.w);
            float mx = fmaxf(fmaxf(fmaxf(a0.x, a0.y), fmaxf(a1.x, a1.y)),
                             fmaxf(fmaxf(a2.x, a2.y), fmaxf(a3.x, a3.y)));
            if (docolsum) {
                float mn = fmaxf(m, mx);
                l = l * __expf(m - mn)
                  + __expf(a0.x - mn) + __expf(a0.y - mn) + __expf(a1.x - mn) + __expf(a1.y - mn)
                  + __expf(a2.x - mn) + __expf(a2.y - mn) + __expf(a3.x - mn) + __expf(a3.y - mn);
                m = mn;
            } else {
                m = fmaxf(m, mx);
            }
        }
        #pragma unroll
        for (int o = 16; o > 0; o >>= 1) {
            float m2 = __shfl_xor_sync(0xffffffffu, m, o);
            if (docolsum) {
                float l2 = __shfl_xor_sync(0xffffffffu, l, o);
                float mn = fmaxf(m, m2);
                l = l * __expf(m - mn) + l2 * __expf(m2 - mn);
                m = mn;
            } else {
                m = fmaxf(m, m2);
            }
        }
        if (lane == 0) { rowm[r] = m; rowstat[r] = l; }
    }
    __syncthreads();

    const int arow = tid >> 1, akoff = (tid & 1) * 8;
    const int vk = tid >> 4, vcol = (tid & 15) * 4;
    float minv = rowm[arow];
    float rl = docolsum ? (1.0f / rowstat[arow]) : 1.0f;
    float lpart = 0.0f;

    float acc[2][4][4];
    #pragma unroll
    for (int i = 0; i < 2; i++)
        #pragma unroll
        for (int j = 0; j < 4; j++)
            #pragma unroll
            for (int c = 0; c < 4; c++) acc[i][j][c] = 0.0f;

    float* wpdst = 0;
    if (docolsum)
        wpdst = g_wp + ((size_t)bh * 8 + blockIdx.x) * TT;

    const int nk = TT / 16;
    for (int kt = 0; kt < nk; kt++) {
        uint4 u = *(const uint4*)&srow[(size_t)arow * TT + kt*16 + akoff];
        float2 a0 = bf2f(u.x), a1 = bf2f(u.y), a2 = bf2f(u.z), a3 = bf2f(u.w);
        float pv_[8];
        pv_[0] = __expf(a0.x - minv) * rl; pv_[1] = __expf(a0.y - minv) * rl;
        pv_[2] = __expf(a1.x - minv) * rl; pv_[3] = __expf(a1.y - minv) * rl;
        pv_[4] = __expf(a2.x - minv) * rl; pv_[5] = __expf(a2.y - minv) * rl;
        pv_[6] = __expf(a3.x - minv) * rl; pv_[7] = __expf(a3.y - minv) * rl;
        if (!docolsum) {
            #pragma unroll
            for (int j = 0; j < 8; j++) lpart += pv_[j];
        }
        #pragma unroll
        for (int j = 0; j < 8; j++) Ps[akoff + j][arow] = f2tf32(pv_[j]);

        uint2 uv = *(const uint2*)&vb[(size_t)(kt*16 + vk) * QKVN + vcol];
        float2 v0 = bf2f(uv.x), v1 = bf2f(uv.y);
        Vs[vk][vcol+0] = f2tf32(v0.x); Vs[vk][vcol+1] = f2tf32(v0.y);
        Vs[vk][vcol+2] = f2tf32(v1.x); Vs[vk][vcol+3] = f2tf32(v1.y);
        __syncthreads();

        if (docolsum) {
            if (tid < 128) {
                int c = tid >> 3, rseg = tid & 7;
                float cs = 0.0f;
                #pragma unroll
                for (int j = 0; j < 16; j++) cs += Ps[c][rseg * 16 + j];
                colpart[c][rseg] = cs;
            }
            __syncthreads();
            if (tid < 16) {
                float cs = 0.0f;
                #pragma unroll
                for (int j = 0; j < 8; j++) cs += colpart[tid][j];
                wpdst[kt * 16 + tid] = cs;
            }
        }

        #pragma unroll
        for (int ks = 0; ks < 2; ks++) {
            int kb2 = ks * 8;
            uint32_t af[2][4];
            #pragma unroll
            for (int mf = 0; mf < 2; mf++) {
                int m = warp_m * 32 + mf * 16 + grp;
                af[mf][0] = __float_as_uint(Ps[kb2 + tig][m]);
                af[mf][1] = __float_as_uint(Ps[kb2 + tig][m + 8]);
                af[mf][2] = __float_as_uint(Ps[kb2 + tig + 4][m]);
                af[mf][3] = __float_as_uint(Ps[kb2 + tig + 4][m + 8]);
            }
            #pragma unroll
            for (int nf = 0; nf < 4; nf++) {
                int n = warp_n * 32 + nf * 8 + grp;
                uint32_t b0 = __float_as_uint(Vs[kb2 + tig][n]);
                uint32_t b1 = __float_as_uint(Vs[kb2 + tig + 4][n]);
                #pragma unroll
                for (int mf = 0; mf < 2; mf++)
                    MMA_TF32(acc[mf][nf], af[mf][0], af[mf][1], af[mf][2], af[mf][3], b0, b1);
            }
        }
        __syncthreads();
    }

    if (!docolsum) {
        lpart += __shfl_xor_sync(0xffffffffu, lpart, 1);
        if ((tid & 1) == 0) rowstat[arow] = lpart;
        __syncthreads();
    }

    #pragma unroll
    for (int mf = 0; mf < 2; mf++) {
        int r_lo = warp_m * 32 + mf * 16 + grp;
        int r_hi = r_lo + 8;
        float inv_lo = docolsum ? 1.0f : (1.0f / rowstat[r_lo]);
        float inv_hi = docolsum ? 1.0f : (1.0f / rowstat[r_hi]);
        #pragma unroll
        for (int nf = 0; nf < 4; nf++) {
            int cl = warp_n * 32 + nf * 8 + tig * 2;
            *(uint32_t*)&g_ab[(size_t)(b*TT + t0 + r_lo) * CC + h*64 + cl] =
                packbf2(acc[mf][nf][0] * inv_lo, acc[mf][nf][1] * inv_lo);
            *(uint32_t*)&g_ab[(size_t)(b*TT + t0 + r_hi) * CC + h*64 + cl] =
                packbf2(acc[mf][nf][2] * inv_hi, acc[mf][nf][3] * inv_hi);
        }
    }
}

// ---------------- reduce colsum partials ----------------
__global__ void wreduce_kernel()
{
    int idx = blockIdx.x * 256 + threadIdx.x;
    int b = idx / TT, s = idx % TT;
    float acc = 0.0f;
    #pragma unroll 8
    for (int j = 0; j < HH * 8; j++)
        acc += g_wp[((size_t)(b * HH * 8 + j)) * TT + s];
    g_w[idx] = acc * (1.0f / HH);
}

// ---------------- row softmax (stage0/l0): shuffle reductions, expf kept ------
__global__ void softmax_rows_kernel(float* __restrict__ S)
{
    float* p = S + (size_t)blockIdx.x * TT;
    int tid = threadIdx.x;
    int lane = tid & 31, wid = tid >> 5;
    __shared__ float wredm[8];
    __shared__ float wreds[8];
    float v[4];
    float m = -3.4e38f;
    #pragma unroll
    for (int i = 0; i < 4; i++) { v[i] = p[tid + i * 256]; m = fmaxf(m, v[i]); }
    #pragma unroll
    for (int o = 16; o > 0; o >>= 1)
        m = fmaxf(m, __shfl_xor_sync(0xffffffffu, m, o));
    if (lane == 0) wredm[wid] = m;
    __syncthreads();
    float mx = wredm[0];
    #pragma unroll
    for (int j = 1; j < 8; j++) mx = fmaxf(mx, wredm[j]);
    float sum = 0.0f;
    #pragma unroll
    for (int i = 0; i < 4; i++) { v[i] = expf(v[i] - mx); sum += v[i]; }
    #pragma unroll
    for (int o = 16; o > 0; o >>= 1)
        sum += __shfl_xor_sync(0xffffffffu, sum, o);
    if (lane == 0) wreds[wid] = sum;
    __syncthreads();
    float tot = wreds[0];
    #pragma unroll
    for (int j = 1; j < 8; j++) tot += wreds[j];
    float inv = 1.0f / tot;
    #pragma unroll
    for (int i = 0; i < 4; i++) p[tid + i * 256] = v[i] * inv;
}

// ---------------- head-averaged probs (stage0/l0 only) ----------------
__global__ void head_avg_kernel()
{
    size_t idx = (size_t)blockIdx.x * 256 + threadIdx.x;
    size_t b = idx / ((size_t)TT * TT / 4);
    size_t r = idx % ((size_t)TT * TT / 4);
    float4 sum = make_float4(0.f, 0.f, 0.f, 0.f);
    #pragma unroll
    for (int h = 0; h < HH; h++) {
        float4 x = *((const float4*)(g_s + (b * HH + h) * (size_t)TT * TT) + r);
        sum.x += x.x; sum.y += x.y; sum.z += x.z; sum.w += x.w;
    }
    sum.x *= (1.0f/HH); sum.y *= (1.0f/HH); sum.z *= (1.0f/HH); sum.w *= (1.0f/HH);
    *((float4*)(g_p0 + b * (size_t)TT * TT) + r) = sum;
}

// ---------------- out = LN(res + add), shuffle reductions ----------------
__global__ void ln_residual_kernel(const float* __restrict__ res, const float* __restrict__ add,
                                   float* __restrict__ out, __nv_bfloat16* __restrict__ outb,
                                   const float* __restrict__ gamma, const float* __restrict__ beta)
{
    int row = blockIdx.x, tid = threadIdx.x;
    int lane = tid & 31, wid = tid >> 5;
    __shared__ float wred1[8];
    __shared__ float wred2[8];
    const float* r = res + (size_t)row * CC;
    const float* a = add + (size_t)row * CC;
    float v0 = r[tid] + a[tid];
    float v1 = r[tid + 256] + a[tid + 256];
    float s = v0 + v1;
    #pragma unroll
    for (int o = 16; o > 0; o >>= 1) s += __shfl_xor_sync(0xffffffffu, s, o);
    if (lane == 0) wred1[wid] = s;
    __syncthreads();
    float tot = wred1[0];
    #pragma unroll
    for (int j = 1; j < 8; j++) tot += wred1[j];
    float mu = tot * (1.0f / CC);
    float d0 = v0 - mu, d1 = v1 - mu;
    float q = d0 * d0 + d1 * d1;
    #pragma unroll
    for (int o = 16; o > 0; o >>= 1) q += __shfl_xor_sync(0xffffffffu, q, o);
    if (lane == 0) wred2[wid] = q;
    __syncthreads();
    float qt = wred2[0];
    #pragma unroll
    for (int j = 1; j < 8; j++) qt += wred2[j];
    float rstd = rsqrtf(qt * (1.0f / CC) + 1e-5f);
    float o0 = d0 * rstd * gamma[tid] + beta[tid];
    float o1 = d1 * rstd * gamma[tid + 256] + beta[tid + 256];
    float* o = out + (size_t)row * CC;
    o[tid] = o0; o[tid + 256] = o1;
    __nv_bfloat16* ob = outb + (size_t)row * CC;
    ob[tid] = __float2bfloat16(o0);
    ob[tid + 256] = __float2bfloat16(o1);
}

// ---------------- w[b,s] = sum_t p0[b,t,s] (stage0 only, order-preserving) ----
__global__ void colsum_kernel()
{
    int idx = blockIdx.x * 256 + threadIdx.x;
    int b = idx / TT, s = idx % TT;
    const float* base = g_p0 + (size_t)b * TT * TT + s;
    float acc = 0.0f;
    for (int t = 0; t < TT; t += 8) {
        float v[8];
        #pragma unroll
        for (int j = 0; j < 8; j++) v[j] = base[(size_t)(t + j) * TT];
        #pragma unroll
        for (int j = 0; j < 8; j++) acc += v[j];
    }
    g_w[idx] = acc;
}

// ---------------- segment scan ----------------
__global__ void segment_kernel()
{
    int b = blockIdx.x, tid = threadIdx.x;
    __shared__ float smin[256], smax[256];
    float lo = 3.4e38f, hi = -3.4e38f;
    for (int t = tid; t < TT; t += 256) {
        float v = g_w[b * TT + t];
        lo = fminf(lo, v); hi = fmaxf(hi, v);
    }
    smin[tid] = lo; smax[tid] = hi; __syncthreads();
    for (int s = 128; s > 0; s >>= 1) {
        if (tid < s) { smin[tid] = fminf(smin[tid], smin[tid + s]); smax[tid] = fmaxf(smax[tid], smax[tid + s]); }
        __syncthreads();
    }
    if (tid == 0) {
        float wmin = smin[0], wmax = smax[0];
        float denom = fmaxf(wmax - wmin, 1e-12f);
        bool prev = ((g_w[b * TT + 0] - wmin) / denom) >= 0.5f;
        int start = 0, segc = 0;
        g_seg[b * TT + 0] = 0;
        g_segstart[b * (TT + 1) + 0] = 0;
        for (int t = 1; t < TT; t++) {
            bool cur = ((g_w[b * TT + t] - wmin) / denom) >= 0.5f;
            if (cur != prev && (start + 1) != t) {
                start = t; segc++;
                g_segstart[b * (TT + 1) + segc] = t;
            }
            g_seg[b * TT + t] = segc;
            prev = cur;
        }
        g_nseg[b] = segc + 1;
        g_segstart[b * (TT + 1) + segc + 1] = TT;
    }
}

// ---------------- aw = softmax_s(w) ----------------
__global__ void batch_softmax_kernel()
{
    int b = blockIdx.x, tid = threadIdx.x;
    __shared__ float red[256];
    float v[4];
    float m = -3.4e38f;
    #pragma unroll
    for (int i = 0; i < 4; i++) { v[i] = g_w[b * TT + tid + i * 256]; m = fmaxf(m, v[i]); }
    red[tid] = m; __syncthreads();
    for (int s = 128; s > 0; s >>= 1) { if (tid < s) red[tid] = fmaxf(red[tid], red[tid + s]); __syncthreads(); }
    float mx = red[0];
    __syncthreads();
    float sum = 0.0f;
    #pragma unroll
    for (int i = 0; i < 4; i++) { v[i] = expf(v[i] - mx); sum += v[i]; }
    red[tid] = sum; __syncthreads();
    for (int s = 128; s > 0; s >>= 1) { if (tid < s) red[tid] += red[tid + s]; __syncthreads(); }
    float inv = 1.0f / red[0];
    #pragma unroll
    for (int i = 0; i < 4; i++) g_aw[b * TT + tid + i * 256] = v[i] * inv;
}

// ---------------- word tokens ----------------
__global__ void word_tokens_kernel(float* __restrict__ out)
{
    int b = blockIdx.y, i = blockIdx.x, tid = threadIdx.x;
    float* dst = out + ((size_t)b * 2 * TT + i) * CC;
    int ns = g_nseg[b];
    if (i >= ns) {
        for (int c = tid; c < CC; c += 256) dst[c] = 0.0f;
        return;
    }
    int t0 = g_segstart[b * (TT + 1) + i];
    int t1 = g_segstart[b * (TT + 1) + i + 1];
    for (int c = tid; c < CC; c += 256) {
        float acc = 0.0f;
        for (int t = t0; t < t1; t++)
            acc += g_x[((size_t)b * TT + t) * CC + c] * g_aw[b * TT + t];
        dst[c] = acc;
    }
}

__global__ void copyx_kernel(const float* __restrict__ xin, float* __restrict__ out)
{
    size_t idx = (size_t)blockIdx.x * 256 + threadIdx.x;
    size_t b = idx / ((size_t)TT * CC);
    size_t rem = idx % ((size_t)TT * CC);
    out[b * (size_t)2 * TT * CC + (size_t)TT * CC + rem] = xin[idx];
}

__global__ void wm_kernel(float* __restrict__ wmout)
{
    size_t idx = (size_t)blockIdx.x * 256 + threadIdx.x;
    size_t b = idx / ((size_t)TT * TT);
    int i = (int)((idx / TT) % TT);
    int t = (int)(idx % TT);
    wmout[idx] = (g_seg[b * TT + t] == i) ? 1.0f : 0.0f;
}

// ---------------- host orchestration ----------------
extern "C" void kernel_launch(void* const* d_in, const int* in_sizes, int n_in,
                              void* d_out, int out_size)
{
    const float* x_in = (const float*)d_in[0];
    const float* Wqkv = (const float*)d_in[1];
    const float* bqkv = (const float*)d_in[2];
    const float* Wo   = (const float*)d_in[3];
    const float* bo   = (const float*)d_in[4];
    const float* W1   = (const float*)d_in[5];
    const float* b1   = (const float*)d_in[6];
    const float* W2   = (const float*)d_in[7];
    const float* b2   = (const float*)d_in[8];
    const float* lng  = (const float*)d_in[9];
    const float* lnb  = (const float*)d_in[10];
    float* out = (float*)d_out;

    float *p_x, *p_qkv, *p_s, *p_t;
    __nv_bfloat16 *p_xb, *p_ab, *p_hb, *p_qkvb, *p_wqkv_b, *p_wo_b, *p_w1_b, *p_w2_b;
    cudaGetSymbolAddress((void**)&p_x, g_x);
    cudaGetSymbolAddress((void**)&p_qkv, g_qkv);
    cudaGetSymbolAddress((void**)&p_s, g_s);
    cudaGetSymbolAddress((void**)&p_t, g_t);
    cudaGetSymbolAddress((void**)&p_xb, g_xb);
    cudaGetSymbolAddress((void**)&p_ab, g_ab);
    cudaGetSymbolAddress((void**)&p_hb, g_hb);
    cudaGetSymbolAddress((void**)&p_qkvb, g_qkvb);
    cudaGetSymbolAddress((void**)&p_wqkv_b, g_wqkv_b);
    cudaGetSymbolAddress((void**)&p_wo_b, g_wo_b);
    cudaGetSymbolAddress((void**)&p_w1_b, g_w1_b);
    cudaGetSymbolAddress((void**)&p_w2_b, g_w2_b);

    cudaMemcpyAsync(p_x, x_in, sizeof(float) * (size_t)BT * CC, cudaMemcpyDeviceToDevice);
    cvt_kernel<<<(int)(((size_t)BT * CC) / 256), 256>>>(x_in, p_xb);

    dim3 tb(32, 8);
    transpose_cvt_all_kernel<<<dim3(1024, 1, 24), tb>>>(Wqkv, Wo, W1, W2,
                                                        p_wqkv_b, p_wo_b, p_w1_b, p_w2_b);

    dim3 grid_qkv(QKVN / 128, BT / 128);
    dim3 grid_cc(CC / 128, BT / 128);
    dim3 grid_ff(FF / 128, BT / 128);
    dim3 grid_qk(2 * CC / 128, BT / 128);
    dim3 grid_sc(TT / 128, TT / 128, BB * HH);
    dim3 grid_pv(TT / 128, BB * HH);

    for (int stage = 0; stage < 2; stage++) {
        int use_mask = (stage == 1);
        for (int l = 0; l < 2; l++) {
            int sl = stage * 2 + l;
            const __nv_bfloat16* Wqb = p_wqkv_b + (size_t)sl * 3 * CC * CC;
            const float* bb = bqkv + (size_t)sl * 3 * CC;

            if (stage == 0 && l == 0) {
                // seg-critical exact island (fp32 throughout for probs0 path)
                gemm_kernel<<<grid_qk, 256>>>(p_x, Wqkv + (size_t)sl * 3 * CC * CC, bb,
                                              p_qkv, BT, QKVN, CC, 0, CC);
                gemm_bb_kernel<<<grid_cc, 256>>>(p_xb, Wqb + (size_t)2 * CC * CC,
                                                 bb + 2 * CC, p_qkv + 2 * CC, 0,
                                                 QKVN, CC, 0, 0);
                scores_kernel<<<grid_sc, 256>>>(use_mask);
                softmax_rows_kernel<<<BB * HH * TT, 256>>>(p_s);
                head_avg_kernel<<<(int)(((size_t)BB * TT * TT / 4) / 256), 256>>>();
                pv_tf32_kernel<<<grid_pv, 256>>>();
            } else {
                gemm_bb_kernel<<<grid_qkv, 256>>>(p_xb, Wqb, bb, 0, p_qkvb,
                                                  QKVN, CC, 0, 1);
                scores_bf16_kernel<<<grid_sc, 256>>>(use_mask);
                int docolsum = (stage == 1 && l == 0) ? 1 : 0;
                fused_softmax_pv_kernel<<<grid_pv, 256>>>(docolsum);
                if (docolsum)
                    wreduce_kernel<<<BT / 256, 256>>>();
            }

            gemm_bb_kernel<<<grid_cc, 256>>>(p_ab, p_wo_b + (size_t)sl * CC * CC,
                                             bo + (size_t)sl * CC, p_t, 0, CC, CC, 0, 0);
            ln_residual_kernel<<<BT, 256>>>(p_x, p_t, p_x, p_xb,
                                            lng + (size_t)(sl * 2 + 0) * CC,
                                            lnb + (size_t)(sl * 2 + 0) * CC);

            gemm_bb_kernel<<<grid_ff, 256>>>(p_xb, p_w1_b + (size_t)sl * FF * CC,
                                             b1 + (size_t)sl * FF, 0, p_hb, FF, CC, 1, 1);
            gemm_bb_kernel<<<grid_cc, 256>>>(p_hb, p_w2_b + (size_t)sl * CC * FF,
                                             b2 + (size_t)sl * CC, p_t, 0, CC, FF, 0, 0);
            ln_residual_kernel<<<BT, 256>>>(p_x, p_t, p_x, p_xb,
                                            lng + (size_t)(sl * 2 + 1) * CC,
                                            lnb + (size_t)(sl * 2 + 1) * CC);
        }
        if (stage == 0) {
            colsum_kernel<<<BT / 256, 256>>>();
            segment_kernel<<<BB, 256>>>();
        } else {
            batch_softmax_kernel<<<BB, 256>>>();
        }
    }

    word_tokens_kernel<<<dim3(TT, BB), 256>>>(out);
    copyx_kernel<<<(int)(((size_t)BT * CC) / 256), 256>>>(x_in, out);
    wm_kernel<<<(int)(((size_t)BB * TT * TT) / 256), 256>>>(out + (size_t)BB * 2 * TT * CC);
}

// round 16
// speedup vs baseline: 1.0855x; 1.0071x over previous
#include <cuda_runtime.h>
#include <cuda_bf16.h>
#include <math.h>
#include <stdint.h>

// Problem constants
#define BB 4
#define TT 1024
#define CC 512
#define HH 8
#define DH 64
#define FF 2048
#define BT (BB*TT)
#define NEGI (-1e9f)
#define QKVN (3*CC)

// ---------------- scratch ----------------
__device__ float g_x[BT*CC];
__device__ float g_qkv[BT*QKVN];
__device__ float g_s[(size_t)BB*HH*TT*TT];
__device__ float g_p0[(size_t)BB*TT*TT];
__device__ float g_t[BT*CC];
__device__ float g_part[(size_t)2*BT*CC];            // K-split partials (16MB)
__device__ float g_w[BT];
__device__ float g_aw[BT];
__device__ float g_wp[BB*HH*8*TT];
__device__ int   g_seg[BT];
__device__ int   g_segstart[BB*(TT+1)];
__device__ int   g_nseg[BB];

// bf16 buffers
__device__ __nv_bfloat16 g_xb[BT*CC];
__device__ __nv_bfloat16 g_ab[BT*CC];
__device__ __nv_bfloat16 g_hb[BT*FF];
__device__ __nv_bfloat16 g_qkvb[BT*QKVN];
__device__ __nv_bfloat16 g_sb[(size_t)BB*HH*TT*TT];
__device__ __nv_bfloat16 g_wqkv_b[4*3*CC*CC];
__device__ __nv_bfloat16 g_wo_b[4*CC*CC];
__device__ __nv_bfloat16 g_w1_b[4*FF*CC];
__device__ __nv_bfloat16 g_w2_b[4*CC*FF];

__device__ __forceinline__ float f2tf32(float x) {
    uint32_t r;
    asm("cvt.rna.tf32.f32 %0, %1;" : "=r"(r) : "f"(x));
    return __uint_as_float(r);
}
__device__ __forceinline__ uint32_t packbf2(float lo, float hi) {
    uint32_t r;
    asm("cvt.rn.bf16x2.f32 %0, %1, %2;" : "=r"(r) : "f"(hi), "f"(lo));
    return r;
}
__device__ __forceinline__ float2 bf2f(uint32_t u) {
    __nv_bfloat162 h = *reinterpret_cast<__nv_bfloat162*>(&u);
    return __bfloat1622float2(h);
}

#define MMA_TF32(acc, a0,a1,a2,a3, b0,b1) \
    asm("mma.sync.aligned.m16n8k8.row.col.f32.tf32.tf32.f32 " \
        "{%0,%1,%2,%3}, {%4,%5,%6,%7}, {%8,%9}, {%0,%1,%2,%3};" \
        : "+f"(acc[0]), "+f"(acc[1]), "+f"(acc[2]), "+f"(acc[3]) \
        : "r"(a0), "r"(a1), "r"(a2), "r"(a3), "r"(b0), "r"(b1))

#define MMA_BF16(acc, a0,a1,a2,a3, b0,b1) \
    asm("mma.sync.aligned.m16n8k16.row.col.f32.bf16.bf16.f32 " \
        "{%0,%1,%2,%3}, {%4,%5,%6,%7}, {%8,%9}, {%0,%1,%2,%3};" \
        : "+f"(acc[0]), "+f"(acc[1]), "+f"(acc[2]), "+f"(acc[3]) \
        : "r"(a0), "r"(a1), "r"(a2), "r"(a3), "r"(b0), "r"(b1))

// ======== single-launch batched transpose+convert (24 weight matrices) ========
__global__ void transpose_cvt_all_kernel(const float* __restrict__ Wqkv,
                                         const float* __restrict__ Wo,
                                         const float* __restrict__ W1,
                                         const float* __restrict__ W2,
                                         __nv_bfloat16* __restrict__ dq,
                                         __nv_bfloat16* __restrict__ dwo,
                                         __nv_bfloat16* __restrict__ d1,
                                         __nv_bfloat16* __restrict__ d2)
{
    __shared__ float tile[32][33];
    int z = blockIdx.z;
    const float* src;
    __nv_bfloat16* dst;
    int K, N;
    if (z < 12)      { src = Wqkv + (size_t)z * CC * CC; dst = dq + (size_t)z * CC * CC; K = CC; N = CC; }
    else if (z < 16) { int m = z - 12; src = Wo + (size_t)m * CC * CC; dst = dwo + (size_t)m * CC * CC; K = CC; N = CC; }
    else if (z < 20) { int m = z - 16; src = W1 + (size_t)m * CC * FF; dst = d1 + (size_t)m * FF * CC; K = CC; N = FF; }
    else             { int m = z - 20; src = W2 + (size_t)m * FF * CC; dst = d2 + (size_t)m * CC * FF; K = FF; N = CC; }

    int ntn = N / 32, ntk = K / 32;
    int flat = blockIdx.x;
    if (flat >= ntn * ntk) return;
    int nb = (flat % ntn) * 32, kb = (flat / ntn) * 32;
    int tx = threadIdx.x, ty = threadIdx.y;
    #pragma unroll
    for (int j = ty; j < 32; j += 8)
        tile[j][tx] = src[(size_t)(kb + j) * N + nb + tx];
    __syncthreads();
    #pragma unroll
    for (int j = ty; j < 32; j += 8)
        dst[(size_t)(nb + j) * K + kb + tx] = __float2bfloat16(tile[tx][j]);
}

__global__ void cvt_kernel(const float* __restrict__ src, __nv_bfloat16* __restrict__ dst)
{
    size_t i = (size_t)blockIdx.x * 256 + threadIdx.x;
    dst[i] = __float2bfloat16(src[i]);
}

// ======== BF16xBF16 GEMM: 128x128x16, 2-stage (R12-proven) ========
__global__ __launch_bounds__(256) void gemm_bb_kernel(
    const __nv_bfloat16* __restrict__ A, const __nv_bfloat16* __restrict__ Wt,
    const float* __restrict__ bias, float* __restrict__ outf,
    __nv_bfloat16* __restrict__ outb, int nstride, int K, int relu, int obf)
{
    __shared__ uint32_t As[2][128][9];
    __shared__ uint32_t Bs[2][128][9];
    int tid = threadIdx.x;
    int lane = tid & 31;
    int warp = tid >> 5;
    int warp_m = warp & 3;
    int warp_n = warp >> 2;
    int grp = lane >> 2;
    int tig = lane & 3;

    int row0 = blockIdx.y * 128, col0 = blockIdx.x * 128;
    const __nv_bfloat16* Ab = A + (size_t)row0 * K;
    const __nv_bfloat16* Wb = Wt + (size_t)col0 * K;

    const int arow = tid >> 1, akoff = (tid & 1) * 8, akp = (tid & 1) * 4;

    float acc[2][8][4];
    #pragma unroll
    for (int i = 0; i < 2; i++)
        #pragma unroll
        for (int j = 0; j < 8; j++)
            #pragma unroll
            for (int c = 0; c < 4; c++) acc[i][j][c] = 0.0f;

    uint4 ua, ub;
    ua = *(const uint4*)&Ab[(size_t)arow * K + akoff];
    ub = *(const uint4*)&Wb[(size_t)arow * K + akoff];
    As[0][arow][akp+0] = ua.x; As[0][arow][akp+1] = ua.y;
    As[0][arow][akp+2] = ua.z; As[0][arow][akp+3] = ua.w;
    Bs[0][arow][akp+0] = ub.x; Bs[0][arow][akp+1] = ub.y;
    Bs[0][arow][akp+2] = ub.z; Bs[0][arow][akp+3] = ub.w;

    int nk = K >> 4;
    for (int kt = 0; kt < nk; kt++) {
        __syncthreads();
        int cur = kt & 1;
        if (kt + 1 < nk) {
            int k0 = (kt + 1) << 4;
            ua = *(const uint4*)&Ab[(size_t)arow * K + k0 + akoff];
            ub = *(const uint4*)&Wb[(size_t)arow * K + k0 + akoff];
        }
        {
            uint32_t af[2][4];
            #pragma unroll
            for (int mf = 0; mf < 2; mf++) {
                int m = warp_m * 32 + mf * 16 + grp;
                af[mf][0] = As[cur][m][tig];
                af[mf][1] = As[cur][m + 8][tig];
                af[mf][2] = As[cur][m][tig + 4];
                af[mf][3] = As[cur][m + 8][tig + 4];
            }
            #pragma unroll
            for (int nf = 0; nf < 8; nf++) {
                int n = warp_n * 64 + nf * 8 + grp;
                uint32_t b0 = Bs[cur][n][tig];
                uint32_t b1 = Bs[cur][n][tig + 4];
                #pragma unroll
                for (int mf = 0; mf < 2; mf++)
                    MMA_BF16(acc[mf][nf], af[mf][0], af[mf][1], af[mf][2], af[mf][3], b0, b1);
            }
        }
        if (kt + 1 < nk) {
            int nb = cur ^ 1;
            As[nb][arow][akp+0] = ua.x; As[nb][arow][akp+1] = ua.y;
            As[nb][arow][akp+2] = ua.z; As[nb][arow][akp+3] = ua.w;
            Bs[nb][arow][akp+0] = ub.x; Bs[nb][arow][akp+1] = ub.y;
            Bs[nb][arow][akp+2] = ub.z; Bs[nb][arow][akp+3] = ub.w;
        }
    }

    #pragma unroll
    for (int mf = 0; mf < 2; mf++) {
        int r_lo = row0 + warp_m * 32 + mf * 16 + grp;
        int r_hi = r_lo + 8;
        #pragma unroll
        for (int nf = 0; nf < 8; nf++) {
            int cl = warp_n * 64 + nf * 8 + tig * 2;
            float bv0 = bias[col0 + cl], bv1 = bias[col0 + cl + 1];
            float v0 = acc[mf][nf][0] + bv0, v1 = acc[mf][nf][1] + bv1;
            float v2 = acc[mf][nf][2] + bv0, v3 = acc[mf][nf][3] + bv1;
            if (relu) { v0 = fmaxf(v0, 0.f); v1 = fmaxf(v1, 0.f);
                        v2 = fmaxf(v2, 0.f); v3 = fmaxf(v3, 0.f); }
            if (!obf) {
                *(float2*)&outf[(size_t)r_lo * nstride + col0 + cl] = make_float2(v0, v1);
                *(float2*)&outf[(size_t)r_hi * nstride + col0 + cl] = make_float2(v2, v3);
            } else {
                *(uint32_t*)&outb[(size_t)r_lo * nstride + col0 + cl] = packbf2(v0, v1);
                *(uint32_t*)&outb[(size_t)r_hi * nstride + col0 + cl] = packbf2(v2, v3);
            }
        }
    }
}

// ======== K-split BF16 GEMM: z selects K half; writes fp32 partials ========
// grid (N/128, M/128, 2). N fixed at CC=512 columns covered, partial stride CC.
__global__ __launch_bounds__(256) void gemm_bb_ks_kernel(
    const __nv_bfloat16* __restrict__ A, const __nv_bfloat16* __restrict__ Wt, int K)
{
    __shared__ uint32_t As[2][128][9];
    __shared__ uint32_t Bs[2][128][9];
    int tid = threadIdx.x;
    int lane = tid & 31;
    int warp = tid >> 5;
    int warp_m = warp & 3;
    int warp_n = warp >> 2;
    int grp = lane >> 2;
    int tig = lane & 3;

    int row0 = blockIdx.y * 128, col0 = blockIdx.x * 128;
    int koff = blockIdx.z * (K >> 1);
    const __nv_bfloat16* Ab = A + (size_t)row0 * K + koff;
    const __nv_bfloat16* Wb = Wt + (size_t)col0 * K + koff;
    float* outp = g_part + (size_t)blockIdx.z * BT * CC;

    const int arow = tid >> 1, akoff = (tid & 1) * 8, akp = (tid & 1) * 4;

    float acc[2][8][4];
    #pragma unroll
    for (int i = 0; i < 2; i++)
        #pragma unroll
        for (int j = 0; j < 8; j++)
            #pragma unroll
            for (int c = 0; c < 4; c++) acc[i][j][c] = 0.0f;

    uint4 ua, ub;
    ua = *(const uint4*)&Ab[(size_t)arow * K + akoff];
    ub = *(const uint4*)&Wb[(size_t)arow * K + akoff];
    As[0][arow][akp+0] = ua.x; As[0][arow][akp+1] = ua.y;
    As[0][arow][akp+2] = ua.z; As[0][arow][akp+3] = ua.w;
    Bs[0][arow][akp+0] = ub.x; Bs[0][arow][akp+1] = ub.y;
    Bs[0][arow][akp+2] = ub.z; Bs[0][arow][akp+3] = ub.w;

    int nk = K >> 5;   // half of K, 16 per tile
    for (int kt = 0; kt < nk; kt++) {
        __syncthreads();
        int cur = kt & 1;
        if (kt + 1 < nk) {
            int k0 = (kt + 1) << 4;
            ua = *(const uint4*)&Ab[(size_t)arow * K + k0 + akoff];
            ub = *(const uint4*)&Wb[(size_t)arow * K + k0 + akoff];
        }
        {
            uint32_t af[2][4];
            #pragma unroll
            for (int mf = 0; mf < 2; mf++) {
                int m = warp_m * 32 + mf * 16 + grp;
                af[mf][0] = As[cur][m][tig];
                af[mf][1] = As[cur][m + 8][tig];
                af[mf][2] = As[cur][m][tig + 4];
                af[mf][3] = As[cur][m + 8][tig + 4];
            }
            #pragma unroll
            for (int nf = 0; nf < 8; nf++) {
                int n = warp_n * 64 + nf * 8 + grp;
                uint32_t b0 = Bs[cur][n][tig];
                uint32_t b1 = Bs[cur][n][tig + 4];
                #pragma unroll
                for (int mf = 0; mf < 2; mf++)
                    MMA_BF16(acc[mf][nf], af[mf][0], af[mf][1], af[mf][2], af[mf][3], b0, b1);
            }
        }
        if (kt + 1 < nk) {
            int nb = cur ^ 1;
            As[nb][arow][akp+0] = ua.x; As[nb][arow][akp+1] = ua.y;
            As[nb][arow][akp+2] = ua.z; As[nb][arow][akp+3] = ua.w;
            Bs[nb][arow][akp+0] = ub.x; Bs[nb][arow][akp+1] = ub.y;
            Bs[nb][arow][akp+2] = ub.z; Bs[nb][arow][akp+3] = ub.w;
        }
    }

    #pragma unroll
    for (int mf = 0; mf < 2; mf++) {
        int r_lo = row0 + warp_m * 32 + mf * 16 + grp;
        int r_hi = r_lo + 8;
        #pragma unroll
        for (int nf = 0; nf < 8; nf++) {
            int cl = col0 + warp_n * 64 + nf * 8 + tig * 2;
            *(float2*)&outp[(size_t)r_lo * CC + cl] = make_float2(acc[mf][nf][0], acc[mf][nf][1]);
            *(float2*)&outp[(size_t)r_hi * CC + cl] = make_float2(acc[mf][nf][2], acc[mf][nf][3]);
        }
    }
}

// ======== combine K-split partials: out[row*stride + c] = p0+p1+bias ========
__global__ void ks_combine_kernel(const float* __restrict__ bias,
                                  float* __restrict__ outf, int nstride)
{
    int i = blockIdx.x * 256 + threadIdx.x;   // over BT*CC
    int row = i >> 9, c = i & 511;
    float v = g_part[i] + g_part[(size_t)BT * CC + i] + bias[c];
    outf[(size_t)row * nstride + c] = v;
}

// ======== exact fp32 SIMT GEMM (seg-critical stage0/l0 Q,K) ========
__global__ __launch_bounds__(256) void gemm_kernel(
    const float* __restrict__ A, const float* __restrict__ W,
    const float* __restrict__ bias, float* __restrict__ Cout,
    int M, int Ntot, int K, int relu, int sub_n)
{
    __shared__ float As[2][16][128];
    __shared__ float Bs[2][16][128];
    int tid = threadIdx.x;
    int tx = tid & 15, ty = tid >> 4;
    int row0 = blockIdx.y * 128, col0 = blockIdx.x * 128;
    int mat = col0 / sub_n;
    int coln = col0 % sub_n;
    const float* Wb = W + (size_t)mat * K * sub_n + coln;
    const float* Ab = A + (size_t)row0 * K;

    const int arow = tid >> 1, akoff = (tid & 1) * 8;
    const int bk = tid >> 4, bcol = (tid & 15) * 8;

    float acc[8][8] = {};
    float4 ra0, ra1, rb0, rb1;

    ra0 = *(const float4*)&Ab[(size_t)arow * K + akoff];
    ra1 = *(const float4*)&Ab[(size_t)arow * K + akoff + 4];
    rb0 = *(const float4*)&Wb[(size_t)bk * sub_n + bcol];
    rb1 = *(const float4*)&Wb[(size_t)bk * sub_n + bcol + 4];
    As[0][akoff+0][arow]=ra0.x; As[0][akoff+1][arow]=ra0.y;
    As[0][akoff+2][arow]=ra0.z; As[0][akoff+3][arow]=ra0.w;
    As[0][akoff+4][arow]=ra1.x; As[0][akoff+5][arow]=ra1.y;
    As[0][akoff+6][arow]=ra1.z; As[0][akoff+7][arow]=ra1.w;
    *(float4*)&Bs[0][bk][bcol]   = rb0;
    *(float4*)&Bs[0][bk][bcol+4] = rb1;
    __syncthreads();

    int nk = K >> 4;
    for (int kt = 0; kt < nk; kt++) {
        int buf = kt & 1;
        if (kt + 1 < nk) {
            int k0 = (kt + 1) << 4;
            ra0 = *(const float4*)&Ab[(size_t)arow * K + k0 + akoff];
            ra1 = *(const float4*)&Ab[(size_t)arow * K + k0 + akoff + 4];
            rb0 = *(const float4*)&Wb[(size_t)(k0 + bk) * sub_n + bcol];
            rb1 = *(const float4*)&Wb[(size_t)(k0 + bk) * sub_n + bcol + 4];
        }
        #pragma unroll
        for (int kk = 0; kk < 16; kk++) {
            float a[8], b[8];
            *(float4*)(a)   = *(const float4*)&As[buf][kk][ty*8];
            *(float4*)(a+4) = *(const float4*)&As[buf][kk][ty*8+4];
            *(float4*)(b)   = *(const float4*)&Bs[buf][kk][tx*8];
            *(float4*)(b+4) = *(const float4*)&Bs[buf][kk][tx*8+4];
            #pragma unroll
            for (int i = 0; i < 8; i++)
                #pragma unroll
                for (int j = 0; j < 8; j++)
                    acc[i][j] += a[i] * b[j];
        }
        if (kt + 1 < nk) {
            int nb2 = buf ^ 1;
            As[nb2][akoff+0][arow]=ra0.x; As[nb2][akoff+1][arow]=ra0.y;
            As[nb2][akoff+2][arow]=ra0.z; As[nb2][akoff+3][arow]=ra0.w;
            As[nb2][akoff+4][arow]=ra1.x; As[nb2][akoff+5][arow]=ra1.y;
            As[nb2][akoff+6][arow]=ra1.z; As[nb2][akoff+7][arow]=ra1.w;
            *(float4*)&Bs[nb2][bk][bcol]   = rb0;
            *(float4*)&Bs[nb2][bk][bcol+4] = rb1;
        }
        __syncthreads();
    }

    const float* bb = bias + (size_t)mat * sub_n + coln;
    float bv[8];
    #pragma unroll
    for (int j = 0; j < 8; j++) bv[j] = bb[tx*8 + j];
    #pragma unroll
    for (int i = 0; i < 8; i++) {
        size_t r = (size_t)(row0 + ty*8 + i);
        float o[8];
        #pragma unroll
        for (int j = 0; j < 8; j++) {
            float v = acc[i][j] + bv[j];
            o[j] = relu ? fmaxf(v, 0.0f) : v;
        }
        *(float4*)&Cout[r * Ntot + col0 + tx*8]     = *(float4*)(o);
        *(float4*)&Cout[r * Ntot + col0 + tx*8 + 4] = *(float4*)(o+4);
    }
}

// ======== exact fp32 scores (stage0/l0 only) ========
__global__ __launch_bounds__(256) void scores_kernel(int use_mask)
{
    int bh = blockIdx.z;
    int b = bh >> 3, h = bh & 7;
    int t0 = blockIdx.y * 128, s0 = blockIdx.x * 128;
    __shared__ float Qs[2][16][128];
    __shared__ float Ks[2][16][128];
    int tid = threadIdx.x;
    int tx = tid & 15, ty = tid >> 4;

    const int arow = tid >> 1, akoff = (tid & 1) * 8;
    const float* qb = g_qkv + (size_t)(b*TT + t0) * QKVN + h*64;
    const float* kb = g_qkv + (size_t)(b*TT + s0) * QKVN + CC + h*64;

    float acc[8][8] = {};
    float4 ra0, ra1, rb0, rb1;

    ra0 = *(const float4*)&qb[(size_t)arow * QKVN + akoff];
    ra1 = *(const float4*)&qb[(size_t)arow * QKVN + akoff + 4];
    rb0 = *(const float4*)&kb[(size_t)arow * QKVN + akoff];
    rb1 = *(const float4*)&kb[(size_t)arow * QKVN + akoff + 4];
    Qs[0][akoff+0][arow]=ra0.x; Qs[0][akoff+1][arow]=ra0.y;
    Qs[0][akoff+2][arow]=ra0.z; Qs[0][akoff+3][arow]=ra0.w;
    Qs[0][akoff+4][arow]=ra1.x; Qs[0][akoff+5][arow]=ra1.y;
    Qs[0][akoff+6][arow]=ra1.z; Qs[0][akoff+7][arow]=ra1.w;
    Ks[0][akoff+0][arow]=rb0.x; Ks[0][akoff+1][arow]=rb0.y;
    Ks[0][akoff+2][arow]=rb0.z; Ks[0][akoff+3][arow]=rb0.w;
    Ks[0][akoff+4][arow]=rb1.x; Ks[0][akoff+5][arow]=rb1.y;
    Ks[0][akoff+6][arow]=rb1.z; Ks[0][akoff+7][arow]=rb1.w;
    __syncthreads();

    #pragma unroll
    for (int kt = 0; kt < 4; kt++) {
        int buf = kt & 1;
        if (kt + 1 < 4) {
            int k0 = (kt + 1) << 4;
            ra0 = *(const float4*)&qb[(size_t)arow * QKVN + k0 + akoff];
            ra1 = *(const float4*)&qb[(size_t)arow * QKVN + k0 + akoff + 4];
            rb0 = *(const float4*)&kb[(size_t)arow * QKVN + k0 + akoff];
            rb1 = *(const float4*)&kb[(size_t)arow * QKVN + k0 + akoff + 4];
        }
        #pragma unroll
        for (int kk = 0; kk < 16; kk++) {
            float a[8], c[8];
            *(float4*)(a)   = *(const float4*)&Qs[buf][kk][ty*8];
            *(float4*)(a+4) = *(const float4*)&Qs[buf][kk][ty*8+4];
            *(float4*)(c)   = *(const float4*)&Ks[buf][kk][tx*8];
            *(float4*)(c+4) = *(const float4*)&Ks[buf][kk][tx*8+4];
            #pragma unroll
            for (int i = 0; i < 8; i++)
                #pragma unroll
                for (int j = 0; j < 8; j++)
                    acc[i][j] += a[i] * c[j];
        }
        if (kt + 1 < 4) {
            int nb2 = buf ^ 1;
            Qs[nb2][akoff+0][arow]=ra0.x; Qs[nb2][akoff+1][arow]=ra0.y;
            Qs[nb2][akoff+2][arow]=ra0.z; Qs[nb2][akoff+3][arow]=ra0.w;
            Qs[nb2][akoff+4][arow]=ra1.x; Qs[nb2][akoff+5][arow]=ra1.y;
            Qs[nb2][akoff+6][arow]=ra1.z; Qs[nb2][akoff+7][arow]=ra1.w;
            Ks[nb2][akoff+0][arow]=rb0.x; Ks[nb2][akoff+1][arow]=rb0.y;
            Ks[nb2][akoff+2][arow]=rb0.z; Ks[nb2][akoff+3][arow]=rb0.w;
            Ks[nb2][akoff+4][arow]=rb1.x; Ks[nb2][akoff+5][arow]=rb1.y;
            Ks[nb2][akoff+6][arow]=rb1.z; Ks[nb2][akoff+7][arow]=rb1.w;
        }
        __syncthreads();
    }

    float* dst = g_s + (size_t)bh * TT * TT;
    int segt[8], segs[8];
    if (use_mask) {
        #pragma unroll
        for (int i = 0; i < 8; i++) segt[i] = g_seg[b*TT + t0 + ty*8 + i];
        #pragma unroll
        for (int j = 0; j < 8; j++) segs[j] = g_seg[b*TT + s0 + tx*8 + j];
    }
    #pragma unroll
    for (int i = 0; i < 8; i++) {
        size_t t = (size_t)(t0 + ty*8 + i);
        float o[8];
        #pragma unroll
        for (int j = 0; j < 8; j++) {
            float v = acc[i][j] * 0.125f;
            if (use_mask && segt[i] != segs[j]) v += NEGI;
            o[j] = v;
        }
        *(float4*)&dst[t * TT + s0 + tx*8]     = *(float4*)(o);
        *(float4*)&dst[t * TT + s0 + tx*8 + 4] = *(float4*)(o+4);
    }
}

// ======== BF16 scores: bf16 in (g_qkvb), bf16 out (g_sb) ========
__global__ __launch_bounds__(256) void scores_bf16_kernel(int use_mask)
{
    int bh = blockIdx.z;
    int b = bh >> 3, h = bh & 7;
    int t0 = blockIdx.y * 128, s0 = blockIdx.x * 128;
    __shared__ uint32_t Qs[2][128][9];
    __shared__ uint32_t Ks[2][128][9];
    int tid = threadIdx.x;
    int lane = tid & 31;
    int warp = tid >> 5;
    int warp_m = warp & 3;
    int warp_n = warp >> 2;
    int grp = lane >> 2;
    int tig = lane & 3;

    const int arow = tid >> 1, akoff = (tid & 1) * 8, akp = (tid & 1) * 4;
    const __nv_bfloat16* qb = g_qkvb + (size_t)(b*TT + t0) * QKVN + h*64;
    const __nv_bfloat16* kb = g_qkvb + (size_t)(b*TT + s0) * QKVN + CC + h*64;

    float acc[2][8][4];
    #pragma unroll
    for (int i = 0; i < 2; i++)
        #pragma unroll
        for (int j = 0; j < 8; j++)
            #pragma unroll
            for (int c = 0; c < 4; c++) acc[i][j][c] = 0.0f;

    uint4 uq, uk;
    uq = *(const uint4*)&qb[(size_t)arow * QKVN + akoff];
    uk = *(const uint4*)&kb[(size_t)arow * QKVN + akoff];
    Qs[0][arow][akp+0] = uq.x; Qs[0][arow][akp+1] = uq.y;
    Qs[0][arow][akp+2] = uq.z; Qs[0][arow][akp+3] = uq.w;
    Ks[0][arow][akp+0] = uk.x; Ks[0][arow][akp+1] = uk.y;
    Ks[0][arow][akp+2] = uk.z; Ks[0][arow][akp+3] = uk.w;

    #pragma unroll
    for (int kt = 0; kt < 4; kt++) {
        __syncthreads();
        int cur = kt & 1;
        if (kt + 1 < 4) {
            int k0 = (kt + 1) << 4;
            uq = *(const uint4*)&qb[(size_t)arow * QKVN + k0 + akoff];
            uk = *(const uint4*)&kb[(size_t)arow * QKVN + k0 + akoff];
        }
        {
            uint32_t af[2][4];
            #pragma unroll
            for (int mf = 0; mf < 2; mf++) {
                int m = warp_m * 32 + mf * 16 + grp;
                af[mf][0] = Qs[cur][m][tig];
                af[mf][1] = Qs[cur][m + 8][tig];
                af[mf][2] = Qs[cur][m][tig + 4];
                af[mf][3] = Qs[cur][m + 8][tig + 4];
            }
            #pragma unroll
            for (int nf = 0; nf < 8; nf++) {
                int n = warp_n * 64 + nf * 8 + grp;
                uint32_t b0 = Ks[cur][n][tig];
                uint32_t b1 = Ks[cur][n][tig + 4];
                #pragma unroll
                for (int mf = 0; mf < 2; mf++)
                    MMA_BF16(acc[mf][nf], af[mf][0], af[mf][1], af[mf][2], af[mf][3], b0, b1);
            }
        }
        if (kt + 1 < 4) {
            int nb2 = cur ^ 1;
            Qs[nb2][arow][akp+0] = uq.x; Qs[nb2][arow][akp+1] = uq.y;
            Qs[nb2][arow][akp+2] = uq.z; Qs[nb2][arow][akp+3] = uq.w;
            Ks[nb2][arow][akp+0] = uk.x; Ks[nb2][arow][akp+1] = uk.y;
            Ks[nb2][arow][akp+2] = uk.z; Ks[nb2][arow][akp+3] = uk.w;
        }
    }

    __nv_bfloat16* dst = g_sb + (size_t)bh * TT * TT;
    #pragma unroll
    for (int mf = 0; mf < 2; mf++) {
        int r_lo = warp_m * 32 + mf * 16 + grp;
        int r_hi = r_lo + 8;
        int sg_lo = 0, sg_hi = 0;
        if (use_mask) {
            sg_lo = g_seg[b*TT + t0 + r_lo];
            sg_hi = g_seg[b*TT + t0 + r_hi];
        }
        #pragma unroll
        for (int nf = 0; nf < 8; nf++) {
            int cl = warp_n * 64 + nf * 8 + tig * 2;
            float v0 = acc[mf][nf][0] * 0.125f, v1 = acc[mf][nf][1] * 0.125f;
            float v2 = acc[mf][nf][2] * 0.125f, v3 = acc[mf][nf][3] * 0.125f;
            if (use_mask) {
                int s_a = g_seg[b*TT + s0 + cl];
                int s_b = g_seg[b*TT + s0 + cl + 1];
                if (sg_lo != s_a) v0 += NEGI;
                if (sg_lo != s_b) v1 += NEGI;
                if (sg_hi != s_a) v2 += NEGI;
                if (sg_hi != s_b) v3 += NEGI;
            }
            *(uint32_t*)&dst[(size_t)(t0 + r_lo) * TT + s0 + cl] = packbf2(v0, v1);
            *(uint32_t*)&dst[(size_t)(t0 + r_hi) * TT + s0 + cl] = packbf2(v2, v3);
        }
    }
}

// ======== TF32 PV (stage0/l0 only): fp32 S @ fp32 V -> bf16 g_ab ========
__global__ __launch_bounds__(256) void pv_tf32_kernel()
{
    int bh = blockIdx.y;
    int b = bh >> 3, h = bh & 7;
    int t0 = blockIdx.x * 128;
    __shared__ float Ps[16][136];
    __shared__ float Vs[16][72];
    int tid = threadIdx.x;
    int lane = tid & 31;
    int warp = tid >> 5;
    int warp_m = warp & 3;
    int warp_n = warp >> 2;
    int grp = lane >> 2;
    int tig = lane & 3;

    const int arow = tid >> 1, akoff = (tid & 1) * 8;
    const int vk = tid >> 4, vcol = (tid & 15) * 4;

    const float* srow = g_s + (size_t)bh * TT * TT + (size_t)t0 * TT;
    const float* vb = g_qkv + (size_t)(b*TT) * QKVN + 2*CC + h*64;

    float acc[2][4][4];
    #pragma unroll
    for (int i = 0; i < 2; i++)
        #pragma unroll
        for (int j = 0; j < 4; j++)
            #pragma unroll
            for (int c = 0; c < 4; c++) acc[i][j][c] = 0.0f;

    float4 ra0, ra1, rv0;
    ra0 = *(const float4*)&srow[(size_t)arow * TT + akoff];
    ra1 = *(const float4*)&srow[(size_t)arow * TT + akoff + 4];
    rv0 = *(const float4*)&vb[(size_t)vk * QKVN + vcol];

    const int nk = TT / 16;
    for (int kt = 0; kt < nk; kt++) {
        Ps[akoff+0][arow] = f2tf32(ra0.x); Ps[akoff+1][arow] = f2tf32(ra0.y);
        Ps[akoff+2][arow] = f2tf32(ra0.z); Ps[akoff+3][arow] = f2tf32(ra0.w);
        Ps[akoff+4][arow] = f2tf32(ra1.x); Ps[akoff+5][arow] = f2tf32(ra1.y);
        Ps[akoff+6][arow] = f2tf32(ra1.z); Ps[akoff+7][arow] = f2tf32(ra1.w);
        Vs[vk][vcol+0] = f2tf32(rv0.x); Vs[vk][vcol+1] = f2tf32(rv0.y);
        Vs[vk][vcol+2] = f2tf32(rv0.z); Vs[vk][vcol+3] = f2tf32(rv0.w);
        __syncthreads();

        if (kt + 1 < nk) {
            int k0 = (kt + 1) << 4;
            ra0 = *(const float4*)&srow[(size_t)arow * TT + k0 + akoff];
            ra1 = *(const float4*)&srow[(size_t)arow * TT + k0 + akoff + 4];
            rv0 = *(const float4*)&vb[(size_t)(k0 + vk) * QKVN + vcol];
        }

        #pragma unroll
        for (int ks = 0; ks < 2; ks++) {
            int kb2 = ks * 8;
            uint32_t af[2][4];
            #pragma unroll
            for (int mf = 0; mf < 2; mf++) {
                int m = warp_m * 32 + mf * 16 + grp;
                af[mf][0] = __float_as_uint(Ps[kb2 + tig][m]);
                af[mf][1] = __float_as_uint(Ps[kb2 + tig][m + 8]);
                af[mf][2] = __float_as_uint(Ps[kb2 + tig + 4][m]);
                af[mf][3] = __float_as_uint(Ps[kb2 + tig + 4][m + 8]);
            }
            #pragma unroll
            for (int nf = 0; nf < 4; nf++) {
                int n = warp_n * 32 + nf * 8 + grp;
                uint32_t b0 = __float_as_uint(Vs[kb2 + tig][n]);
                uint32_t b1 = __float_as_uint(Vs[kb2 + tig + 4][n]);
                #pragma unroll
                for (int mf = 0; mf < 2; mf++)
                    MMA_TF32(acc[mf][nf], af[mf][0], af[mf][1], af[mf][2], af[mf][3], b0, b1);
            }
        }
        __syncthreads();
    }

    #pragma unroll
    for (int mf = 0; mf < 2; mf++) {
        int r_lo = warp_m * 32 + mf * 16 + grp;
        int r_hi = r_lo + 8;
        #pragma unroll
        for (int nf = 0; nf < 4; nf++) {
            int cl = warp_n * 32 + nf * 8 + tig * 2;
            *(uint32_t*)&g_ab[(size_t)(b*TT + t0 + r_lo) * CC + h*64 + cl] =
                packbf2(acc[mf][nf][0], acc[mf][nf][1]);
            *(uint32_t*)&g_ab[(size_t)(b*TT + t0 + r_hi) * CC + h*64 + cl] =
                packbf2(acc[mf][nf][2], acc[mf][nf][3]);
        }
    }
}

// ======== FUSED softmax + PV, bf16 S + bf16 V -> bf16 g_ab (fast exp) ========
__global__ __launch_bounds__(256) void fused_softmax_pv_kernel(int docolsum)
{
    int bh = blockIdx.y;
    int b = bh >> 3, h = bh & 7;
    int t0 = blockIdx.x * 128;
    const __nv_bfloat16* srow = g_sb + (size_t)bh * TT * TT + (size_t)t0 * TT;
    const __nv_bfloat16* vb = g_qkvb + (size_t)(b*TT) * QKVN + 2*CC + h*64;

    __shared__ float rowm[128];
    __shared__ float rowstat[128];
    __shared__ float Ps[16][136];
    __shared__ float Vs[16][72];
    __shared__ float colpart[16][8];

    int tid = threadIdx.x;
    int lane = tid & 31;
    int warp = tid >> 5;
    int warp_m = warp & 3;
    int warp_n = warp >> 2;
    int grp = lane >> 2;
    int tig = lane & 3;

    for (int r = warp * 16; r < warp * 16 + 16; r++) {
        const __nv_bfloat16* p = srow + (size_t)r * TT;
        float m = -3.4e38f, l = 0.0f;
        #pragma unroll
        for (int i = 0; i < 4; i++) {
            uint4 u = *(const uint4*)&p[lane * 8 + i * 256];
            float2 a0 = bf2f(u.x), a1 = bf2f(u.y), a2 = bf2f(u.z), a3 = bf2f(u.w);
            float mx = fmaxf(fmaxf(fmaxf(a0.x, a0.y), fmaxf(a1.x, a1.y)),
                             fmaxf(fmaxf(a2.x, a2.y), fmaxf(a3.x, a3.y)));
            if (docolsum) {
                float mn = fmaxf(m, mx);
                l = l * __expf(m - mn)
                  + __expf(a0.x - mn) + __expf(a0.y - mn) + __expf(a1.x - mn) + __expf(a1.y - mn)
                  + __expf(a2.x - mn) + __expf(a2.y - mn) + __expf(a3.x - mn) + __expf(a3.y - mn);
                m = mn;
            } else {
                m = fmaxf(m, mx);
            }
        }
        #pragma unroll
        for (int o = 16; o > 0; o >>= 1) {
            float m2 = __shfl_xor_sync(0xffffffffu, m, o);
            if (docolsum) {
                float l2 = __shfl_xor_sync(0xffffffffu, l, o);
                float mn = fmaxf(m, m2);
                l = l * __expf(m - mn) + l2 * __expf(m2 - mn);
                m = mn;
            } else {
                m = fmaxf(m, m2);
            }
        }
        if (lane == 0) { rowm[r] = m; rowstat[r] = l; }
    }
    __syncthreads();

    const int arow = tid >> 1, akoff = (tid & 1) * 8;
    const int vk = tid >> 4, vcol = (tid & 15) * 4;
    float minv = rowm[arow];
    float rl = docolsum ? (1.0f / rowstat[arow]) : 1.0f;
    float lpart = 0.0f;

    float acc[2][4][4];
    #pragma unroll
    for (int i = 0; i < 2; i++)
        #pragma unroll
        for (int j = 0; j < 4; j++)
            #pragma unroll
            for (int c = 0; c < 4; c++) acc[i][j][c] = 0.0f;

    float* wpdst = 0;
    if (docolsum)
        wpdst = g_wp + ((size_t)bh * 8 + blockIdx.x) * TT;

    const int nk = TT / 16;
    for (int kt = 0; kt < nk; kt++) {
        uint4 u = *(const uint4*)&srow[(size_t)arow * TT + kt*16 + akoff];
        float2 a0 = bf2f(u.x), a1 = bf2f(u.y), a2 = bf2f(u.z), a3 = bf2f(u.w);
        float pv_[8];
        pv_[0] = __expf(a0.x - minv) * rl; pv_[1] = __expf(a0.y - minv) * rl;
        pv_[2] = __expf(a1.x - minv) * rl; pv_[3] = __expf(a1.y - minv) * rl;
        pv_[4] = __expf(a2.x - minv) * rl; pv_[5] = __expf(a2.y - minv) * rl;
        pv_[6] = __expf(a3.x - minv) * rl; pv_[7] = __expf(a3.y - minv) * rl;
        if (!docolsum) {
            #pragma unroll
            for (int j = 0; j < 8; j++) lpart += pv_[j];
        }
        #pragma unroll
        for (int j = 0; j < 8; j++) Ps[akoff + j][arow] = f2tf32(pv_[j]);

        uint2 uv = *(const uint2*)&vb[(size_t)(kt*16 + vk) * QKVN + vcol];
        float2 v0 = bf2f(uv.x), v1 = bf2f(uv.y);
        Vs[vk][vcol+0] = f2tf32(v0.x); Vs[vk][vcol+1] = f2tf32(v0.y);
        Vs[vk][vcol+2] = f2tf32(v1.x); Vs[vk][vcol+3] = f2tf32(v1.y);
        __syncthreads();

        if (docolsum) {
            if (tid < 128) {
                int c = tid >> 3, rseg = tid & 7;
                float cs = 0.0f;
                #pragma unroll
                for (int j = 0; j < 16; j++) cs += Ps[c][rseg * 16 + j];
                colpart[c][rseg] = cs;
            }
            __syncthreads();
            if (tid < 16) {
                float cs = 0.0f;
                #pragma unroll
                for (int j = 0; j < 8; j++) cs += colpart[tid][j];
                wpdst[kt * 16 + tid] = cs;
            }
        }

        #pragma unroll
        for (int ks = 0; ks < 2; ks++) {
            int kb2 = ks * 8;
            uint32_t af[2][4];
            #pragma unroll
            for (int mf = 0; mf < 2; mf++) {
                int m = warp_m * 32 + mf * 16 + grp;
                af[mf][0] = __float_as_uint(Ps[kb2 + tig][m]);
                af[mf][1] = __float_as_uint(Ps[kb2 + tig][m + 8]);
                af[mf][2] = __float_as_uint(Ps[kb2 + tig + 4][m]);
                af[mf][3] = __float_as_uint(Ps[kb2 + tig + 4][m + 8]);
            }
            #pragma unroll
            for (int nf = 0; nf < 4; nf++) {
                int n = warp_n * 32 + nf * 8 + grp;
                uint32_t b0 = __float_as_uint(Vs[kb2 + tig][n]);
                uint32_t b1 = __float_as_uint(Vs[kb2 + tig + 4][n]);
                #pragma unroll
                for (int mf = 0; mf < 2; mf++)
                    MMA_TF32(acc[mf][nf], af[mf][0], af[mf][1], af[mf][2], af[mf][3], b0, b1);
            }
        }
        __syncthreads();
    }

    if (!docolsum) {
        lpart += __shfl_xor_sync(0xffffffffu, lpart, 1);
        if ((tid & 1) == 0) rowstat[arow] = lpart;
        __syncthreads();
    }

    #pragma unroll
    for (int mf = 0; mf < 2; mf++) {
        int r_lo = warp_m * 32 + mf * 16 + grp;
        int r_hi = r_lo + 8;
        float inv_lo = docolsum ? 1.0f : (1.0f / rowstat[r_lo]);
        float inv_hi = docolsum ? 1.0f : (1.0f / rowstat[r_hi]);
        #pragma unroll
        for (int nf = 0; nf < 4; nf++) {
            int cl = warp_n * 32 + nf * 8 + tig * 2;
            *(uint32_t*)&g_ab[(size_t)(b*TT + t0 + r_lo) * CC + h*64 + cl] =
                packbf2(acc[mf][nf][0] * inv_lo, acc[mf][nf][1] * inv_lo);
            *(uint32_t*)&g_ab[(size_t)(b*TT + t0 + r_hi) * CC + h*64 + cl] =
                packbf2(acc[mf][nf][2] * inv_hi, acc[mf][nf][3] * inv_hi);
        }
    }
}

// ---------------- reduce colsum partials ----------------
__global__ void wreduce_kernel()
{
    int idx = blockIdx.x * 256 + threadIdx.x;
    int b = idx / TT, s = idx % TT;
    float acc = 0.0f;
    #pragma unroll 8
    for (int j = 0; j < HH * 8; j++)
        acc += g_wp[((size_t)(b * HH * 8 + j)) * TT + s];
    g_w[idx] = acc * (1.0f / HH);
}

// ---------------- row softmax (stage0/l0): shuffle reductions, expf kept ------
__global__ void softmax_rows_kernel(float* __restrict__ S)
{
    float* p = S + (size_t)blockIdx.x * TT;
    int tid = threadIdx.x;
    int lane = tid & 31, wid = tid >> 5;
    __shared__ float wredm[8];
    __shared__ float wreds[8];
    float v[4];
    float m = -3.4e38f;
    #pragma unroll
    for (int i = 0; i < 4; i++) { v[i] = p[tid + i * 256]; m = fmaxf(m, v[i]); }
    #pragma unroll
    for (int o = 16; o > 0; o >>= 1)
        m = fmaxf(m, __shfl_xor_sync(0xffffffffu, m, o));
    if (lane == 0) wredm[wid] = m;
    __syncthreads();
    float mx = wredm[0];
    #pragma unroll
    for (int j = 1; j < 8; j++) mx = fmaxf(mx, wredm[j]);
    float sum = 0.0f;
    #pragma unroll
    for (int i = 0; i < 4; i++) { v[i] = expf(v[i] - mx); sum += v[i]; }
    #pragma unroll
    for (int o = 16; o > 0; o >>= 1)
        sum += __shfl_xor_sync(0xffffffffu, sum, o);
    if (lane == 0) wreds[wid] = sum;
    __syncthreads();
    float tot = wreds[0];
    #pragma unroll
    for (int j = 1; j < 8; j++) tot += wreds[j];
    float inv = 1.0f / tot;
    #pragma unroll
    for (int i = 0; i < 4; i++) p[tid + i * 256] = v[i] * inv;
}

// ---------------- head-averaged probs (stage0/l0 only) ----------------
__global__ void head_avg_kernel()
{
    size_t idx = (size_t)blockIdx.x * 256 + threadIdx.x;
    size_t b = idx / ((size_t)TT * TT / 4);
    size_t r = idx % ((size_t)TT * TT / 4);
    float4 sum = make_float4(0.f, 0.f, 0.f, 0.f);
    #pragma unroll
    for (int h = 0; h < HH; h++) {
        float4 x = *((const float4*)(g_s + (b * HH + h) * (size_t)TT * TT) + r);
        sum.x += x.x; sum.y += x.y; sum.z += x.z; sum.w += x.w;
    }
    sum.x *= (1.0f/HH); sum.y *= (1.0f/HH); sum.z *= (1.0f/HH); sum.w *= (1.0f/HH);
    *((float4*)(g_p0 + b * (size_t)TT * TT) + r) = sum;
}

// ---------------- out = LN(res + add), shuffle reductions ----------------
__global__ void ln_residual_kernel(const float* __restrict__ res, const float* __restrict__ add,
                                   float* __restrict__ out, __nv_bfloat16* __restrict__ outb,
                                   const float* __restrict__ gamma, const float* __restrict__ beta)
{
    int row = blockIdx.x, tid = threadIdx.x;
    int lane = tid & 31, wid = tid >> 5;
    __shared__ float wred1[8];
    __shared__ float wred2[8];
    const float* r = res + (size_t)row * CC;
    const float* a = add + (size_t)row * CC;
    float v0 = r[tid] + a[tid];
    float v1 = r[tid + 256] + a[tid + 256];
    float s = v0 + v1;
    #pragma unroll
    for (int o = 16; o > 0; o >>= 1) s += __shfl_xor_sync(0xffffffffu, s, o);
    if (lane == 0) wred1[wid] = s;
    __syncthreads();
    float tot = wred1[0];
    #pragma unroll
    for (int j = 1; j < 8; j++) tot += wred1[j];
    float mu = tot * (1.0f / CC);
    float d0 = v0 - mu, d1 = v1 - mu;
    float q = d0 * d0 + d1 * d1;
    #pragma unroll
    for (int o = 16; o > 0; o >>= 1) q += __shfl_xor_sync(0xffffffffu, q, o);
    if (lane == 0) wred2[wid] = q;
    __syncthreads();
    float qt = wred2[0];
    #pragma unroll
    for (int j = 1; j < 8; j++) qt += wred2[j];
    float rstd = rsqrtf(qt * (1.0f / CC) + 1e-5f);
    float o0 = d0 * rstd * gamma[tid] + beta[tid];
    float o1 = d1 * rstd * gamma[tid + 256] + beta[tid + 256];
    float* o = out + (size_t)row * CC;
    o[tid] = o0; o[tid + 256] = o1;
    __nv_bfloat16* ob = outb + (size_t)row * CC;
    ob[tid] = __float2bfloat16(o0);
    ob[tid + 256] = __float2bfloat16(o1);
}

// ---------------- w[b,s] = sum_t p0[b,t,s] (stage0 only, order-preserving) ----
__global__ void colsum_kernel()
{
    int idx = blockIdx.x * 256 + threadIdx.x;
    int b = idx / TT, s = idx % TT;
    const float* base = g_p0 + (size_t)b * TT * TT + s;
    float acc = 0.0f;
    for (int t = 0; t < TT; t += 8) {
        float v[8];
        #pragma unroll
        for (int j = 0; j < 8; j++) v[j] = base[(size_t)(t + j) * TT];
        #pragma unroll
        for (int j = 0; j < 8; j++) acc += v[j];
    }
    g_w[idx] = acc;
}

// ---------------- segment scan ----------------
__global__ void segment_kernel()
{
    int b = blockIdx.x, tid = threadIdx.x;
    __shared__ float smin[256], smax[256];
    float lo = 3.4e38f, hi = -3.4e38f;
    for (int t = tid; t < TT; t += 256) {
        float v = g_w[b * TT + t];
        lo = fminf(lo, v); hi = fmaxf(hi, v);
    }
    smin[tid] = lo; smax[tid] = hi; __syncthreads();
    for (int s = 128; s > 0; s >>= 1) {
        if (tid < s) { smin[tid] = fminf(smin[tid], smin[tid + s]); smax[tid] = fmaxf(smax[tid], smax[tid + s]); }
        __syncthreads();
    }
    if (tid == 0) {
        float wmin = smin[0], wmax = smax[0];
        float denom = fmaxf(wmax - wmin, 1e-12f);
        bool prev = ((g_w[b * TT + 0] - wmin) / denom) >= 0.5f;
        int start = 0, segc = 0;
        g_seg[b * TT + 0] = 0;
        g_segstart[b * (TT + 1) + 0] = 0;
        for (int t = 1; t < TT; t++) {
            bool cur = ((g_w[b * TT + t] - wmin) / denom) >= 0.5f;
            if (cur != prev && (start + 1) != t) {
                start = t; segc++;
                g_segstart[b * (TT + 1) + segc] = t;
            }
            g_seg[b * TT + t] = segc;
            prev = cur;
        }
        g_nseg[b] = segc + 1;
        g_segstart[b * (TT + 1) + segc + 1] = TT;
    }
}

// ---------------- aw = softmax_s(w) ----------------
__global__ void batch_softmax_kernel()
{
    int b = blockIdx.x, tid = threadIdx.x;
    __shared__ float red[256];
    float v[4];
    float m = -3.4e38f;
    #pragma unroll
    for (int i = 0; i < 4; i++) { v[i] = g_w[b * TT + tid + i * 256]; m = fmaxf(m, v[i]); }
    red[tid] = m; __syncthreads();
    for (int s = 128; s > 0; s >>= 1) { if (tid < s) red[tid] = fmaxf(red[tid], red[tid + s]); __syncthreads(); }
    float mx = red[0];
    __syncthreads();
    float sum = 0.0f;
    #pragma unroll
    for (int i = 0; i < 4; i++) { v[i] = expf(v[i] - mx); sum += v[i]; }
    red[tid] = sum; __syncthreads();
    for (int s = 128; s > 0; s >>= 1) { if (tid < s) red[tid] += red[tid + s]; __syncthreads(); }
    float inv = 1.0f / red[0];
    #pragma unroll
    for (int i = 0; i < 4; i++) g_aw[b * TT + tid + i * 256] = v[i] * inv;
}

// ---------------- word tokens ----------------
__global__ void word_tokens_kernel(float* __restrict__ out)
{
    int b = blockIdx.y, i = blockIdx.x, tid = threadIdx.x;
    float* dst = out + ((size_t)b * 2 * TT + i) * CC;
    int ns = g_nseg[b];
    if (i >= ns) {
        for (int c = tid; c < CC; c += 256) dst[c] = 0.0f;
        return;
    }
    int t0 = g_segstart[b * (TT + 1) + i];
    int t1 = g_segstart[b * (TT + 1) + i + 1];
    for (int c = tid; c < CC; c += 256) {
        float acc = 0.0f;
        for (int t = t0; t < t1; t++)
            acc += g_x[((size_t)b * TT + t) * CC + c] * g_aw[b * TT + t];
        dst[c] = acc;
    }
}

__global__ void copyx_kernel(const float* __restrict__ xin, float* __restrict__ out)
{
    size_t idx = (size_t)blockIdx.x * 256 + threadIdx.x;
    size_t b = idx / ((size_t)TT * CC);
    size_t rem = idx % ((size_t)TT * CC);
    out[b * (size_t)2 * TT * CC + (size_t)TT * CC + rem] = xin[idx];
}

__global__ void wm_kernel(float* __restrict__ wmout)
{
    size_t idx = (size_t)blockIdx.x * 256 + threadIdx.x;
    size_t b = idx / ((size_t)TT * TT);
    int i = (int)((idx / TT) % TT);
    int t = (int)(idx % TT);
    wmout[idx] = (g_seg[b * TT + t] == i) ? 1.0f : 0.0f;
}

// ---------------- host orchestration ----------------
extern "C" void kernel_launch(void* const* d_in, const int* in_sizes, int n_in,
                              void* d_out, int out_size)
{
    const float* x_in = (const float*)d_in[0];
    const float* Wqkv = (const float*)d_in[1];
    const float* bqkv = (const float*)d_in[2];
    const float* Wo   = (const float*)d_in[3];
    const float* bo   = (const float*)d_in[4];
    const float* W1   = (const float*)d_in[5];
    const float* b1   = (const float*)d_in[6];
    const float* W2   = (const float*)d_in[7];
    const float* b2   = (const float*)d_in[8];
    const float* lng  = (const float*)d_in[9];
    const float* lnb  = (const float*)d_in[10];
    float* out = (float*)d_out;

    float *p_x, *p_qkv, *p_s, *p_t;
    __nv_bfloat16 *p_xb, *p_ab, *p_hb, *p_qkvb, *p_wqkv_b, *p_wo_b, *p_w1_b, *p_w2_b;
    cudaGetSymbolAddress((void**)&p_x, g_x);
    cudaGetSymbolAddress((void**)&p_qkv, g_qkv);
    cudaGetSymbolAddress((void**)&p_s, g_s);
    cudaGetSymbolAddress((void**)&p_t, g_t);
    cudaGetSymbolAddress((void**)&p_xb, g_xb);
    cudaGetSymbolAddress((void**)&p_ab, g_ab);
    cudaGetSymbolAddress((void**)&p_hb, g_hb);
    cudaGetSymbolAddress((void**)&p_qkvb, g_qkvb);
    cudaGetSymbolAddress((void**)&p_wqkv_b, g_wqkv_b);
    cudaGetSymbolAddress((void**)&p_wo_b, g_wo_b);
    cudaGetSymbolAddress((void**)&p_w1_b, g_w1_b);
    cudaGetSymbolAddress((void**)&p_w2_b, g_w2_b);

    cudaMemcpyAsync(p_x, x_in, sizeof(float) * (size_t)BT * CC, cudaMemcpyDeviceToDevice);
    cvt_kernel<<<(int)(((size_t)BT * CC) / 256), 256>>>(x_in, p_xb);

    dim3 tb(32, 8);
    transpose_cvt_all_kernel<<<dim3(1024, 1, 24), tb>>>(Wqkv, Wo, W1, W2,
                                                        p_wqkv_b, p_wo_b, p_w1_b, p_w2_b);

    dim3 grid_qkv(QKVN / 128, BT / 128);
    dim3 grid_cc_ks(CC / 128, BT / 128, 2);   // K-split: 256 CTAs
    dim3 grid_ff(FF / 128, BT / 128);
    dim3 grid_qk(2 * CC / 128, BT / 128);
    dim3 grid_sc(TT / 128, TT / 128, BB * HH);
    dim3 grid_pv(TT / 128, BB * HH);
    int comb_blocks = (BT * CC) / 256;

    for (int stage = 0; stage < 2; stage++) {
        int use_mask = (stage == 1);
        for (int l = 0; l < 2; l++) {
            int sl = stage * 2 + l;
            const __nv_bfloat16* Wqb = p_wqkv_b + (size_t)sl * 3 * CC * CC;
            const float* bb = bqkv + (size_t)sl * 3 * CC;

            if (stage == 0 && l == 0) {
                // seg-critical exact island (fp32 throughout for probs0 path)
                gemm_kernel<<<grid_qk, 256>>>(p_x, Wqkv + (size_t)sl * 3 * CC * CC, bb,
                                              p_qkv, BT, QKVN, CC, 0, CC);
                gemm_bb_ks_kernel<<<grid_cc_ks, 256>>>(p_xb, Wqb + (size_t)2 * CC * CC, CC);
                ks_combine_kernel<<<comb_blocks, 256>>>(bb + 2 * CC, p_qkv + 2 * CC, QKVN);
                scores_kernel<<<grid_sc, 256>>>(use_mask);
                softmax_rows_kernel<<<BB * HH * TT, 256>>>(p_s);
                head_avg_kernel<<<(int)(((size_t)BB * TT * TT / 4) / 256), 256>>>();
                pv_tf32_kernel<<<grid_pv, 256>>>();
            } else {
                gemm_bb_kernel<<<grid_qkv, 256>>>(p_xb, Wqb, bb, 0, p_qkvb,
                                                  QKVN, CC, 0, 1);
                scores_bf16_kernel<<<grid_sc, 256>>>(use_mask);
                int docolsum = (stage == 1 && l == 0) ? 1 : 0;
                fused_softmax_pv_kernel<<<grid_pv, 256>>>(docolsum);
                if (docolsum)
                    wreduce_kernel<<<BT / 256, 256>>>();
            }

            gemm_bb_ks_kernel<<<grid_cc_ks, 256>>>(p_ab, p_wo_b + (size_t)sl * CC * CC, CC);
            ks_combine_kernel<<<comb_blocks, 256>>>(bo + (size_t)sl * CC, p_t, CC);
            ln_residual_kernel<<<BT, 256>>>(p_x, p_t, p_x, p_xb,
                                            lng + (size_t)(sl * 2 + 0) * CC,
                                            lnb + (size_t)(sl * 2 + 0) * CC);

            gemm_bb_kernel<<<grid_ff, 256>>>(p_xb, p_w1_b + (size_t)sl * FF * CC,
                                             b1 + (size_t)sl * FF, 0, p_hb, FF, CC, 1, 1);
            gemm_bb_ks_kernel<<<grid_cc_ks, 256>>>(p_hb, p_w2_b + (size_t)sl * CC * FF, FF);
            ks_combine_kernel<<<comb_blocks, 256>>>(b2 + (size_t)sl * CC, p_t, CC);
            ln_residual_kernel<<<BT, 256>>>(p_x, p_t, p_x, p_xb,
                                            lng + (size_t)(sl * 2 + 1) * CC,
                                            lnb + (size_t)(sl * 2 + 1) * CC);
        }
        if (stage == 0) {
            colsum_kernel<<<BT / 256, 256>>>();
            segment_kernel<<<BB, 256>>>();
        } else {
            batch_softmax_kernel<<<BB, 256>>>();
        }
    }

    word_tokens_kernel<<<dim3(TT, BB), 256>>>(out);
    copyx_kernel<<<(int)(((size_t)BT * CC) / 256), 256>>>(x_in, out);
    wm_kernel<<<(int)(((size_t)BB * TT * TT) / 256), 256>>>(out + (size_t)BB * 2 * TT * CC);
}

// round 17
// speedup vs baseline: 1.1064x; 1.0193x over previous
#include <cuda_runtime.h>
#include <cuda_bf16.h>
#include <math.h>
#include <stdint.h>

// Problem constants
#define BB 4
#define TT 1024
#define CC 512
#define HH 8
#define DH 64
#define FF 2048
#define BT (BB*TT)
#define NEGI (-1e9f)
#define QKVN (3*CC)

// ---------------- scratch ----------------
__device__ float g_x[BT*CC];
__device__ float g_qkv[BT*QKVN];
__device__ float g_s[(size_t)BB*HH*TT*TT];
__device__ float g_p0[(size_t)BB*TT*TT];
__device__ float g_part[(size_t)2*BT*CC];            // K-split partials (16MB)
__device__ float g_w[BT];
__device__ float g_aw[BT];
__device__ float g_wp[BB*HH*8*TT];
__device__ int   g_seg[BT];
__device__ int   g_segstart[BB*(TT+1)];
__device__ int   g_nseg[BB];

// bf16 buffers
__device__ __nv_bfloat16 g_xb[BT*CC];
__device__ __nv_bfloat16 g_ab[BT*CC];
__device__ __nv_bfloat16 g_hb[BT*FF];
__device__ __nv_bfloat16 g_qkvb[BT*QKVN];
__device__ __nv_bfloat16 g_sb[(size_t)BB*HH*TT*TT];
__device__ __nv_bfloat16 g_wqkv_b[4*3*CC*CC];
__device__ __nv_bfloat16 g_wo_b[4*CC*CC];
__device__ __nv_bfloat16 g_w1_b[4*FF*CC];
__device__ __nv_bfloat16 g_w2_b[4*CC*FF];

__device__ __forceinline__ float f2tf32(float x) {
    uint32_t r;
    asm("cvt.rna.tf32.f32 %0, %1;" : "=r"(r) : "f"(x));
    return __uint_as_float(r);
}
__device__ __forceinline__ uint32_t packbf2(float lo, float hi) {
    uint32_t r;
    asm("cvt.rn.bf16x2.f32 %0, %1, %2;" : "=r"(r) : "f"(hi), "f"(lo));
    return r;
}
__device__ __forceinline__ float2 bf2f(uint32_t u) {
    __nv_bfloat162 h = *reinterpret_cast<__nv_bfloat162*>(&u);
    return __bfloat1622float2(h);
}

#define MMA_TF32(acc, a0,a1,a2,a3, b0,b1) \
    asm("mma.sync.aligned.m16n8k8.row.col.f32.tf32.tf32.f32 " \
        "{%0,%1,%2,%3}, {%4,%5,%6,%7}, {%8,%9}, {%0,%1,%2,%3};" \
        : "+f"(acc[0]), "+f"(acc[1]), "+f"(acc[2]), "+f"(acc[3]) \
        : "r"(a0), "r"(a1), "r"(a2), "r"(a3), "r"(b0), "r"(b1))

#define MMA_BF16(acc, a0,a1,a2,a3, b0,b1) \
    asm("mma.sync.aligned.m16n8k16.row.col.f32.bf16.bf16.f32 " \
        "{%0,%1,%2,%3}, {%4,%5,%6,%7}, {%8,%9}, {%0,%1,%2,%3};" \
        : "+f"(acc[0]), "+f"(acc[1]), "+f"(acc[2]), "+f"(acc[3]) \
        : "r"(a0), "r"(a1), "r"(a2), "r"(a3), "r"(b0), "r"(b1))

// ======== single-launch batched transpose+convert (24 weight matrices) ========
__global__ void transpose_cvt_all_kernel(const float* __restrict__ Wqkv,
                                         const float* __restrict__ Wo,
                                         const float* __restrict__ W1,
                                         const float* __restrict__ W2,
                                         __nv_bfloat16* __restrict__ dq,
                                         __nv_bfloat16* __restrict__ dwo,
                                         __nv_bfloat16* __restrict__ d1,
                                         __nv_bfloat16* __restrict__ d2)
{
    __shared__ float tile[32][33];
    int z = blockIdx.z;
    const float* src;
    __nv_bfloat16* dst;
    int K, N;
    if (z < 12)      { src = Wqkv + (size_t)z * CC * CC; dst = dq + (size_t)z * CC * CC; K = CC; N = CC; }
    else if (z < 16) { int m = z - 12; src = Wo + (size_t)m * CC * CC; dst = dwo + (size_t)m * CC * CC; K = CC; N = CC; }
    else if (z < 20) { int m = z - 16; src = W1 + (size_t)m * CC * FF; dst = d1 + (size_t)m * FF * CC; K = CC; N = FF; }
    else             { int m = z - 20; src = W2 + (size_t)m * FF * CC; dst = d2 + (size_t)m * CC * FF; K = FF; N = CC; }

    int ntn = N / 32, ntk = K / 32;
    int flat = blockIdx.x;
    if (flat >= ntn * ntk) return;
    int nb = (flat % ntn) * 32, kb = (flat / ntn) * 32;
    int tx = threadIdx.x, ty = threadIdx.y;
    #pragma unroll
    for (int j = ty; j < 32; j += 8)
        tile[j][tx] = src[(size_t)(kb + j) * N + nb + tx];
    __syncthreads();
    #pragma unroll
    for (int j = ty; j < 32; j += 8)
        dst[(size_t)(nb + j) * K + kb + tx] = __float2bfloat16(tile[tx][j]);
}

__global__ void cvt_kernel(const float* __restrict__ src, __nv_bfloat16* __restrict__ dst)
{
    size_t i = (size_t)blockIdx.x * 256 + threadIdx.x;
    dst[i] = __float2bfloat16(src[i]);
}

// ======== BF16xBF16 GEMM: 128x128x16, 2-stage (R12-proven) ========
__global__ __launch_bounds__(256) void gemm_bb_kernel(
    const __nv_bfloat16* __restrict__ A, const __nv_bfloat16* __restrict__ Wt,
    const float* __restrict__ bias, float* __restrict__ outf,
    __nv_bfloat16* __restrict__ outb, int nstride, int K, int relu, int obf)
{
    __shared__ uint32_t As[2][128][9];
    __shared__ uint32_t Bs[2][128][9];
    int tid = threadIdx.x;
    int lane = tid & 31;
    int warp = tid >> 5;
    int warp_m = warp & 3;
    int warp_n = warp >> 2;
    int grp = lane >> 2;
    int tig = lane & 3;

    int row0 = blockIdx.y * 128, col0 = blockIdx.x * 128;
    const __nv_bfloat16* Ab = A + (size_t)row0 * K;
    const __nv_bfloat16* Wb = Wt + (size_t)col0 * K;

    const int arow = tid >> 1, akoff = (tid & 1) * 8, akp = (tid & 1) * 4;

    float acc[2][8][4];
    #pragma unroll
    for (int i = 0; i < 2; i++)
        #pragma unroll
        for (int j = 0; j < 8; j++)
            #pragma unroll
            for (int c = 0; c < 4; c++) acc[i][j][c] = 0.0f;

    uint4 ua, ub;
    ua = *(const uint4*)&Ab[(size_t)arow * K + akoff];
    ub = *(const uint4*)&Wb[(size_t)arow * K + akoff];
    As[0][arow][akp+0] = ua.x; As[0][arow][akp+1] = ua.y;
    As[0][arow][akp+2] = ua.z; As[0][arow][akp+3] = ua.w;
    Bs[0][arow][akp+0] = ub.x; Bs[0][arow][akp+1] = ub.y;
    Bs[0][arow][akp+2] = ub.z; Bs[0][arow][akp+3] = ub.w;

    int nk = K >> 4;
    for (int kt = 0; kt < nk; kt++) {
        __syncthreads();
        int cur = kt & 1;
        if (kt + 1 < nk) {
            int k0 = (kt + 1) << 4;
            ua = *(const uint4*)&Ab[(size_t)arow * K + k0 + akoff];
            ub = *(const uint4*)&Wb[(size_t)arow * K + k0 + akoff];
        }
        {
            uint32_t af[2][4];
            #pragma unroll
            for (int mf = 0; mf < 2; mf++) {
                int m = warp_m * 32 + mf * 16 + grp;
                af[mf][0] = As[cur][m][tig];
                af[mf][1] = As[cur][m + 8][tig];
                af[mf][2] = As[cur][m][tig + 4];
                af[mf][3] = As[cur][m + 8][tig + 4];
            }
            #pragma unroll
            for (int nf = 0; nf < 8; nf++) {
                int n = warp_n * 64 + nf * 8 + grp;
                uint32_t b0 = Bs[cur][n][tig];
                uint32_t b1 = Bs[cur][n][tig + 4];
                #pragma unroll
                for (int mf = 0; mf < 2; mf++)
                    MMA_BF16(acc[mf][nf], af[mf][0], af[mf][1], af[mf][2], af[mf][3], b0, b1);
            }
        }
        if (kt + 1 < nk) {
            int nb = cur ^ 1;
            As[nb][arow][akp+0] = ua.x; As[nb][arow][akp+1] = ua.y;
            As[nb][arow][akp+2] = ua.z; As[nb][arow][akp+3] = ua.w;
            Bs[nb][arow][akp+0] = ub.x; Bs[nb][arow][akp+1] = ub.y;
            Bs[nb][arow][akp+2] = ub.z; Bs[nb][arow][akp+3] = ub.w;
        }
    }

    #pragma unroll
    for (int mf = 0; mf < 2; mf++) {
        int r_lo = row0 + warp_m * 32 + mf * 16 + grp;
        int r_hi = r_lo + 8;
        #pragma unroll
        for (int nf = 0; nf < 8; nf++) {
            int cl = warp_n * 64 + nf * 8 + tig * 2;
            float bv0 = bias[col0 + cl], bv1 = bias[col0 + cl + 1];
            float v0 = acc[mf][nf][0] + bv0, v1 = acc[mf][nf][1] + bv1;
            float v2 = acc[mf][nf][2] + bv0, v3 = acc[mf][nf][3] + bv1;
            if (relu) { v0 = fmaxf(v0, 0.f); v1 = fmaxf(v1, 0.f);
                        v2 = fmaxf(v2, 0.f); v3 = fmaxf(v3, 0.f); }
            if (!obf) {
                *(float2*)&outf[(size_t)r_lo * nstride + col0 + cl] = make_float2(v0, v1);
                *(float2*)&outf[(size_t)r_hi * nstride + col0 + cl] = make_float2(v2, v3);
            } else {
                *(uint32_t*)&outb[(size_t)r_lo * nstride + col0 + cl] = packbf2(v0, v1);
                *(uint32_t*)&outb[(size_t)r_hi * nstride + col0 + cl] = packbf2(v2, v3);
            }
        }
    }
}

// ======== K-split BF16 GEMM: z selects K half; writes fp32 partials ========
__global__ __launch_bounds__(256) void gemm_bb_ks_kernel(
    const __nv_bfloat16* __restrict__ A, const __nv_bfloat16* __restrict__ Wt, int K)
{
    __shared__ uint32_t As[2][128][9];
    __shared__ uint32_t Bs[2][128][9];
    int tid = threadIdx.x;
    int lane = tid & 31;
    int warp = tid >> 5;
    int warp_m = warp & 3;
    int warp_n = warp >> 2;
    int grp = lane >> 2;
    int tig = lane & 3;

    int row0 = blockIdx.y * 128, col0 = blockIdx.x * 128;
    int koff = blockIdx.z * (K >> 1);
    const __nv_bfloat16* Ab = A + (size_t)row0 * K + koff;
    const __nv_bfloat16* Wb = Wt + (size_t)col0 * K + koff;
    float* outp = g_part + (size_t)blockIdx.z * BT * CC;

    const int arow = tid >> 1, akoff = (tid & 1) * 8, akp = (tid & 1) * 4;

    float acc[2][8][4];
    #pragma unroll
    for (int i = 0; i < 2; i++)
        #pragma unroll
        for (int j = 0; j < 8; j++)
            #pragma unroll
            for (int c = 0; c < 4; c++) acc[i][j][c] = 0.0f;

    uint4 ua, ub;
    ua = *(const uint4*)&Ab[(size_t)arow * K + akoff];
    ub = *(const uint4*)&Wb[(size_t)arow * K + akoff];
    As[0][arow][akp+0] = ua.x; As[0][arow][akp+1] = ua.y;
    As[0][arow][akp+2] = ua.z; As[0][arow][akp+3] = ua.w;
    Bs[0][arow][akp+0] = ub.x; Bs[0][arow][akp+1] = ub.y;
    Bs[0][arow][akp+2] = ub.z; Bs[0][arow][akp+3] = ub.w;

    int nk = K >> 5;
    for (int kt = 0; kt < nk; kt++) {
        __syncthreads();
        int cur = kt & 1;
        if (kt + 1 < nk) {
            int k0 = (kt + 1) << 4;
            ua = *(const uint4*)&Ab[(size_t)arow * K + k0 + akoff];
            ub = *(const uint4*)&Wb[(size_t)arow * K + k0 + akoff];
        }
        {
            uint32_t af[2][4];
            #pragma unroll
            for (int mf = 0; mf < 2; mf++) {
                int m = warp_m * 32 + mf * 16 + grp;
                af[mf][0] = As[cur][m][tig];
                af[mf][1] = As[cur][m + 8][tig];
                af[mf][2] = As[cur][m][tig + 4];
                af[mf][3] = As[cur][m + 8][tig + 4];
            }
            #pragma unroll
            for (int nf = 0; nf < 8; nf++) {
                int n = warp_n * 64 + nf * 8 + grp;
                uint32_t b0 = Bs[cur][n][tig];
                uint32_t b1 = Bs[cur][n][tig + 4];
                #pragma unroll
                for (int mf = 0; mf < 2; mf++)
                    MMA_BF16(acc[mf][nf], af[mf][0], af[mf][1], af[mf][2], af[mf][3], b0, b1);
            }
        }
        if (kt + 1 < nk) {
            int nb = cur ^ 1;
            As[nb][arow][akp+0] = ua.x; As[nb][arow][akp+1] = ua.y;
            As[nb][arow][akp+2] = ua.z; As[nb][arow][akp+3] = ua.w;
            Bs[nb][arow][akp+0] = ub.x; Bs[nb][arow][akp+1] = ub.y;
            Bs[nb][arow][akp+2] = ub.z; Bs[nb][arow][akp+3] = ub.w;
        }
    }

    #pragma unroll
    for (int mf = 0; mf < 2; mf++) {
        int r_lo = row0 + warp_m * 32 + mf * 16 + grp;
        int r_hi = r_lo + 8;
        #pragma unroll
        for (int nf = 0; nf < 8; nf++) {
            int cl = col0 + warp_n * 64 + nf * 8 + tig * 2;
            *(float2*)&outp[(size_t)r_lo * CC + cl] = make_float2(acc[mf][nf][0], acc[mf][nf][1]);
            *(float2*)&outp[(size_t)r_hi * CC + cl] = make_float2(acc[mf][nf][2], acc[mf][nf][3]);
        }
    }
}

// ======== combine K-split partials (V path only) ========
__global__ void ks_combine_kernel(const float* __restrict__ bias,
                                  float* __restrict__ outf, int nstride)
{
    int i = blockIdx.x * 256 + threadIdx.x;
    int row = i >> 9, c = i & 511;
    float v = g_part[i] + g_part[(size_t)BT * CC + i] + bias[c];
    outf[(size_t)row * nstride + c] = v;
}

// ======== exact fp32 SIMT GEMM (seg-critical stage0/l0 Q,K) ========
__global__ __launch_bounds__(256) void gemm_kernel(
    const float* __restrict__ A, const float* __restrict__ W,
    const float* __restrict__ bias, float* __restrict__ Cout,
    int M, int Ntot, int K, int relu, int sub_n)
{
    __shared__ float As[2][16][128];
    __shared__ float Bs[2][16][128];
    int tid = threadIdx.x;
    int tx = tid & 15, ty = tid >> 4;
    int row0 = blockIdx.y * 128, col0 = blockIdx.x * 128;
    int mat = col0 / sub_n;
    int coln = col0 % sub_n;
    const float* Wb = W + (size_t)mat * K * sub_n + coln;
    const float* Ab = A + (size_t)row0 * K;

    const int arow = tid >> 1, akoff = (tid & 1) * 8;
    const int bk = tid >> 4, bcol = (tid & 15) * 8;

    float acc[8][8] = {};
    float4 ra0, ra1, rb0, rb1;

    ra0 = *(const float4*)&Ab[(size_t)arow * K + akoff];
    ra1 = *(const float4*)&Ab[(size_t)arow * K + akoff + 4];
    rb0 = *(const float4*)&Wb[(size_t)bk * sub_n + bcol];
    rb1 = *(const float4*)&Wb[(size_t)bk * sub_n + bcol + 4];
    As[0][akoff+0][arow]=ra0.x; As[0][akoff+1][arow]=ra0.y;
    As[0][akoff+2][arow]=ra0.z; As[0][akoff+3][arow]=ra0.w;
    As[0][akoff+4][arow]=ra1.x; As[0][akoff+5][arow]=ra1.y;
    As[0][akoff+6][arow]=ra1.z; As[0][akoff+7][arow]=ra1.w;
    *(float4*)&Bs[0][bk][bcol]   = rb0;
    *(float4*)&Bs[0][bk][bcol+4] = rb1;
    __syncthreads();

    int nk = K >> 4;
    for (int kt = 0; kt < nk; kt++) {
        int buf = kt & 1;
        if (kt + 1 < nk) {
            int k0 = (kt + 1) << 4;
            ra0 = *(const float4*)&Ab[(size_t)arow * K + k0 + akoff];
            ra1 = *(const float4*)&Ab[(size_t)arow * K + k0 + akoff + 4];
            rb0 = *(const float4*)&Wb[(size_t)(k0 + bk) * sub_n + bcol];
            rb1 = *(const float4*)&Wb[(size_t)(k0 + bk) * sub_n + bcol + 4];
        }
        #pragma unroll
        for (int kk = 0; kk < 16; kk++) {
            float a[8], b[8];
            *(float4*)(a)   = *(const float4*)&As[buf][kk][ty*8];
            *(float4*)(a+4) = *(const float4*)&As[buf][kk][ty*8+4];
            *(float4*)(b)   = *(const float4*)&Bs[buf][kk][tx*8];
            *(float4*)(b+4) = *(const float4*)&Bs[buf][kk][tx*8+4];
            #pragma unroll
            for (int i = 0; i < 8; i++)
                #pragma unroll
                for (int j = 0; j < 8; j++)
                    acc[i][j] += a[i] * b[j];
        }
        if (kt + 1 < nk) {
            int nb2 = buf ^ 1;
            As[nb2][akoff+0][arow]=ra0.x; As[nb2][akoff+1][arow]=ra0.y;
            As[nb2][akoff+2][arow]=ra0.z; As[nb2][akoff+3][arow]=ra0.w;
            As[nb2][akoff+4][arow]=ra1.x; As[nb2][akoff+5][arow]=ra1.y;
            As[nb2][akoff+6][arow]=ra1.z; As[nb2][akoff+7][arow]=ra1.w;
            *(float4*)&Bs[nb2][bk][bcol]   = rb0;
            *(float4*)&Bs[nb2][bk][bcol+4] = rb1;
        }
        __syncthreads();
    }

    const float* bb = bias + (size_t)mat * sub_n + coln;
    float bv[8];
    #pragma unroll
    for (int j = 0; j < 8; j++) bv[j] = bb[tx*8 + j];
    #pragma unroll
    for (int i = 0; i < 8; i++) {
        size_t r = (size_t)(row0 + ty*8 + i);
        float o[8];
        #pragma unroll
        for (int j = 0; j < 8; j++) {
            float v = acc[i][j] + bv[j];
            o[j] = relu ? fmaxf(v, 0.0f) : v;
        }
        *(float4*)&Cout[r * Ntot + col0 + tx*8]     = *(float4*)(o);
        *(float4*)&Cout[r * Ntot + col0 + tx*8 + 4] = *(float4*)(o+4);
    }
}

// ======== exact fp32 scores (stage0/l0 only) ========
__global__ __launch_bounds__(256) void scores_kernel(int use_mask)
{
    int bh = blockIdx.z;
    int b = bh >> 3, h = bh & 7;
    int t0 = blockIdx.y * 128, s0 = blockIdx.x * 128;
    __shared__ float Qs[2][16][128];
    __shared__ float Ks[2][16][128];
    int tid = threadIdx.x;
    int tx = tid & 15, ty = tid >> 4;

    const int arow = tid >> 1, akoff = (tid & 1) * 8;
    const float* qb = g_qkv + (size_t)(b*TT + t0) * QKVN + h*64;
    const float* kb = g_qkv + (size_t)(b*TT + s0) * QKVN + CC + h*64;

    float acc[8][8] = {};
    float4 ra0, ra1, rb0, rb1;

    ra0 = *(const float4*)&qb[(size_t)arow * QKVN + akoff];
    ra1 = *(const float4*)&qb[(size_t)arow * QKVN + akoff + 4];
    rb0 = *(const float4*)&kb[(size_t)arow * QKVN + akoff];
    rb1 = *(const float4*)&kb[(size_t)arow * QKVN + akoff + 4];
    Qs[0][akoff+0][arow]=ra0.x; Qs[0][akoff+1][arow]=ra0.y;
    Qs[0][akoff+2][arow]=ra0.z; Qs[0][akoff+3][arow]=ra0.w;
    Qs[0][akoff+4][arow]=ra1.x; Qs[0][akoff+5][arow]=ra1.y;
    Qs[0][akoff+6][arow]=ra1.z; Qs[0][akoff+7][arow]=ra1.w;
    Ks[0][akoff+0][arow]=rb0.x; Ks[0][akoff+1][arow]=rb0.y;
    Ks[0][akoff+2][arow]=rb0.z; Ks[0][akoff+3][arow]=rb0.w;
    Ks[0][akoff+4][arow]=rb1.x; Ks[0][akoff+5][arow]=rb1.y;
    Ks[0][akoff+6][arow]=rb1.z; Ks[0][akoff+7][arow]=rb1.w;
    __syncthreads();

    #pragma unroll
    for (int kt = 0; kt < 4; kt++) {
        int buf = kt & 1;
        if (kt + 1 < 4) {
            int k0 = (kt + 1) << 4;
            ra0 = *(const float4*)&qb[(size_t)arow * QKVN + k0 + akoff];
            ra1 = *(const float4*)&qb[(size_t)arow * QKVN + k0 + akoff + 4];
            rb0 = *(const float4*)&kb[(size_t)arow * QKVN + k0 + akoff];
            rb1 = *(const float4*)&kb[(size_t)arow * QKVN + k0 + akoff + 4];
        }
        #pragma unroll
        for (int kk = 0; kk < 16; kk++) {
            float a[8], c[8];
            *(float4*)(a)   = *(const float4*)&Qs[buf][kk][ty*8];
            *(float4*)(a+4) = *(const float4*)&Qs[buf][kk][ty*8+4];
            *(float4*)(c)   = *(const float4*)&Ks[buf][kk][tx*8];
            *(float4*)(c+4) = *(const float4*)&Ks[buf][kk][tx*8+4];
            #pragma unroll
            for (int i = 0; i < 8; i++)
                #pragma unroll
                for (int j = 0; j < 8; j++)
                    acc[i][j] += a[i] * c[j];
        }
        if (kt + 1 < 4) {
            int nb2 = buf ^ 1;
            Qs[nb2][akoff+0][arow]=ra0.x; Qs[nb2][akoff+1][arow]=ra0.y;
            Qs[nb2][akoff+2][arow]=ra0.z; Qs[nb2][akoff+3][arow]=ra0.w;
            Qs[nb2][akoff+4][arow]=ra1.x; Qs[nb2][akoff+5][arow]=ra1.y;
            Qs[nb2][akoff+6][arow]=ra1.z; Qs[nb2][akoff+7][arow]=ra1.w;
            Ks[nb2][akoff+0][arow]=rb0.x; Ks[nb2][akoff+1][arow]=rb0.y;
            Ks[nb2][akoff+2][arow]=rb0.z; Ks[nb2][akoff+3][arow]=rb0.w;
            Ks[nb2][akoff+4][arow]=rb1.x; Ks[nb2][akoff+5][arow]=rb1.y;
            Ks[nb2][akoff+6][arow]=rb1.z; Ks[nb2][akoff+7][arow]=rb1.w;
        }
        __syncthreads();
    }

    float* dst = g_s + (size_t)bh * TT * TT;
    int segt[8], segs[8];
    if (use_mask) {
        #pragma unroll
        for (int i = 0; i < 8; i++) segt[i] = g_seg[b*TT + t0 + ty*8 + i];
        #pragma unroll
        for (int j = 0; j < 8; j++) segs[j] = g_seg[b*TT + s0 + tx*8 + j];
    }
    #pragma unroll
    for (int i = 0; i < 8; i++) {
        size_t t = (size_t)(t0 + ty*8 + i);
        float o[8];
        #pragma unroll
        for (int j = 0; j < 8; j++) {
            float v = acc[i][j] * 0.125f;
            if (use_mask && segt[i] != segs[j]) v += NEGI;
            o[j] = v;
        }
        *(float4*)&dst[t * TT + s0 + tx*8]     = *(float4*)(o);
        *(float4*)&dst[t * TT + s0 + tx*8 + 4] = *(float4*)(o+4);
    }
}

// ======== BF16 scores: bf16 in (g_qkvb), bf16 out (g_sb) ========
__global__ __launch_bounds__(256) void scores_bf16_kernel(int use_mask)
{
    int bh = blockIdx.z;
    int b = bh >> 3, h = bh & 7;
    int t0 = blockIdx.y * 128, s0 = blockIdx.x * 128;
    __shared__ uint32_t Qs[2][128][9];
    __shared__ uint32_t Ks[2][128][9];
    int tid = threadIdx.x;
    int lane = tid & 31;
    int warp = tid >> 5;
    int warp_m = warp & 3;
    int warp_n = warp >> 2;
    int grp = lane >> 2;
    int tig = lane & 3;

    const int arow = tid >> 1, akoff = (tid & 1) * 8, akp = (tid & 1) * 4;
    const __nv_bfloat16* qb = g_qkvb + (size_t)(b*TT + t0) * QKVN + h*64;
    const __nv_bfloat16* kb = g_qkvb + (size_t)(b*TT + s0) * QKVN + CC + h*64;

    float acc[2][8][4];
    #pragma unroll
    for (int i = 0; i < 2; i++)
        #pragma unroll
        for (int j = 0; j < 8; j++)
            #pragma unroll
            for (int c = 0; c < 4; c++) acc[i][j][c] = 0.0f;

    uint4 uq, uk;
    uq = *(const uint4*)&qb[(size_t)arow * QKVN + akoff];
    uk = *(const uint4*)&kb[(size_t)arow * QKVN + akoff];
    Qs[0][arow][akp+0] = uq.x; Qs[0][arow][akp+1] = uq.y;
    Qs[0][arow][akp+2] = uq.z; Qs[0][arow][akp+3] = uq.w;
    Ks[0][arow][akp+0] = uk.x; Ks[0][arow][akp+1] = uk.y;
    Ks[0][arow][akp+2] = uk.z; Ks[0][arow][akp+3] = uk.w;

    #pragma unroll
    for (int kt = 0; kt < 4; kt++) {
        __syncthreads();
        int cur = kt & 1;
        if (kt + 1 < 4) {
            int k0 = (kt + 1) << 4;
            uq = *(const uint4*)&qb[(size_t)arow * QKVN + k0 + akoff];
            uk = *(const uint4*)&kb[(size_t)arow * QKVN + k0 + akoff];
        }
        {
            uint32_t af[2][4];
            #pragma unroll
            for (int mf = 0; mf < 2; mf++) {
                int m = warp_m * 32 + mf * 16 + grp;
                af[mf][0] = Qs[cur][m][tig];
                af[mf][1] = Qs[cur][m + 8][tig];
                af[mf][2] = Qs[cur][m][tig + 4];
                af[mf][3] = Qs[cur][m + 8][tig + 4];
            }
            #pragma unroll
            for (int nf = 0; nf < 8; nf++) {
                int n = warp_n * 64 + nf * 8 + grp;
                uint32_t b0 = Ks[cur][n][tig];
                uint32_t b1 = Ks[cur][n][tig + 4];
                #pragma unroll
                for (int mf = 0; mf < 2; mf++)
                    MMA_BF16(acc[mf][nf], af[mf][0], af[mf][1], af[mf][2], af[mf][3], b0, b1);
            }
        }
        if (kt + 1 < 4) {
            int nb2 = cur ^ 1;
            Qs[nb2][arow][akp+0] = uq.x; Qs[nb2][arow][akp+1] = uq.y;
            Qs[nb2][arow][akp+2] = uq.z; Qs[nb2][arow][akp+3] = uq.w;
            Ks[nb2][arow][akp+0] = uk.x; Ks[nb2][arow][akp+1] = uk.y;
            Ks[nb2][arow][akp+2] = uk.z; Ks[nb2][arow][akp+3] = uk.w;
        }
    }

    __nv_bfloat16* dst = g_sb + (size_t)bh * TT * TT;
    #pragma unroll
    for (int mf = 0; mf < 2; mf++) {
        int r_lo = warp_m * 32 + mf * 16 + grp;
        int r_hi = r_lo + 8;
        int sg_lo = 0, sg_hi = 0;
        if (use_mask) {
            sg_lo = g_seg[b*TT + t0 + r_lo];
            sg_hi = g_seg[b*TT + t0 + r_hi];
        }
        #pragma unroll
        for (int nf = 0; nf < 8; nf++) {
            int cl = warp_n * 64 + nf * 8 + tig * 2;
            float v0 = acc[mf][nf][0] * 0.125f, v1 = acc[mf][nf][1] * 0.125f;
            float v2 = acc[mf][nf][2] * 0.125f, v3 = acc[mf][nf][3] * 0.125f;
            if (use_mask) {
                int s_a = g_seg[b*TT + s0 + cl];
                int s_b = g_seg[b*TT + s0 + cl + 1];
                if (sg_lo != s_a) v0 += NEGI;
                if (sg_lo != s_b) v1 += NEGI;
                if (sg_hi != s_a) v2 += NEGI;
                if (sg_hi != s_b) v3 += NEGI;
            }
            *(uint32_t*)&dst[(size_t)(t0 + r_lo) * TT + s0 + cl] = packbf2(v0, v1);
            *(uint32_t*)&dst[(size_t)(t0 + r_hi) * TT + s0 + cl] = packbf2(v2, v3);
        }
    }
}

// ======== TF32 PV (stage0/l0 only): fp32 S @ fp32 V -> bf16 g_ab ========
__global__ __launch_bounds__(256) void pv_tf32_kernel()
{
    int bh = blockIdx.y;
    int b = bh >> 3, h = bh & 7;
    int t0 = blockIdx.x * 128;
    __shared__ float Ps[16][136];
    __shared__ float Vs[16][72];
    int tid = threadIdx.x;
    int lane = tid & 31;
    int warp = tid >> 5;
    int warp_m = warp & 3;
    int warp_n = warp >> 2;
    int grp = lane >> 2;
    int tig = lane & 3;

    const int arow = tid >> 1, akoff = (tid & 1) * 8;
    const int vk = tid >> 4, vcol = (tid & 15) * 4;

    const float* srow = g_s + (size_t)bh * TT * TT + (size_t)t0 * TT;
    const float* vb = g_qkv + (size_t)(b*TT) * QKVN + 2*CC + h*64;

    float acc[2][4][4];
    #pragma unroll
    for (int i = 0; i < 2; i++)
        #pragma unroll
        for (int j = 0; j < 4; j++)
            #pragma unroll
            for (int c = 0; c < 4; c++) acc[i][j][c] = 0.0f;

    float4 ra0, ra1, rv0;
    ra0 = *(const float4*)&srow[(size_t)arow * TT + akoff];
    ra1 = *(const float4*)&srow[(size_t)arow * TT + akoff + 4];
    rv0 = *(const float4*)&vb[(size_t)vk * QKVN + vcol];

    const int nk = TT / 16;
    for (int kt = 0; kt < nk; kt++) {
        Ps[akoff+0][arow] = f2tf32(ra0.x); Ps[akoff+1][arow] = f2tf32(ra0.y);
        Ps[akoff+2][arow] = f2tf32(ra0.z); Ps[akoff+3][arow] = f2tf32(ra0.w);
        Ps[akoff+4][arow] = f2tf32(ra1.x); Ps[akoff+5][arow] = f2tf32(ra1.y);
        Ps[akoff+6][arow] = f2tf32(ra1.z); Ps[akoff+7][arow] = f2tf32(ra1.w);
        Vs[vk][vcol+0] = f2tf32(rv0.x); Vs[vk][vcol+1] = f2tf32(rv0.y);
        Vs[vk][vcol+2] = f2tf32(rv0.z); Vs[vk][vcol+3] = f2tf32(rv0.w);
        __syncthreads();

        if (kt + 1 < nk) {
            int k0 = (kt + 1) << 4;
            ra0 = *(const float4*)&srow[(size_t)arow * TT + k0 + akoff];
            ra1 = *(const float4*)&srow[(size_t)arow * TT + k0 + akoff + 4];
            rv0 = *(const float4*)&vb[(size_t)(k0 + vk) * QKVN + vcol];
        }

        #pragma unroll
        for (int ks = 0; ks < 2; ks++) {
            int kb2 = ks * 8;
            uint32_t af[2][4];
            #pragma unroll
            for (int mf = 0; mf < 2; mf++) {
                int m = warp_m * 32 + mf * 16 + grp;
                af[mf][0] = __float_as_uint(Ps[kb2 + tig][m]);
                af[mf][1] = __float_as_uint(Ps[kb2 + tig][m + 8]);
                af[mf][2] = __float_as_uint(Ps[kb2 + tig + 4][m]);
                af[mf][3] = __float_as_uint(Ps[kb2 + tig + 4][m + 8]);
            }
            #pragma unroll
            for (int nf = 0; nf < 4; nf++) {
                int n = warp_n * 32 + nf * 8 + grp;
                uint32_t b0 = __float_as_uint(Vs[kb2 + tig][n]);
                uint32_t b1 = __float_as_uint(Vs[kb2 + tig + 4][n]);
                #pragma unroll
                for (int mf = 0; mf < 2; mf++)
                    MMA_TF32(acc[mf][nf], af[mf][0], af[mf][1], af[mf][2], af[mf][3], b0, b1);
            }
        }
        __syncthreads();
    }

    #pragma unroll
    for (int mf = 0; mf < 2; mf++) {
        int r_lo = warp_m * 32 + mf * 16 + grp;
        int r_hi = r_lo + 8;
        #pragma unroll
        for (int nf = 0; nf < 4; nf++) {
            int cl = warp_n * 32 + nf * 8 + tig * 2;
            *(uint32_t*)&g_ab[(size_t)(b*TT + t0 + r_lo) * CC + h*64 + cl] =
                packbf2(acc[mf][nf][0], acc[mf][nf][1]);
            *(uint32_t*)&g_ab[(size_t)(b*TT + t0 + r_hi) * CC + h*64 + cl] =
                packbf2(acc[mf][nf][2], acc[mf][nf][3]);
        }
    }
}

// ======== FUSED softmax + PV, bf16 S + bf16 V -> bf16 g_ab (fast exp) ========
__global__ __launch_bounds__(256) void fused_softmax_pv_kernel(int docolsum)
{
    int bh = blockIdx.y;
    int b = bh >> 3, h = bh & 7;
    int t0 = blockIdx.x * 128;
    const __nv_bfloat16* srow = g_sb + (size_t)bh * TT * TT + (size_t)t0 * TT;
    const __nv_bfloat16* vb = g_qkvb + (size_t)(b*TT) * QKVN + 2*CC + h*64;

    __shared__ float rowm[128];
    __shared__ float rowstat[128];
    __shared__ float Ps[16][136];
    __shared__ float Vs[16][72];
    __shared__ float colpart[16][8];

    int tid = threadIdx.x;
    int lane = tid & 31;
    int warp = tid >> 5;
    int warp_m = warp & 3;
    int warp_n = warp >> 2;
    int grp = lane >> 2;
    int tig = lane & 3;

    for (int r = warp * 16; r < warp * 16 + 16; r++) {
        const __nv_bfloat16* p = srow + (size_t)r * TT;
        float m = -3.4e38f, l = 0.0f;
        #pragma unroll
        for (int i = 0; i < 4; i++) {
            uint4 u = *(const uint4*)&p[lane * 8 + i * 256];
            float2 a0 = bf2f(u.x), a1 = bf2f(u.y), a2 = bf2f(u.z), a3 = bf2f(u.w);
            float mx = fmaxf(fmaxf(fmaxf(a0.x, a0.y), fmaxf(a1.x, a1.y)),
                             fmaxf(fmaxf(a2.x, a2.y), fmaxf(a3.x, a3.y)));
            if (docolsum) {
                float mn = fmaxf(m, mx);
                l = l * __expf(m - mn)
                  + __expf(a0.x - mn) + __expf(a0.y - mn) + __expf(a1.x - mn) + __expf(a1.y - mn)
                  + __expf(a2.x - mn) + __expf(a2.y - mn) + __expf(a3.x - mn) + __expf(a3.y - mn);
                m = mn;
            } else {
                m = fmaxf(m, mx);
            }
        }
        #pragma unroll
        for (int o = 16; o > 0; o >>= 1) {
            float m2 = __shfl_xor_sync(0xffffffffu, m, o);
            if (docolsum) {
                float l2 = __shfl_xor_sync(0xffffffffu, l, o);
                float mn = fmaxf(m, m2);
                l = l * __expf(m - mn) + l2 * __expf(m2 - mn);
                m = mn;
            } else {
                m = fmaxf(m, m2);
            }
        }
        if (lane == 0) { rowm[r] = m; rowstat[r] = l; }
    }
    __syncthreads();

    const int arow = tid >> 1, akoff = (tid & 1) * 8;
    const int vk = tid >> 4, vcol = (tid & 15) * 4;
    float minv = rowm[arow];
    float rl = docolsum ? (1.0f / rowstat[arow]) : 1.0f;
    float lpart = 0.0f;

    float acc[2][4][4];
    #pragma unroll
    for (int i = 0; i < 2; i++)
        #pragma unroll
        for (int j = 0; j < 4; j++)
            #pragma unroll
            for (int c = 0; c < 4; c++) acc[i][j][c] = 0.0f;

    float* wpdst = 0;
    if (docolsum)
        wpdst = g_wp + ((size_t)bh * 8 + blockIdx.x) * TT;

    const int nk = TT / 16;
    for (int kt = 0; kt < nk; kt++) {
        uint4 u = *(const uint4*)&srow[(size_t)arow * TT + kt*16 + akoff];
        float2 a0 = bf2f(u.x), a1 = bf2f(u.y), a2 = bf2f(u.z), a3 = bf2f(u.w);
        float pv_[8];
        pv_[0] = __expf(a0.x - minv) * rl; pv_[1] = __expf(a0.y - minv) * rl;
        pv_[2] = __expf(a1.x - minv) * rl; pv_[3] = __expf(a1.y - minv) * rl;
        pv_[4] = __expf(a2.x - minv) * rl; pv_[5] = __expf(a2.y - minv) * rl;
        pv_[6] = __expf(a3.x - minv) * rl; pv_[7] = __expf(a3.y - minv) * rl;
        if (!docolsum) {
            #pragma unroll
            for (int j = 0; j < 8; j++) lpart += pv_[j];
        }
        #pragma unroll
        for (int j = 0; j < 8; j++) Ps[akoff + j][arow] = f2tf32(pv_[j]);

        uint2 uv = *(const uint2*)&vb[(size_t)(kt*16 + vk) * QKVN + vcol];
        float2 v0 = bf2f(uv.x), v1 = bf2f(uv.y);
        Vs[vk][vcol+0] = f2tf32(v0.x); Vs[vk][vcol+1] = f2tf32(v0.y);
        Vs[vk][vcol+2] = f2tf32(v1.x); Vs[vk][vcol+3] = f2tf32(v1.y);
        __syncthreads();

        if (docolsum) {
            if (tid < 128) {
                int c = tid >> 3, rseg = tid & 7;
                float cs = 0.0f;
                #pragma unroll
                for (int j = 0; j < 16; j++) cs += Ps[c][rseg * 16 + j];
                colpart[c][rseg] = cs;
            }
            __syncthreads();
            if (tid < 16) {
                float cs = 0.0f;
                #pragma unroll
                for (int j = 0; j < 8; j++) cs += colpart[tid][j];
                wpdst[kt * 16 + tid] = cs;
            }
        }

        #pragma unroll
        for (int ks = 0; ks < 2; ks++) {
            int kb2 = ks * 8;
            uint32_t af[2][4];
            #pragma unroll
            for (int mf = 0; mf < 2; mf++) {
                int m = warp_m * 32 + mf * 16 + grp;
                af[mf][0] = __float_as_uint(Ps[kb2 + tig][m]);
                af[mf][1] = __float_as_uint(Ps[kb2 + tig][m + 8]);
                af[mf][2] = __float_as_uint(Ps[kb2 + tig + 4][m]);
                af[mf][3] = __float_as_uint(Ps[kb2 + tig + 4][m + 8]);
            }
            #pragma unroll
            for (int nf = 0; nf < 4; nf++) {
                int n = warp_n * 32 + nf * 8 + grp;
                uint32_t b0 = __float_as_uint(Vs[kb2 + tig][n]);
                uint32_t b1 = __float_as_uint(Vs[kb2 + tig + 4][n]);
                #pragma unroll
                for (int mf = 0; mf < 2; mf++)
                    MMA_TF32(acc[mf][nf], af[mf][0], af[mf][1], af[mf][2], af[mf][3], b0, b1);
            }
        }
        __syncthreads();
    }

    if (!docolsum) {
        lpart += __shfl_xor_sync(0xffffffffu, lpart, 1);
        if ((tid & 1) == 0) rowstat[arow] = lpart;
        __syncthreads();
    }

    #pragma unroll
    for (int mf = 0; mf < 2; mf++) {
        int r_lo = warp_m * 32 + mf * 16 + grp;
        int r_hi = r_lo + 8;
        float inv_lo = docolsum ? 1.0f : (1.0f / rowstat[r_lo]);
        float inv_hi = docolsum ? 1.0f : (1.0f / rowstat[r_hi]);
        #pragma unroll
        for (int nf = 0; nf < 4; nf++) {
            int cl = warp_n * 32 + nf * 8 + tig * 2;
            *(uint32_t*)&g_ab[(size_t)(b*TT + t0 + r_lo) * CC + h*64 + cl] =
                packbf2(acc[mf][nf][0] * inv_lo, acc[mf][nf][1] * inv_lo);
            *(uint32_t*)&g_ab[(size_t)(b*TT + t0 + r_hi) * CC + h*64 + cl] =
                packbf2(acc[mf][nf][2] * inv_hi, acc[mf][nf][3] * inv_hi);
        }
    }
}

// ---------------- reduce colsum partials ----------------
__global__ void wreduce_kernel()
{
    int idx = blockIdx.x * 256 + threadIdx.x;
    int b = idx / TT, s = idx % TT;
    float acc = 0.0f;
    #pragma unroll 8
    for (int j = 0; j < HH * 8; j++)
        acc += g_wp[((size_t)(b * HH * 8 + j)) * TT + s];
    g_w[idx] = acc * (1.0f / HH);
}

// ---------------- row softmax (stage0/l0): shuffle reductions, expf kept ------
__global__ void softmax_rows_kernel(float* __restrict__ S)
{
    float* p = S + (size_t)blockIdx.x * TT;
    int tid = threadIdx.x;
    int lane = tid & 31, wid = tid >> 5;
    __shared__ float wredm[8];
    __shared__ float wreds[8];
    float v[4];
    float m = -3.4e38f;
    #pragma unroll
    for (int i = 0; i < 4; i++) { v[i] = p[tid + i * 256]; m = fmaxf(m, v[i]); }
    #pragma unroll
    for (int o = 16; o > 0; o >>= 1)
        m = fmaxf(m, __shfl_xor_sync(0xffffffffu, m, o));
    if (lane == 0) wredm[wid] = m;
    __syncthreads();
    float mx = wredm[0];
    #pragma unroll
    for (int j = 1; j < 8; j++) mx = fmaxf(mx, wredm[j]);
    float sum = 0.0f;
    #pragma unroll
    for (int i = 0; i < 4; i++) { v[i] = expf(v[i] - mx); sum += v[i]; }
    #pragma unroll
    for (int o = 16; o > 0; o >>= 1)
        sum += __shfl_xor_sync(0xffffffffu, sum, o);
    if (lane == 0) wreds[wid] = sum;
    __syncthreads();
    float tot = wreds[0];
    #pragma unroll
    for (int j = 1; j < 8; j++) tot += wreds[j];
    float inv = 1.0f / tot;
    #pragma unroll
    for (int i = 0; i < 4; i++) p[tid + i * 256] = v[i] * inv;
}

// ---------------- head-averaged probs (stage0/l0 only) ----------------
__global__ void head_avg_kernel()
{
    size_t idx = (size_t)blockIdx.x * 256 + threadIdx.x;
    size_t b = idx / ((size_t)TT * TT / 4);
    size_t r = idx % ((size_t)TT * TT / 4);
    float4 sum = make_float4(0.f, 0.f, 0.f, 0.f);
    #pragma unroll
    for (int h = 0; h < HH; h++) {
        float4 x = *((const float4*)(g_s + (b * HH + h) * (size_t)TT * TT) + r);
        sum.x += x.x; sum.y += x.y; sum.z += x.z; sum.w += x.w;
    }
    sum.x *= (1.0f/HH); sum.y *= (1.0f/HH); sum.z *= (1.0f/HH); sum.w *= (1.0f/HH);
    *((float4*)(g_p0 + b * (size_t)TT * TT) + r) = sum;
}

// ---------------- out = LN(res + add), shuffle reductions ----------------
__global__ void ln_residual_kernel(const float* __restrict__ res, const float* __restrict__ add,
                                   float* __restrict__ out, __nv_bfloat16* __restrict__ outb,
                                   const float* __restrict__ gamma, const float* __restrict__ beta)
{
    int row = blockIdx.x, tid = threadIdx.x;
    int lane = tid & 31, wid = tid >> 5;
    __shared__ float wred1[8];
    __shared__ float wred2[8];
    const float* r = res + (size_t)row * CC;
    const float* a = add + (size_t)row * CC;
    float v0 = r[tid] + a[tid];
    float v1 = r[tid + 256] + a[tid + 256];
    float s = v0 + v1;
    #pragma unroll
    for (int o = 16; o > 0; o >>= 1) s += __shfl_xor_sync(0xffffffffu, s, o);
    if (lane == 0) wred1[wid] = s;
    __syncthreads();
    float tot = wred1[0];
    #pragma unroll
    for (int j = 1; j < 8; j++) tot += wred1[j];
    float mu = tot * (1.0f / CC);
    float d0 = v0 - mu, d1 = v1 - mu;
    float q = d0 * d0 + d1 * d1;
    #pragma unroll
    for (int o = 16; o > 0; o >>= 1) q += __shfl_xor_sync(0xffffffffu, q, o);
    if (lane == 0) wred2[wid] = q;
    __syncthreads();
    float qt = wred2[0];
    #pragma unroll
    for (int j = 1; j < 8; j++) qt += wred2[j];
    float rstd = rsqrtf(qt * (1.0f / CC) + 1e-5f);
    float o0 = d0 * rstd * gamma[tid] + beta[tid];
    float o1 = d1 * rstd * gamma[tid + 256] + beta[tid + 256];
    float* o = out + (size_t)row * CC;
    o[tid] = o0; o[tid + 256] = o1;
    __nv_bfloat16* ob = outb + (size_t)row * CC;
    ob[tid] = __float2bfloat16(o0);
    ob[tid + 256] = __float2bfloat16(o1);
}

// ---------------- LN with K-split partial combine fused in ----------------
// add[c] = part0[row*CC+c] + part1[row*CC+c] + bias[c]  (same as combine->LN)
__global__ void ln_residual_ks_kernel(const float* __restrict__ res,
                                      const float* __restrict__ bias,
                                      float* __restrict__ out, __nv_bfloat16* __restrict__ outb,
                                      const float* __restrict__ gamma, const float* __restrict__ beta)
{
    int row = blockIdx.x, tid = threadIdx.x;
    int lane = tid & 31, wid = tid >> 5;
    __shared__ float wred1[8];
    __shared__ float wred2[8];
    const float* r = res + (size_t)row * CC;
    const float* p0 = g_part + (size_t)row * CC;
    const float* p1 = g_part + (size_t)BT * CC + (size_t)row * CC;
    float a0 = p0[tid] + p1[tid] + bias[tid];
    float a1 = p0[tid + 256] + p1[tid + 256] + bias[tid + 256];
    float v0 = r[tid] + a0;
    float v1 = r[tid + 256] + a1;
    float s = v0 + v1;
    #pragma unroll
    for (int o = 16; o > 0; o >>= 1) s += __shfl_xor_sync(0xffffffffu, s, o);
    if (lane == 0) wred1[wid] = s;
    __syncthreads();
    float tot = wred1[0];
    #pragma unroll
    for (int j = 1; j < 8; j++) tot += wred1[j];
    float mu = tot * (1.0f / CC);
    float d0 = v0 - mu, d1 = v1 - mu;
    float q = d0 * d0 + d1 * d1;
    #pragma unroll
    for (int o = 16; o > 0; o >>= 1) q += __shfl_xor_sync(0xffffffffu, q, o);
    if (lane == 0) wred2[wid] = q;
    __syncthreads();
    float qt = wred2[0];
    #pragma unroll
    for (int j = 1; j < 8; j++) qt += wred2[j];
    float rstd = rsqrtf(qt * (1.0f / CC) + 1e-5f);
    float o0 = d0 * rstd * gamma[tid] + beta[tid];
    float o1 = d1 * rstd * gamma[tid + 256] + beta[tid + 256];
    float* o = out + (size_t)row * CC;
    o[tid] = o0; o[tid + 256] = o1;
    __nv_bfloat16* ob = outb + (size_t)row * CC;
    ob[tid] = __float2bfloat16(o0);
    ob[tid + 256] = __float2bfloat16(o1);
}

// ---------------- w[b,s] = sum_t p0[b,t,s] (stage0 only, order-preserving) ----
__global__ void colsum_kernel()
{
    int idx = blockIdx.x * 256 + threadIdx.x;
    int b = idx / TT, s = idx % TT;
    const float* base = g_p0 + (size_t)b * TT * TT + s;
    float acc = 0.0f;
    for (int t = 0; t < TT; t += 8) {
        float v[8];
        #pragma unroll
        for (int j = 0; j < 8; j++) v[j] = base[(size_t)(t + j) * TT];
        #pragma unroll
        for (int j = 0; j < 8; j++) acc += v[j];
    }
    g_w[idx] = acc;
}

// ---------------- segment scan ----------------
__global__ void segment_kernel()
{
    int b = blockIdx.x, tid = threadIdx.x;
    __shared__ float smin[256], smax[256];
    float lo = 3.4e38f, hi = -3.4e38f;
    for (int t = tid; t < TT; t += 256) {
        float v = g_w[b * TT + t];
        lo = fminf(lo, v); hi = fmaxf(hi, v);
    }
    smin[tid] = lo; smax[tid] = hi; __syncthreads();
    for (int s = 128; s > 0; s >>= 1) {
        if (tid < s) { smin[tid] = fminf(smin[tid], smin[tid + s]); smax[tid] = fmaxf(smax[tid], smax[tid + s]); }
        __syncthreads();
    }
    if (tid == 0) {
        float wmin = smin[0], wmax = smax[0];
        float denom = fmaxf(wmax - wmin, 1e-12f);
        bool prev = ((g_w[b * TT + 0] - wmin) / denom) >= 0.5f;
        int start = 0, segc = 0;
        g_seg[b * TT + 0] = 0;
        g_segstart[b * (TT + 1) + 0] = 0;
        for (int t = 1; t < TT; t++) {
            bool cur = ((g_w[b * TT + t] - wmin) / denom) >= 0.5f;
            if (cur != prev && (start + 1) != t) {
                start = t; segc++;
                g_segstart[b * (TT + 1) + segc] = t;
            }
            g_seg[b * TT + t] = segc;
            prev = cur;
        }
        g_nseg[b] = segc + 1;
        g_segstart[b * (TT + 1) + segc + 1] = TT;
    }
}

// ---------------- aw = softmax_s(w) ----------------
__global__ void batch_softmax_kernel()
{
    int b = blockIdx.x, tid = threadIdx.x;
    __shared__ float red[256];
    float v[4];
    float m = -3.4e38f;
    #pragma unroll
    for (int i = 0; i < 4; i++) { v[i] = g_w[b * TT + tid + i * 256]; m = fmaxf(m, v[i]); }
    red[tid] = m; __syncthreads();
    for (int s = 128; s > 0; s >>= 1) { if (tid < s) red[tid] = fmaxf(red[tid], red[tid + s]); __syncthreads(); }
    float mx = red[0];
    __syncthreads();
    float sum = 0.0f;
    #pragma unroll
    for (int i = 0; i < 4; i++) { v[i] = expf(v[i] - mx); sum += v[i]; }
    red[tid] = sum; __syncthreads();
    for (int s = 128; s > 0; s >>= 1) { if (tid < s) red[tid] += red[tid + s]; __syncthreads(); }
    float inv = 1.0f / red[0];
    #pragma unroll
    for (int i = 0; i < 4; i++) g_aw[b * TT + tid + i * 256] = v[i] * inv;
}

// ---------------- word tokens ----------------
__global__ void word_tokens_kernel(float* __restrict__ out)
{
    int b = blockIdx.y, i = blockIdx.x, tid = threadIdx.x;
    float* dst = out + ((size_t)b * 2 * TT + i) * CC;
    int ns = g_nseg[b];
    if (i >= ns) {
        for (int c = tid; c < CC; c += 256) dst[c] = 0.0f;
        return;
    }
    int t0 = g_segstart[b * (TT + 1) + i];
    int t1 = g_segstart[b * (TT + 1) + i + 1];
    for (int c = tid; c < CC; c += 256) {
        float acc = 0.0f;
        for (int t = t0; t < t1; t++)
            acc += g_x[((size_t)b * TT + t) * CC + c] * g_aw[b * TT + t];
        dst[c] = acc;
    }
}

__global__ void copyx_kernel(const float* __restrict__ xin, float* __restrict__ out)
{
    size_t idx = (size_t)blockIdx.x * 256 + threadIdx.x;
    size_t b = idx / ((size_t)TT * CC);
    size_t rem = idx % ((size_t)TT * CC);
    out[b * (size_t)2 * TT * CC + (size_t)TT * CC + rem] = xin[idx];
}

__global__ void wm_kernel(float* __restrict__ wmout)
{
    size_t idx = (size_t)blockIdx.x * 256 + threadIdx.x;
    size_t b = idx / ((size_t)TT * TT);
    int i = (int)((idx / TT) % TT);
    int t = (int)(idx % TT);
    wmout[idx] = (g_seg[b * TT + t] == i) ? 1.0f : 0.0f;
}

// ---------------- host orchestration ----------------
extern "C" void kernel_launch(void* const* d_in, const int* in_sizes, int n_in,
                              void* d_out, int out_size)
{
    const float* x_in = (const float*)d_in[0];
    const float* Wqkv = (const float*)d_in[1];
    const float* bqkv = (const float*)d_in[2];
    const float* Wo   = (const float*)d_in[3];
    const float* bo   = (const float*)d_in[4];
    const float* W1   = (const float*)d_in[5];
    const float* b1   = (const float*)d_in[6];
    const float* W2   = (const float*)d_in[7];
    const float* b2   = (const float*)d_in[8];
    const float* lng  = (const float*)d_in[9];
    const float* lnb  = (const float*)d_in[10];
    float* out = (float*)d_out;

    float *p_x, *p_qkv, *p_s, *p_t;
    __nv_bfloat16 *p_xb, *p_ab, *p_hb, *p_qkvb, *p_wqkv_b, *p_wo_b, *p_w1_b, *p_w2_b;
    cudaGetSymbolAddress((void**)&p_x, g_x);
    cudaGetSymbolAddress((void**)&p_qkv, g_qkv);
    cudaGetSymbolAddress((void**)&p_s, g_s);
    (void)p_t;
    cudaGetSymbolAddress((void**)&p_xb, g_xb);
    cudaGetSymbolAddress((void**)&p_ab, g_ab);
    cudaGetSymbolAddress((void**)&p_hb, g_hb);
    cudaGetSymbolAddress((void**)&p_qkvb, g_qkvb);
    cudaGetSymbolAddress((void**)&p_wqkv_b, g_wqkv_b);
    cudaGetSymbolAddress((void**)&p_wo_b, g_wo_b);
    cudaGetSymbolAddress((void**)&p_w1_b, g_w1_b);
    cudaGetSymbolAddress((void**)&p_w2_b, g_w2_b);

    cudaMemcpyAsync(p_x, x_in, sizeof(float) * (size_t)BT * CC, cudaMemcpyDeviceToDevice);
    cvt_kernel<<<(int)(((size_t)BT * CC) / 256), 256>>>(x_in, p_xb);

    dim3 tb(32, 8);
    transpose_cvt_all_kernel<<<dim3(1024, 1, 24), tb>>>(Wqkv, Wo, W1, W2,
                                                        p_wqkv_b, p_wo_b, p_w1_b, p_w2_b);

    dim3 grid_qkv(QKVN / 128, BT / 128);
    dim3 grid_cc_ks(CC / 128, BT / 128, 2);
    dim3 grid_ff(FF / 128, BT / 128);
    dim3 grid_qk(2 * CC / 128, BT / 128);
    dim3 grid_sc(TT / 128, TT / 128, BB * HH);
    dim3 grid_pv(TT / 128, BB * HH);
    int comb_blocks = (BT * CC) / 256;

    for (int stage = 0; stage < 2; stage++) {
        int use_mask = (stage == 1);
        for (int l = 0; l < 2; l++) {
            int sl = stage * 2 + l;
            const __nv_bfloat16* Wqb = p_wqkv_b + (size_t)sl * 3 * CC * CC;
            const float* bb = bqkv + (size_t)sl * 3 * CC;

            if (stage == 0 && l == 0) {
                // seg-critical exact island (fp32 throughout for probs0 path)
                gemm_kernel<<<grid_qk, 256>>>(p_x, Wqkv + (size_t)sl * 3 * CC * CC, bb,
                                              p_qkv, BT, QKVN, CC, 0, CC);
                gemm_bb_ks_kernel<<<grid_cc_ks, 256>>>(p_xb, Wqb + (size_t)2 * CC * CC, CC);
                ks_combine_kernel<<<comb_blocks, 256>>>(bb + 2 * CC, p_qkv + 2 * CC, QKVN);
                scores_kernel<<<grid_sc, 256>>>(use_mask);
                softmax_rows_kernel<<<BB * HH * TT, 256>>>(p_s);
                head_avg_kernel<<<(int)(((size_t)BB * TT * TT / 4) / 256), 256>>>();
                pv_tf32_kernel<<<grid_pv, 256>>>();
            } else {
                gemm_bb_kernel<<<grid_qkv, 256>>>(p_xb, Wqb, bb, 0, p_qkvb,
                                                  QKVN, CC, 0, 1);
                scores_bf16_kernel<<<grid_sc, 256>>>(use_mask);
                int docolsum = (stage == 1 && l == 0) ? 1 : 0;
                fused_softmax_pv_kernel<<<grid_pv, 256>>>(docolsum);
                if (docolsum)
                    wreduce_kernel<<<BT / 256, 256>>>();
            }

            // Wo GEMM (K-split) -> fused combine+LN
            gemm_bb_ks_kernel<<<grid_cc_ks, 256>>>(p_ab, p_wo_b + (size_t)sl * CC * CC, CC);
            ln_residual_ks_kernel<<<BT, 256>>>(p_x, bo + (size_t)sl * CC, p_x, p_xb,
                                               lng + (size_t)(sl * 2 + 0) * CC,
                                               lnb + (size_t)(sl * 2 + 0) * CC);

            gemm_bb_kernel<<<grid_ff, 256>>>(p_xb, p_w1_b + (size_t)sl * FF * CC,
                                             b1 + (size_t)sl * FF, 0, p_hb, FF, CC, 1, 1);
            // W2 GEMM (K-split) -> fused combine+LN
            gemm_bb_ks_kernel<<<grid_cc_ks, 256>>>(p_hb, p_w2_b + (size_t)sl * CC * FF, FF);
            ln_residual_ks_kernel<<<BT, 256>>>(p_x, b2 + (size_t)sl * CC, p_x, p_xb,
                                               lng + (size_t)(sl * 2 + 1) * CC,
                                               lnb + (size_t)(sl * 2 + 1) * CC);
        }
        if (stage == 0) {
            colsum_kernel<<<BT / 256, 256>>>();
            segment_kernel<<<BB, 256>>>();
        } else {
            batch_softmax_kernel<<<BB, 256>>>();
        }
    }

    word_tokens_kernel<<<dim3(TT, BB), 256>>>(out);
    copyx_kernel<<<(int)(((size_t)BT * CC) / 256), 256>>>(x_in, out);
    wm_kernel<<<(int)(((size_t)BB * TT * TT) / 256), 256>>>(out + (size_t)BB * 2 * TT * CC);
}